// round 1
// baseline (speedup 1.0000x reference)
#include <cuda_runtime.h>

// Problem constants
#define B_   2
#define S_   2048
#define HID_ 2048
#define H_   16
#define HKV_ 8
#define D_   128
#define R_   64
#define NROW (B_*S_)   // 4096

// Scratch (device globals — no allocation allowed)
__device__ __align__(16) float g_A [(size_t)NROW*2048];            // [row][1024 Aq | 512 Ak | 512 Av]
__device__ __align__(16) float g_q [(size_t)B_*H_  *S_*D_];        // [(b*H+h)][s][d]
__device__ __align__(16) float g_k [(size_t)B_*HKV_*S_*D_];        // [(b*HKV+kv)][pos][d]
__device__ __align__(16) float g_v [(size_t)B_*HKV_*S_*D_];
__device__ __align__(16) float g_ao[(size_t)NROW*2048];            // attention out, [row][h*128+d]

// ---------------------------------------------------------------------------
// Generic SGEMM:  C[m][n] = alpha * sum_k A[m][k] * B[n][k]   (A: MxK, B: NxK)
// 128x128x16 tile, 256 threads, 8x8 register tile per thread.
// ---------------------------------------------------------------------------
__global__ void __launch_bounds__(256) gemm_nt(
    const float* __restrict__ A, const float* __restrict__ B,
    float* __restrict__ C, int M, int N, int K, int ldc, float alpha)
{
    __shared__ float As[16][128];
    __shared__ float Bs[16][128];

    const int tid = threadIdx.x;
    const int tx = tid & 15, ty = tid >> 4;
    const int m0 = blockIdx.y * 128;
    const int n0 = blockIdx.x * 128;
    const int lr = tid >> 2;   // 0..63
    const int lc = tid & 3;    // 0..3 (float4 index)

    float acc[8][8];
    #pragma unroll
    for (int i = 0; i < 8; i++)
        #pragma unroll
        for (int j = 0; j < 8; j++) acc[i][j] = 0.f;

    for (int k0 = 0; k0 < K; k0 += 16) {
        #pragma unroll
        for (int it = 0; it < 2; it++) {
            int r = lr + it * 64;
            float4 va = *(const float4*)(A + (size_t)(m0 + r) * K + k0 + lc * 4);
            As[lc*4+0][r] = va.x; As[lc*4+1][r] = va.y;
            As[lc*4+2][r] = va.z; As[lc*4+3][r] = va.w;
            float4 vb = *(const float4*)(B + (size_t)(n0 + r) * K + k0 + lc * 4);
            Bs[lc*4+0][r] = vb.x; Bs[lc*4+1][r] = vb.y;
            Bs[lc*4+2][r] = vb.z; Bs[lc*4+3][r] = vb.w;
        }
        __syncthreads();
        #pragma unroll
        for (int kk = 0; kk < 16; kk++) {
            float4 a0 = *(const float4*)&As[kk][ty*8];
            float4 a1 = *(const float4*)&As[kk][ty*8+4];
            float4 b0 = *(const float4*)&Bs[kk][tx*8];
            float4 b1 = *(const float4*)&Bs[kk][tx*8+4];
            float av[8] = {a0.x,a0.y,a0.z,a0.w,a1.x,a1.y,a1.z,a1.w};
            float bw[8] = {b0.x,b0.y,b0.z,b0.w,b1.x,b1.y,b1.z,b1.w};
            #pragma unroll
            for (int i = 0; i < 8; i++)
                #pragma unroll
                for (int j = 0; j < 8; j++)
                    acc[i][j] = fmaf(av[i], bw[j], acc[i][j]);
        }
        __syncthreads();
    }

    #pragma unroll
    for (int i = 0; i < 8; i++) {
        float* crow = C + (size_t)(m0 + ty*8 + i) * ldc + n0 + tx*8;
        float4 o0, o1;
        o0.x = acc[i][0]*alpha; o0.y = acc[i][1]*alpha;
        o0.z = acc[i][2]*alpha; o0.w = acc[i][3]*alpha;
        o1.x = acc[i][4]*alpha; o1.y = acc[i][5]*alpha;
        o1.z = acc[i][6]*alpha; o1.w = acc[i][7]*alpha;
        *(float4*)crow     = o0;
        *(float4*)(crow+4) = o1;
    }
}

// ---------------------------------------------------------------------------
// Zero-fill two buffers (KV caches; reference zero-inits before scatter)
// ---------------------------------------------------------------------------
__global__ void zero2_kernel(float* a, float* b)
{
    size_t i = ((size_t)blockIdx.x * blockDim.x + threadIdx.x) * 4;
    float4 z = {0.f, 0.f, 0.f, 0.f};
    *(float4*)(a + i) = z;
    *(float4*)(b + i) = z;
}

// ---------------------------------------------------------------------------
// q/k/v build: per (row, head) block of 128 threads.
//   x[d] = (1/64) * sum_r A[row][off+r] * Bmat[h][r][d], then RoPE (q,k), scatter (k,v)
// grid.y: 0..15 = q heads, 16..23 = k kv-heads, 24..31 = v kv-heads
// ---------------------------------------------------------------------------
__global__ void __launch_bounds__(128) qkv_kernel(
    const float* __restrict__ gA,
    const float* __restrict__ Bq, const float* __restrict__ Bk, const float* __restrict__ Bv,
    const float* __restrict__ fcos, const float* __restrict__ fsin,
    const int* __restrict__ widx)
{
    const int row = blockIdx.x;        // b*S + s
    const int hh  = blockIdx.y;        // 0..31
    const int d   = threadIdx.x;       // 0..127
    const int b = row >> 11;
    const int s = row & 2047;

    __shared__ float a[64];
    __shared__ float pre[128];

    const float* Bmat; const float* asrc; float* outp;
    int pos; bool dorope;
    if (hh < 16) {
        int h = hh;
        asrc = gA + (size_t)row * 2048 + h * 64;
        Bmat = Bq + (size_t)h * 64 * 128;
        pos = s; dorope = true;
        outp = g_q + ((size_t)(b * H_ + h) * S_ + s) * D_;
    } else if (hh < 24) {
        int kvh = hh - 16;
        asrc = gA + (size_t)row * 2048 + 1024 + kvh * 64;
        Bmat = Bk + (size_t)kvh * 64 * 128;
        pos = widx[s]; dorope = true;
        outp = g_k + ((size_t)(b * HKV_ + kvh) * S_ + pos) * D_;
    } else {
        int kvh = hh - 24;
        asrc = gA + (size_t)row * 2048 + 1536 + kvh * 64;
        Bmat = Bv + (size_t)kvh * 64 * 128;
        pos = widx[s]; dorope = false;
        outp = g_v + ((size_t)(b * HKV_ + kvh) * S_ + pos) * D_;
    }

    if (d < 64) a[d] = asrc[d];
    __syncthreads();

    float sum = 0.f;
    #pragma unroll 16
    for (int r = 0; r < 64; r++)
        sum = fmaf(a[r], Bmat[(size_t)r * 128 + d], sum);
    sum *= (1.0f / 64.0f);

    if (dorope) {
        pre[d] = sum;
        __syncthreads();
        float c  = fcos[(size_t)pos * 64 + (d & 63)];
        float sn = fsin[(size_t)pos * 64 + (d & 63)];
        if (d < 64) sum = pre[d] * c - pre[d + 64] * sn;
        else        sum = pre[d - 64] * sn + pre[d] * c;
    }
    outp[d] = sum;
}

// ---------------------------------------------------------------------------
// Flash attention (fp32, causal). One block per (q-tile of 64, b*H+h).
// Q/K kept d-major in smem (ld=68 to dodge conflicts), V n-major.
// 256 threads: 16x16; score 4x4 tiles, PV 4x8 tiles.
// ---------------------------------------------------------------------------
#define QLD 68
#define FLASH_SMEM ((128*QLD*2 + 64*65 + 192) * 4)

__global__ void __launch_bounds__(256) flash_kernel()
{
    extern __shared__ float sm[];
    float* Qs   = sm;                 // [128][QLD] (d-major)
    float* KVs  = sm + 128 * QLD;     // K: [128][QLD] d-major; V phase: [64][128] n-major
    float* Sx   = KVs + 128 * QLD;    // [64][65]
    float* mrow = Sx + 64 * 65;       // [64]
    float* lrow = mrow + 64;          // [64]
    float* scl  = lrow + 64;          // [64]

    const int tid = threadIdx.x;
    const int tx = tid & 15, ty = tid >> 4;
    const int qt = blockIdx.x;
    const int bh = blockIdx.y;
    const int b = bh >> 4, h = bh & 15;
    const int kv = h >> 1;            // G = 2
    const int qp = qt * 64;

    const float* qbase = g_q + ((size_t)(b * H_ + h) * S_ + qp) * D_;
    const float* kbase = g_k + (size_t)(b * HKV_ + kv) * S_ * D_;
    const float* vbase = g_v + (size_t)(b * HKV_ + kv) * S_ * D_;

    for (int idx = tid; idx < 64 * 128; idx += 256) {
        int m = idx >> 7, d = idx & 127;
        Qs[d * QLD + m] = qbase[idx];
    }
    if (tid < 64) { mrow[tid] = -1e30f; lrow[tid] = 0.f; }

    float oacc[4][8];
    #pragma unroll
    for (int i = 0; i < 4; i++)
        #pragma unroll
        for (int j = 0; j < 8; j++) oacc[i][j] = 0.f;

    const float scale = 0.088388347648318447f;  // 1/sqrt(128)

    for (int kt = 0; kt <= qt; kt++) {
        __syncthreads();  // protect KVs/Sx reuse + (first iter) Q store
        const float* kp = kbase + (size_t)kt * 64 * D_;
        for (int idx = tid; idx < 64 * 128; idx += 256) {
            int n = idx >> 7, d = idx & 127;
            KVs[d * QLD + n] = kp[idx];
        }
        __syncthreads();

        // scores: S[m][n] = sum_d Q[m][d] K[n][d]
        float s4[4][4];
        #pragma unroll
        for (int i = 0; i < 4; i++)
            #pragma unroll
            for (int j = 0; j < 4; j++) s4[i][j] = 0.f;

        #pragma unroll 4
        for (int d = 0; d < 128; d++) {
            float4 a  = *(const float4*)&Qs[d * QLD + ty * 4];
            float4 bb = *(const float4*)&KVs[d * QLD + tx * 4];
            float av[4] = {a.x, a.y, a.z, a.w};
            float bw[4] = {bb.x, bb.y, bb.z, bb.w};
            #pragma unroll
            for (int i = 0; i < 4; i++)
                #pragma unroll
                for (int j = 0; j < 4; j++)
                    s4[i][j] = fmaf(av[i], bw[j], s4[i][j]);
        }
        const bool diag = (kt == qt);
        #pragma unroll
        for (int i = 0; i < 4; i++) {
            int m = ty * 4 + i;
            #pragma unroll
            for (int j = 0; j < 4; j++) {
                int n = tx * 4 + j;
                float v = s4[i][j] * scale;
                Sx[m * 65 + n] = (diag && n > m) ? -1e30f : v;
            }
        }
        __syncthreads();

        // online softmax: thread (r = tid/4, sg = tid%4) handles 16 cols
        {
            int r = tid >> 2, sg = tid & 3;
            float vals[16]; float mloc = -1e30f;
            #pragma unroll
            for (int c = 0; c < 16; c++) {
                vals[c] = Sx[r * 65 + sg * 16 + c];
                mloc = fmaxf(mloc, vals[c]);
            }
            mloc = fmaxf(mloc, __shfl_xor_sync(0xffffffffu, mloc, 1));
            mloc = fmaxf(mloc, __shfl_xor_sync(0xffffffffu, mloc, 2));
            float mold = mrow[r];
            float mnew = fmaxf(mold, mloc);
            float psum = 0.f;
            #pragma unroll
            for (int c = 0; c < 16; c++) {
                float p = __expf(vals[c] - mnew);
                Sx[r * 65 + sg * 16 + c] = p;
                psum += p;
            }
            psum += __shfl_xor_sync(0xffffffffu, psum, 1);
            psum += __shfl_xor_sync(0xffffffffu, psum, 2);
            if (sg == 0) {
                float sc = __expf(mold - mnew);
                scl[r]  = sc;
                mrow[r] = mnew;
                lrow[r] = lrow[r] * sc + psum;
            }
        }

        // load V tile (n-major) into KVs (safe: score phase done)
        const float* vp = vbase + (size_t)kt * 64 * D_;
        for (int idx = tid; idx < 64 * 128; idx += 256) KVs[idx] = vp[idx];
        __syncthreads();

        // rescale O and accumulate P @ V
        float rs[4];
        #pragma unroll
        for (int i = 0; i < 4; i++) rs[i] = scl[ty * 4 + i];
        #pragma unroll
        for (int i = 0; i < 4; i++)
            #pragma unroll
            for (int j = 0; j < 8; j++) oacc[i][j] *= rs[i];

        #pragma unroll 2
        for (int nk = 0; nk < 64; nk++) {
            float p[4];
            #pragma unroll
            for (int i = 0; i < 4; i++) p[i] = Sx[(ty * 4 + i) * 65 + nk];
            float4 v0 = *(const float4*)&KVs[nk * 128 + tx * 8];
            float4 v1 = *(const float4*)&KVs[nk * 128 + tx * 8 + 4];
            float vv[8] = {v0.x, v0.y, v0.z, v0.w, v1.x, v1.y, v1.z, v1.w};
            #pragma unroll
            for (int i = 0; i < 4; i++)
                #pragma unroll
                for (int j = 0; j < 8; j++)
                    oacc[i][j] = fmaf(p[i], vv[j], oacc[i][j]);
        }
    }

    // epilogue: normalize and write to g_ao as [row][h*128+d]
    #pragma unroll
    for (int i = 0; i < 4; i++) {
        int m = ty * 4 + i;
        float inv = 1.0f / lrow[m];
        float* orow = g_ao + (size_t)(b * S_ + qp + m) * 2048 + h * 128 + tx * 8;
        float4 o0, o1;
        o0.x = oacc[i][0]*inv; o0.y = oacc[i][1]*inv;
        o0.z = oacc[i][2]*inv; o0.w = oacc[i][3]*inv;
        o1.x = oacc[i][4]*inv; o1.y = oacc[i][5]*inv;
        o1.z = oacc[i][6]*inv; o1.w = oacc[i][7]*inv;
        *(float4*)orow       = o0;
        *(float4*)(orow + 4) = o1;
    }
}

// ---------------------------------------------------------------------------
extern "C" void kernel_launch(void* const* d_in, const int* in_sizes, int n_in,
                              void* d_out, int out_size)
{
    const float* hs   = (const float*)d_in[0];   // (B,S,HID)
    const float* WAq  = (const float*)d_in[1];   // (1024, 2048)
    const float* WAk  = (const float*)d_in[2];   // (512, 2048)
    const float* WAv  = (const float*)d_in[3];   // (512, 2048)
    const float* Bq   = (const float*)d_in[4];   // (16,64,128)
    const float* Bk   = (const float*)d_in[5];   // (8,64,128)
    const float* Bv   = (const float*)d_in[6];   // (8,64,128)
    const float* Wo   = (const float*)d_in[7];   // (2048, 2048)
    const float* fcos = (const float*)d_in[8];   // (2048, 64)
    const float* fsin = (const float*)d_in[9];   // (2048, 64)
    // d_in[10] = mask (causal; applied analytically)
    const int*   widx = (const int*)d_in[11];    // (2048,)
    float* out = (float*)d_out;

    float *pA, *pk, *pv, *pao;
    cudaGetSymbolAddress((void**)&pA,  g_A);
    cudaGetSymbolAddress((void**)&pk,  g_k);
    cudaGetSymbolAddress((void**)&pv,  g_v);
    cudaGetSymbolAddress((void**)&pao, g_ao);

    cudaFuncSetAttribute(flash_kernel,
                         cudaFuncAttributeMaxDynamicSharedMemorySize, FLASH_SMEM);

    dim3 blk(256);
    // 1) low-rank projections into g_A column blocks
    gemm_nt<<<dim3(8, 32), blk>>>(hs, WAq, pA,        NROW, 1024, 2048, 2048, 1.0f);
    gemm_nt<<<dim3(4, 32), blk>>>(hs, WAk, pA + 1024, NROW,  512, 2048, 2048, 1.0f);
    gemm_nt<<<dim3(4, 32), blk>>>(hs, WAv, pA + 1536, NROW,  512, 2048, 2048, 1.0f);

    // 2) zero KV caches (scatter semantics), then build q/k/v (+RoPE, scatter)
    zero2_kernel<<<(B_*HKV_*S_*D_) / (4 * 256), 256>>>(pk, pv);
    qkv_kernel<<<dim3(NROW, 32), 128>>>(pA, Bq, Bk, Bv, fcos, fsin, widx);

    // 3) causal flash attention
    flash_kernel<<<dim3(S_ / 64, B_ * H_), 256, FLASH_SMEM>>>();

    // 4) output projection
    gemm_nt<<<dim3(16, 32), blk>>>(pao, Wo, out, NROW, 2048, 2048, 2048, 1.0f);
}

// round 3
// speedup vs baseline: 1.4139x; 1.4139x over previous
#include <cuda_runtime.h>
#include <cstdint>

// Problem constants
#define B_   2
#define S_   2048
#define H_   16
#define HKV_ 8
#define D_   128
#define NROW (B_*S_)   // 4096

// Scratch (device globals — no allocation allowed)
__device__ __align__(16) float g_A [(size_t)NROW*2048];            // [row][1024 Aq | 512 Ak | 512 Av]
__device__ __align__(16) float g_q [(size_t)B_*H_  *S_*D_];
__device__ __align__(16) float g_k [(size_t)B_*HKV_*S_*D_];
__device__ __align__(16) float g_v [(size_t)B_*HKV_*S_*D_];
__device__ __align__(16) float g_ao[(size_t)NROW*2048];

// ---------------------------------------------------------------------------
__device__ __forceinline__ uint32_t f2tf32(float x) {   // round-to-nearest tf32
    uint32_t r;
    asm("cvt.rna.tf32.f32 %0, %1;" : "=r"(r) : "f"(x));
    return r;
}

__device__ __forceinline__ void mma_tf32(float* c, const uint32_t* a, const uint32_t* b) {
    asm volatile(
        "mma.sync.aligned.m16n8k8.row.col.f32.tf32.tf32.f32 "
        "{%0,%1,%2,%3}, {%4,%5,%6,%7}, {%8,%9}, {%0,%1,%2,%3};"
        : "+f"(c[0]), "+f"(c[1]), "+f"(c[2]), "+f"(c[3])
        : "r"(a[0]), "r"(a[1]), "r"(a[2]), "r"(a[3]), "r"(b[0]), "r"(b[1]));
}

// ---------------------------------------------------------------------------
// tf32 mma.sync GEMM:  C[m][n] = alpha * sum_k A[m][k] * B[n][k]
// 128x128 block, 8 warps (warp tile 64x32), K-chunks of 32.
// Smem tiles 128x32 padded to stride 36 (conflict-free fragment loads).
// M,N multiples of 128; K multiple of 32.
// ---------------------------------------------------------------------------
#define TS 36                       // smem row stride (floats)
#define TILE_WORDS (128*TS)         // one tile
#define GT_SMEM (2*2*TILE_WORDS*4)  // A0 B0 A1 B1  = 73728 B

__global__ void __launch_bounds__(256, 1) gemm_tc(
    const float* __restrict__ A, const float* __restrict__ B,
    float* __restrict__ C, int K, int ldc, float alpha)
{
    extern __shared__ float sm[];
    // layout: [buf][A|B][128][TS]
    const int tid = threadIdx.x;
    const int wid = tid >> 5, lane = tid & 31;
    const int wm = wid >> 2, wn = wid & 3;       // warp grid 2 x 4
    const int lr = lane >> 2, lc = lane & 3;     // fragment row/col within tile
    const int m0 = blockIdx.y << 7, n0 = blockIdx.x << 7;
    A += (size_t)m0 * K;
    B += (size_t)n0 * K;
    C += (size_t)m0 * ldc + n0;

    float acc[4][4][4];
    #pragma unroll
    for (int i = 0; i < 4; i++)
        #pragma unroll
        for (int j = 0; j < 4; j++)
            #pragma unroll
            for (int r = 0; r < 4; r++) acc[i][j][r] = 0.f;

    // each thread moves 4 float4 per tile (128x32 = 1024 float4, 256 thr)
    int ldrow[4], ldc4[4];
    #pragma unroll
    for (int i = 0; i < 4; i++) {
        int idx = tid * 4 + i;
        ldrow[i] = idx >> 3;
        ldc4[i]  = idx & 7;
    }

    const int nch = K >> 5;

    // prologue: chunk 0 -> buf 0
    #pragma unroll
    for (int i = 0; i < 4; i++) {
        float4 va = *(const float4*)(A + (size_t)ldrow[i] * K + (ldc4[i] << 2));
        float4 vb = *(const float4*)(B + (size_t)ldrow[i] * K + (ldc4[i] << 2));
        float* pa = sm + ldrow[i] * TS + (ldc4[i] << 2);
        float* pb = sm + TILE_WORDS + ldrow[i] * TS + (ldc4[i] << 2);
        pa[0] = __uint_as_float(f2tf32(va.x)); pa[1] = __uint_as_float(f2tf32(va.y));
        pa[2] = __uint_as_float(f2tf32(va.z)); pa[3] = __uint_as_float(f2tf32(va.w));
        pb[0] = __uint_as_float(f2tf32(vb.x)); pb[1] = __uint_as_float(f2tf32(vb.y));
        pb[2] = __uint_as_float(f2tf32(vb.z)); pb[3] = __uint_as_float(f2tf32(vb.w));
    }
    __syncthreads();

    for (int c = 0; c < nch; c++) {
        const float* As = sm + (c & 1) * 2 * TILE_WORDS;
        const float* Bs = As + TILE_WORDS;

        // prefetch next chunk into registers
        float4 na[4], nb[4];
        if (c + 1 < nch) {
            const int k0 = (c + 1) << 5;
            #pragma unroll
            for (int i = 0; i < 4; i++) {
                na[i] = *(const float4*)(A + (size_t)ldrow[i] * K + k0 + (ldc4[i] << 2));
                nb[i] = *(const float4*)(B + (size_t)ldrow[i] * K + k0 + (ldc4[i] << 2));
            }
        }

        // compute: 4 k-steps of 8
        #pragma unroll
        for (int ks = 0; ks < 4; ks++) {
            const int kk = ks << 3;
            uint32_t af[4][4], bf[4][2];
            #pragma unroll
            for (int mi = 0; mi < 4; mi++) {
                const float* p = As + (wm * 64 + mi * 16 + lr) * TS + kk + lc;
                af[mi][0] = __float_as_uint(p[0]);
                af[mi][1] = __float_as_uint(p[8 * TS]);
                af[mi][2] = __float_as_uint(p[4]);
                af[mi][3] = __float_as_uint(p[8 * TS + 4]);
            }
            #pragma unroll
            for (int ni = 0; ni < 4; ni++) {
                const float* p = Bs + (wn * 32 + ni * 8 + lr) * TS + kk + lc;
                bf[ni][0] = __float_as_uint(p[0]);
                bf[ni][1] = __float_as_uint(p[4]);
            }
            #pragma unroll
            for (int mi = 0; mi < 4; mi++)
                #pragma unroll
                for (int ni = 0; ni < 4; ni++)
                    mma_tf32(acc[mi][ni], af[mi], bf[ni]);
        }

        // store prefetched chunk into the other buffer
        if (c + 1 < nch) {
            float* dst = sm + ((c + 1) & 1) * 2 * TILE_WORDS;
            #pragma unroll
            for (int i = 0; i < 4; i++) {
                float* pa = dst + ldrow[i] * TS + (ldc4[i] << 2);
                float* pb = dst + TILE_WORDS + ldrow[i] * TS + (ldc4[i] << 2);
                pa[0] = __uint_as_float(f2tf32(na[i].x)); pa[1] = __uint_as_float(f2tf32(na[i].y));
                pa[2] = __uint_as_float(f2tf32(na[i].z)); pa[3] = __uint_as_float(f2tf32(na[i].w));
                pb[0] = __uint_as_float(f2tf32(nb[i].x)); pb[1] = __uint_as_float(f2tf32(nb[i].y));
                pb[2] = __uint_as_float(f2tf32(nb[i].z)); pb[3] = __uint_as_float(f2tf32(nb[i].w));
            }
        }
        __syncthreads();
    }

    // epilogue: c0,c1 -> (row, col), c2,c3 -> (row+8, col)
    #pragma unroll
    for (int mi = 0; mi < 4; mi++) {
        const int row = wm * 64 + mi * 16 + lr;
        #pragma unroll
        for (int ni = 0; ni < 4; ni++) {
            const int col = wn * 32 + ni * 8 + lc * 2;
            float2 v0 = { acc[mi][ni][0] * alpha, acc[mi][ni][1] * alpha };
            float2 v1 = { acc[mi][ni][2] * alpha, acc[mi][ni][3] * alpha };
            *(float2*)(C + (size_t)row * ldc + col)       = v0;
            *(float2*)(C + (size_t)(row + 8) * ldc + col) = v1;
        }
    }
}

// ---------------------------------------------------------------------------
// Zero-fill two buffers (KV caches)
// ---------------------------------------------------------------------------
__global__ void zero2_kernel(float* a, float* b)
{
    size_t i = ((size_t)blockIdx.x * blockDim.x + threadIdx.x) * 4;
    float4 z = {0.f, 0.f, 0.f, 0.f};
    *(float4*)(a + i) = z;
    *(float4*)(b + i) = z;
}

// ---------------------------------------------------------------------------
// q/k/v build (A already scaled by 1/64 via gemm alpha)
// ---------------------------------------------------------------------------
__global__ void __launch_bounds__(128) qkv_kernel(
    const float* __restrict__ gA,
    const float* __restrict__ Bq, const float* __restrict__ Bk, const float* __restrict__ Bv,
    const float* __restrict__ fcos, const float* __restrict__ fsin,
    const int* __restrict__ widx)
{
    const int row = blockIdx.x;
    const int hh  = blockIdx.y;
    const int d   = threadIdx.x;
    const int b = row >> 11;
    const int s = row & 2047;

    __shared__ float a[64];
    __shared__ float pre[128];

    const float* Bmat; const float* asrc; float* outp;
    int pos; bool dorope;
    if (hh < 16) {
        int h = hh;
        asrc = gA + (size_t)row * 2048 + h * 64;
        Bmat = Bq + (size_t)h * 64 * 128;
        pos = s; dorope = true;
        outp = g_q + ((size_t)(b * H_ + h) * S_ + s) * D_;
    } else if (hh < 24) {
        int kvh = hh - 16;
        asrc = gA + (size_t)row * 2048 + 1024 + kvh * 64;
        Bmat = Bk + (size_t)kvh * 64 * 128;
        pos = widx[s]; dorope = true;
        outp = g_k + ((size_t)(b * HKV_ + kvh) * S_ + pos) * D_;
    } else {
        int kvh = hh - 24;
        asrc = gA + (size_t)row * 2048 + 1536 + kvh * 64;
        Bmat = Bv + (size_t)kvh * 64 * 128;
        pos = widx[s]; dorope = false;
        outp = g_v + ((size_t)(b * HKV_ + kvh) * S_ + pos) * D_;
    }

    if (d < 64) a[d] = asrc[d];
    __syncthreads();

    float sum = 0.f;
    #pragma unroll 16
    for (int r = 0; r < 64; r++)
        sum = fmaf(a[r], Bmat[(size_t)r * 128 + d], sum);

    if (dorope) {
        pre[d] = sum;
        __syncthreads();
        float c  = fcos[(size_t)pos * 64 + (d & 63)];
        float sn = fsin[(size_t)pos * 64 + (d & 63)];
        if (d < 64) sum = pre[d] * c - pre[d + 64] * sn;
        else        sum = pre[d - 64] * sn + pre[d] * c;
    }
    outp[d] = sum;
}

// ---------------------------------------------------------------------------
// Flash attention (fp32, causal) — unchanged this round
// ---------------------------------------------------------------------------
#define QLD 68
#define FLASH_SMEM ((128*QLD*2 + 64*65 + 192) * 4)

__global__ void __launch_bounds__(256) flash_kernel()
{
    extern __shared__ float sm[];
    float* Qs   = sm;
    float* KVs  = sm + 128 * QLD;
    float* Sx   = KVs + 128 * QLD;
    float* mrow = Sx + 64 * 65;
    float* lrow = mrow + 64;
    float* scl  = lrow + 64;

    const int tid = threadIdx.x;
    const int tx = tid & 15, ty = tid >> 4;
    const int qt = blockIdx.x;
    const int bh = blockIdx.y;
    const int b = bh >> 4, h = bh & 15;
    const int kv = h >> 1;
    const int qp = qt * 64;

    const float* qbase = g_q + ((size_t)(b * H_ + h) * S_ + qp) * D_;
    const float* kbase = g_k + (size_t)(b * HKV_ + kv) * S_ * D_;
    const float* vbase = g_v + (size_t)(b * HKV_ + kv) * S_ * D_;

    for (int idx = tid; idx < 64 * 128; idx += 256) {
        int m = idx >> 7, d = idx & 127;
        Qs[d * QLD + m] = qbase[idx];
    }
    if (tid < 64) { mrow[tid] = -1e30f; lrow[tid] = 0.f; }

    float oacc[4][8];
    #pragma unroll
    for (int i = 0; i < 4; i++)
        #pragma unroll
        for (int j = 0; j < 8; j++) oacc[i][j] = 0.f;

    const float scale = 0.088388347648318447f;

    for (int kt = 0; kt <= qt; kt++) {
        __syncthreads();
        const float* kp = kbase + (size_t)kt * 64 * D_;
        for (int idx = tid; idx < 64 * 128; idx += 256) {
            int n = idx >> 7, d = idx & 127;
            KVs[d * QLD + n] = kp[idx];
        }
        __syncthreads();

        float s4[4][4];
        #pragma unroll
        for (int i = 0; i < 4; i++)
            #pragma unroll
            for (int j = 0; j < 4; j++) s4[i][j] = 0.f;

        #pragma unroll 4
        for (int d = 0; d < 128; d++) {
            float4 a  = *(const float4*)&Qs[d * QLD + ty * 4];
            float4 bb = *(const float4*)&KVs[d * QLD + tx * 4];
            float av[4] = {a.x, a.y, a.z, a.w};
            float bw[4] = {bb.x, bb.y, bb.z, bb.w};
            #pragma unroll
            for (int i = 0; i < 4; i++)
                #pragma unroll
                for (int j = 0; j < 4; j++)
                    s4[i][j] = fmaf(av[i], bw[j], s4[i][j]);
        }
        const bool diag = (kt == qt);
        #pragma unroll
        for (int i = 0; i < 4; i++) {
            int m = ty * 4 + i;
            #pragma unroll
            for (int j = 0; j < 4; j++) {
                int n = tx * 4 + j;
                float v = s4[i][j] * scale;
                Sx[m * 65 + n] = (diag && n > m) ? -1e30f : v;
            }
        }
        __syncthreads();

        {
            int r = tid >> 2, sg = tid & 3;
            float vals[16]; float mloc = -1e30f;
            #pragma unroll
            for (int c = 0; c < 16; c++) {
                vals[c] = Sx[r * 65 + sg * 16 + c];
                mloc = fmaxf(mloc, vals[c]);
            }
            mloc = fmaxf(mloc, __shfl_xor_sync(0xffffffffu, mloc, 1));
            mloc = fmaxf(mloc, __shfl_xor_sync(0xffffffffu, mloc, 2));
            float mold = mrow[r];
            float mnew = fmaxf(mold, mloc);
            float psum = 0.f;
            #pragma unroll
            for (int c = 0; c < 16; c++) {
                float p = __expf(vals[c] - mnew);
                Sx[r * 65 + sg * 16 + c] = p;
                psum += p;
            }
            psum += __shfl_xor_sync(0xffffffffu, psum, 1);
            psum += __shfl_xor_sync(0xffffffffu, psum, 2);
            if (sg == 0) {
                float sc = __expf(mold - mnew);
                scl[r]  = sc;
                mrow[r] = mnew;
                lrow[r] = lrow[r] * sc + psum;
            }
        }

        const float* vp = vbase + (size_t)kt * 64 * D_;
        for (int idx = tid; idx < 64 * 128; idx += 256) KVs[idx] = vp[idx];
        __syncthreads();

        float rs[4];
        #pragma unroll
        for (int i = 0; i < 4; i++) rs[i] = scl[ty * 4 + i];
        #pragma unroll
        for (int i = 0; i < 4; i++)
            #pragma unroll
            for (int j = 0; j < 8; j++) oacc[i][j] *= rs[i];

        #pragma unroll 2
        for (int nk = 0; nk < 64; nk++) {
            float p[4];
            #pragma unroll
            for (int i = 0; i < 4; i++) p[i] = Sx[(ty * 4 + i) * 65 + nk];
            float4 v0 = *(const float4*)&KVs[nk * 128 + tx * 8];
            float4 v1 = *(const float4*)&KVs[nk * 128 + tx * 8 + 4];
            float vv[8] = {v0.x, v0.y, v0.z, v0.w, v1.x, v1.y, v1.z, v1.w};
            #pragma unroll
            for (int i = 0; i < 4; i++)
                #pragma unroll
                for (int j = 0; j < 8; j++)
                    oacc[i][j] = fmaf(p[i], vv[j], oacc[i][j]);
        }
    }

    #pragma unroll
    for (int i = 0; i < 4; i++) {
        int m = ty * 4 + i;
        float inv = 1.0f / lrow[m];
        float* orow = g_ao + (size_t)(b * S_ + qp + m) * 2048 + h * 128 + tx * 8;
        float4 o0, o1;
        o0.x = oacc[i][0]*inv; o0.y = oacc[i][1]*inv;
        o0.z = oacc[i][2]*inv; o0.w = oacc[i][3]*inv;
        o1.x = oacc[i][4]*inv; o1.y = oacc[i][5]*inv;
        o1.z = oacc[i][6]*inv; o1.w = oacc[i][7]*inv;
        *(float4*)orow       = o0;
        *(float4*)(orow + 4) = o1;
    }
}

// ---------------------------------------------------------------------------
extern "C" void kernel_launch(void* const* d_in, const int* in_sizes, int n_in,
                              void* d_out, int out_size)
{
    const float* hs   = (const float*)d_in[0];
    const float* WAq  = (const float*)d_in[1];
    const float* WAk  = (const float*)d_in[2];
    const float* WAv  = (const float*)d_in[3];
    const float* Bq   = (const float*)d_in[4];
    const float* Bk   = (const float*)d_in[5];
    const float* Bv   = (const float*)d_in[6];
    const float* Wo   = (const float*)d_in[7];
    const float* fcos = (const float*)d_in[8];
    const float* fsin = (const float*)d_in[9];
    const int*   widx = (const int*)d_in[11];
    float* out = (float*)d_out;

    float *pA, *pk, *pv, *pao;
    cudaGetSymbolAddress((void**)&pA,  g_A);
    cudaGetSymbolAddress((void**)&pk,  g_k);
    cudaGetSymbolAddress((void**)&pv,  g_v);
    cudaGetSymbolAddress((void**)&pao, g_ao);

    cudaFuncSetAttribute(gemm_tc,
                         cudaFuncAttributeMaxDynamicSharedMemorySize, GT_SMEM);
    cudaFuncSetAttribute(flash_kernel,
                         cudaFuncAttributeMaxDynamicSharedMemorySize, FLASH_SMEM);

    const float inv64 = 1.0f / 64.0f;
    // 1) low-rank projections (alpha folds the /64 scaling)
    gemm_tc<<<dim3(8, 32), 256, GT_SMEM>>>(hs, WAq, pA,        2048, 2048, inv64);
    gemm_tc<<<dim3(4, 32), 256, GT_SMEM>>>(hs, WAk, pA + 1024, 2048, 2048, inv64);
    gemm_tc<<<dim3(4, 32), 256, GT_SMEM>>>(hs, WAv, pA + 1536, 2048, 2048, inv64);

    // 2) zero KV caches, build q/k/v (+RoPE, scatter)
    zero2_kernel<<<(B_*HKV_*S_*D_) / (4 * 256), 256>>>(pk, pv);
    qkv_kernel<<<dim3(NROW, 32), 128>>>(pA, Bq, Bk, Bv, fcos, fsin, widx);

    // 3) causal flash attention (fp32 SIMT this round)
    flash_kernel<<<dim3(S_ / 64, B_ * H_), 256, FLASH_SMEM>>>();

    // 4) output projection
    gemm_tc<<<dim3(16, 32), 256, GT_SMEM>>>(pao, Wo, out, 2048, 2048, 1.0f);
}

// round 4
// speedup vs baseline: 2.5489x; 1.8027x over previous
#include <cuda_runtime.h>
#include <cstdint>

// Problem constants
#define B_   2
#define S_   2048
#define H_   16
#define HKV_ 8
#define D_   128
#define NROW (B_*S_)   // 4096

// Scratch (device globals — no allocation allowed)
__device__ __align__(16) float g_A [(size_t)NROW*2048];            // [row][1024 Aq | 512 Ak | 512 Av]
__device__ __align__(16) float g_q [(size_t)B_*H_  *S_*D_];
__device__ __align__(16) float g_k [(size_t)B_*HKV_*S_*D_];
__device__ __align__(16) float g_v [(size_t)B_*HKV_*S_*D_];
__device__ __align__(16) float g_ao[(size_t)NROW*2048];

// ---------------------------------------------------------------------------
__device__ __forceinline__ uint32_t f2tf32(float x) {   // round-to-nearest tf32
    uint32_t r;
    asm("cvt.rna.tf32.f32 %0, %1;" : "=r"(r) : "f"(x));
    return r;
}
__device__ __forceinline__ float tf32r(float x) { return __uint_as_float(f2tf32(x)); }

__device__ __forceinline__ void mma_tf32(float* c, const uint32_t* a, const uint32_t* b) {
    asm volatile(
        "mma.sync.aligned.m16n8k8.row.col.f32.tf32.tf32.f32 "
        "{%0,%1,%2,%3}, {%4,%5,%6,%7}, {%8,%9}, {%0,%1,%2,%3};"
        : "+f"(c[0]), "+f"(c[1]), "+f"(c[2]), "+f"(c[3])
        : "r"(a[0]), "r"(a[1]), "r"(a[2]), "r"(a[3]), "r"(b[0]), "r"(b[1]));
}

// ---------------------------------------------------------------------------
// tf32 mma.sync GEMM:  C[m][n] = alpha * sum_k A[m][k] * B[n][k]
// ---------------------------------------------------------------------------
#define TS 36
#define TILE_WORDS (128*TS)
#define GT_SMEM (2*2*TILE_WORDS*4)

__global__ void __launch_bounds__(256, 1) gemm_tc(
    const float* __restrict__ A, const float* __restrict__ B,
    float* __restrict__ C, int K, int ldc, float alpha)
{
    extern __shared__ float sm[];
    const int tid = threadIdx.x;
    const int wid = tid >> 5, lane = tid & 31;
    const int wm = wid >> 2, wn = wid & 3;
    const int lr = lane >> 2, lc = lane & 3;
    const int m0 = blockIdx.y << 7, n0 = blockIdx.x << 7;
    A += (size_t)m0 * K;
    B += (size_t)n0 * K;
    C += (size_t)m0 * ldc + n0;

    float acc[4][4][4];
    #pragma unroll
    for (int i = 0; i < 4; i++)
        #pragma unroll
        for (int j = 0; j < 4; j++)
            #pragma unroll
            for (int r = 0; r < 4; r++) acc[i][j][r] = 0.f;

    int ldrow[4], ldc4[4];
    #pragma unroll
    for (int i = 0; i < 4; i++) {
        int idx = tid * 4 + i;
        ldrow[i] = idx >> 3;
        ldc4[i]  = idx & 7;
    }

    const int nch = K >> 5;

    #pragma unroll
    for (int i = 0; i < 4; i++) {
        float4 va = *(const float4*)(A + (size_t)ldrow[i] * K + (ldc4[i] << 2));
        float4 vb = *(const float4*)(B + (size_t)ldrow[i] * K + (ldc4[i] << 2));
        float* pa = sm + ldrow[i] * TS + (ldc4[i] << 2);
        float* pb = sm + TILE_WORDS + ldrow[i] * TS + (ldc4[i] << 2);
        pa[0] = tf32r(va.x); pa[1] = tf32r(va.y); pa[2] = tf32r(va.z); pa[3] = tf32r(va.w);
        pb[0] = tf32r(vb.x); pb[1] = tf32r(vb.y); pb[2] = tf32r(vb.z); pb[3] = tf32r(vb.w);
    }
    __syncthreads();

    for (int c = 0; c < nch; c++) {
        const float* As = sm + (c & 1) * 2 * TILE_WORDS;
        const float* Bs = As + TILE_WORDS;

        float4 na[4], nb[4];
        if (c + 1 < nch) {
            const int k0 = (c + 1) << 5;
            #pragma unroll
            for (int i = 0; i < 4; i++) {
                na[i] = *(const float4*)(A + (size_t)ldrow[i] * K + k0 + (ldc4[i] << 2));
                nb[i] = *(const float4*)(B + (size_t)ldrow[i] * K + k0 + (ldc4[i] << 2));
            }
        }

        #pragma unroll
        for (int ks = 0; ks < 4; ks++) {
            const int kk = ks << 3;
            uint32_t af[4][4], bf[4][2];
            #pragma unroll
            for (int mi = 0; mi < 4; mi++) {
                const float* p = As + (wm * 64 + mi * 16 + lr) * TS + kk + lc;
                af[mi][0] = __float_as_uint(p[0]);
                af[mi][1] = __float_as_uint(p[8 * TS]);
                af[mi][2] = __float_as_uint(p[4]);
                af[mi][3] = __float_as_uint(p[8 * TS + 4]);
            }
            #pragma unroll
            for (int ni = 0; ni < 4; ni++) {
                const float* p = Bs + (wn * 32 + ni * 8 + lr) * TS + kk + lc;
                bf[ni][0] = __float_as_uint(p[0]);
                bf[ni][1] = __float_as_uint(p[4]);
            }
            #pragma unroll
            for (int mi = 0; mi < 4; mi++)
                #pragma unroll
                for (int ni = 0; ni < 4; ni++)
                    mma_tf32(acc[mi][ni], af[mi], bf[ni]);
        }

        if (c + 1 < nch) {
            float* dst = sm + ((c + 1) & 1) * 2 * TILE_WORDS;
            #pragma unroll
            for (int i = 0; i < 4; i++) {
                float* pa = dst + ldrow[i] * TS + (ldc4[i] << 2);
                float* pb = dst + TILE_WORDS + ldrow[i] * TS + (ldc4[i] << 2);
                pa[0] = tf32r(na[i].x); pa[1] = tf32r(na[i].y);
                pa[2] = tf32r(na[i].z); pa[3] = tf32r(na[i].w);
                pb[0] = tf32r(nb[i].x); pb[1] = tf32r(nb[i].y);
                pb[2] = tf32r(nb[i].z); pb[3] = tf32r(nb[i].w);
            }
        }
        __syncthreads();
    }

    #pragma unroll
    for (int mi = 0; mi < 4; mi++) {
        const int row = wm * 64 + mi * 16 + lr;
        #pragma unroll
        for (int ni = 0; ni < 4; ni++) {
            const int col = wn * 32 + ni * 8 + lc * 2;
            float2 v0 = { acc[mi][ni][0] * alpha, acc[mi][ni][1] * alpha };
            float2 v1 = { acc[mi][ni][2] * alpha, acc[mi][ni][3] * alpha };
            *(float2*)(C + (size_t)row * ldc + col)       = v0;
            *(float2*)(C + (size_t)(row + 8) * ldc + col) = v1;
        }
    }
}

// ---------------------------------------------------------------------------
__global__ void zero2_kernel(float* a, float* b)
{
    size_t i = ((size_t)blockIdx.x * blockDim.x + threadIdx.x) * 4;
    float4 z = {0.f, 0.f, 0.f, 0.f};
    *(float4*)(a + i) = z;
    *(float4*)(b + i) = z;
}

// ---------------------------------------------------------------------------
// q/k/v build (A already scaled by 1/64 via gemm alpha)
// ---------------------------------------------------------------------------
__global__ void __launch_bounds__(128) qkv_kernel(
    const float* __restrict__ gA,
    const float* __restrict__ Bq, const float* __restrict__ Bk, const float* __restrict__ Bv,
    const float* __restrict__ fcos, const float* __restrict__ fsin,
    const int* __restrict__ widx)
{
    const int row = blockIdx.x;
    const int hh  = blockIdx.y;
    const int d   = threadIdx.x;
    const int b = row >> 11;
    const int s = row & 2047;

    __shared__ float a[64];
    __shared__ float pre[128];

    const float* Bmat; const float* asrc; float* outp;
    int pos; bool dorope;
    if (hh < 16) {
        int h = hh;
        asrc = gA + (size_t)row * 2048 + h * 64;
        Bmat = Bq + (size_t)h * 64 * 128;
        pos = s; dorope = true;
        outp = g_q + ((size_t)(b * H_ + h) * S_ + s) * D_;
    } else if (hh < 24) {
        int kvh = hh - 16;
        asrc = gA + (size_t)row * 2048 + 1024 + kvh * 64;
        Bmat = Bk + (size_t)kvh * 64 * 128;
        pos = widx[s]; dorope = true;
        outp = g_k + ((size_t)(b * HKV_ + kvh) * S_ + pos) * D_;
    } else {
        int kvh = hh - 24;
        asrc = gA + (size_t)row * 2048 + 1536 + kvh * 64;
        Bmat = Bv + (size_t)kvh * 64 * 128;
        pos = widx[s]; dorope = false;
        outp = g_v + ((size_t)(b * HKV_ + kvh) * S_ + pos) * D_;
    }

    if (d < 64) a[d] = asrc[d];
    __syncthreads();

    float sum = 0.f;
    #pragma unroll 16
    for (int r = 0; r < 64; r++)
        sum = fmaf(a[r], Bmat[(size_t)r * 128 + d], sum);

    if (dorope) {
        pre[d] = sum;
        __syncthreads();
        float c  = fcos[(size_t)pos * 64 + (d & 63)];
        float sn = fsin[(size_t)pos * 64 + (d & 63)];
        if (d < 64) sum = pre[d] * c - pre[d + 64] * sn;
        else        sum = pre[d - 64] * sn + pre[d] * c;
    }
    outp[d] = sum;
}

// ---------------------------------------------------------------------------
// Flash attention with tf32 mma.sync. 64 q-rows per CTA, 4 warps (m16 each),
// k-tiles of 64. Q frags register-resident; K [n][k] stride 132; V [k][d]
// stride 136 (conflict-free transposed B-frag reads); P via smem stride 68.
// ---------------------------------------------------------------------------
#define KTS 132
#define VTS 136
#define PTS 68
#define FL_SMEM ((64*KTS + 64*VTS + 64*PTS) * 4)   // 86016 B

__global__ void __launch_bounds__(128, 2) flash_tc()
{
    extern __shared__ float sm[];
    float* Ks = sm;
    float* Vs = Ks + 64 * KTS;
    float* Ps = Vs + 64 * VTS;

    const int tid = threadIdx.x;
    const int w = tid >> 5, lane = tid & 31;
    const int lr = lane >> 2, lc = lane & 3;
    const int qt = (int)gridDim.x - 1 - (int)blockIdx.x;   // long CTAs first
    const int bh = blockIdx.y;
    const int b = bh >> 4, h = bh & 15;
    const int kvh = h >> 1;
    const int qp = qt * 64;

    const float* qbase = g_q + ((size_t)(b * H_ + h) * S_ + qp) * D_;
    const float* kbase = g_k + (size_t)(b * HKV_ + kvh) * S_ * D_;
    const float* vbase = g_v + (size_t)(b * HKV_ + kvh) * S_ * D_;

    const float SC = 0.088388347648318447f;  // 1/sqrt(128)

    // stage Q (scaled + tf32) into Ks, pull frags to registers
    for (int i = tid; i < 64 * 32; i += 128) {
        int r = i >> 5, c4 = (i & 31) << 2;
        float4 v = *(const float4*)(qbase + (size_t)r * 128 + c4);
        float* p = Ks + r * KTS + c4;
        p[0] = tf32r(v.x * SC); p[1] = tf32r(v.y * SC);
        p[2] = tf32r(v.z * SC); p[3] = tf32r(v.w * SC);
    }
    __syncthreads();

    uint32_t qf[16][4];
    #pragma unroll
    for (int k8 = 0; k8 < 16; k8++) {
        const float* p = Ks + (w * 16 + lr) * KTS + (k8 << 3) + lc;
        qf[k8][0] = __float_as_uint(p[0]);
        qf[k8][1] = __float_as_uint(p[8 * KTS]);
        qf[k8][2] = __float_as_uint(p[4]);
        qf[k8][3] = __float_as_uint(p[8 * KTS + 4]);
    }
    __syncthreads();

    float oacc[16][4];
    #pragma unroll
    for (int i = 0; i < 16; i++)
        #pragma unroll
        for (int j = 0; j < 4; j++) oacc[i][j] = 0.f;
    float m0 = -1e30f, m1 = -1e30f, l0 = 0.f, l1 = 0.f;
    const int r0g = qp + w * 16 + lr, r1g = r0g + 8;

    for (int kt = 0; kt <= qt; kt++) {
        const float* kp = kbase + (size_t)kt * 64 * 128;
        const float* vp = vbase + (size_t)kt * 64 * 128;
        for (int i = tid; i < 64 * 32; i += 128) {
            int r = i >> 5, c4 = (i & 31) << 2;
            float4 k4 = *(const float4*)(kp + (size_t)r * 128 + c4);
            float4 v4 = *(const float4*)(vp + (size_t)r * 128 + c4);
            float* pk = Ks + r * KTS + c4;
            pk[0] = tf32r(k4.x); pk[1] = tf32r(k4.y); pk[2] = tf32r(k4.z); pk[3] = tf32r(k4.w);
            float* pv = Vs + r * VTS + c4;
            pv[0] = tf32r(v4.x); pv[1] = tf32r(v4.y); pv[2] = tf32r(v4.z); pv[3] = tf32r(v4.w);
        }
        __syncthreads();

        // S = Q K^T
        float sacc[8][4];
        #pragma unroll
        for (int i = 0; i < 8; i++)
            #pragma unroll
            for (int j = 0; j < 4; j++) sacc[i][j] = 0.f;

        #pragma unroll
        for (int k8 = 0; k8 < 16; k8++) {
            #pragma unroll
            for (int nt = 0; nt < 8; nt++) {
                const float* p = Ks + (nt * 8 + lr) * KTS + (k8 << 3) + lc;
                uint32_t bf[2] = { __float_as_uint(p[0]), __float_as_uint(p[4]) };
                mma_tf32(sacc[nt], qf[k8], bf);
            }
        }

        if (kt == qt) {   // causal mask on diagonal tile (colbase == qp)
            #pragma unroll
            for (int nt = 0; nt < 8; nt++) {
                int c0 = qp + nt * 8 + 2 * lc;
                if (c0     > r0g) sacc[nt][0] = -1e30f;
                if (c0 + 1 > r0g) sacc[nt][1] = -1e30f;
                if (c0     > r1g) sacc[nt][2] = -1e30f;
                if (c0 + 1 > r1g) sacc[nt][3] = -1e30f;
            }
        }

        // online softmax (registers + quad shuffles)
        float mi0 = -1e30f, mi1 = -1e30f;
        #pragma unroll
        for (int nt = 0; nt < 8; nt++) {
            mi0 = fmaxf(mi0, fmaxf(sacc[nt][0], sacc[nt][1]));
            mi1 = fmaxf(mi1, fmaxf(sacc[nt][2], sacc[nt][3]));
        }
        mi0 = fmaxf(mi0, __shfl_xor_sync(0xffffffffu, mi0, 1));
        mi0 = fmaxf(mi0, __shfl_xor_sync(0xffffffffu, mi0, 2));
        mi1 = fmaxf(mi1, __shfl_xor_sync(0xffffffffu, mi1, 1));
        mi1 = fmaxf(mi1, __shfl_xor_sync(0xffffffffu, mi1, 2));
        float mn0 = fmaxf(m0, mi0), mn1 = fmaxf(m1, mi1);
        float sf0 = __expf(m0 - mn0), sf1 = __expf(m1 - mn1);
        m0 = mn0; m1 = mn1;

        float ps0 = 0.f, ps1 = 0.f;
        float* pr0 = Ps + (w * 16 + lr) * PTS + 2 * lc;
        float* pr1 = pr0 + 8 * PTS;
        #pragma unroll
        for (int nt = 0; nt < 8; nt++) {
            float p00 = __expf(sacc[nt][0] - m0), p01 = __expf(sacc[nt][1] - m0);
            float p10 = __expf(sacc[nt][2] - m1), p11 = __expf(sacc[nt][3] - m1);
            ps0 += p00 + p01; ps1 += p10 + p11;
            float2 a = { tf32r(p00), tf32r(p01) };
            float2 c = { tf32r(p10), tf32r(p11) };
            *(float2*)(pr0 + nt * 8) = a;
            *(float2*)(pr1 + nt * 8) = c;
        }
        ps0 += __shfl_xor_sync(0xffffffffu, ps0, 1);
        ps0 += __shfl_xor_sync(0xffffffffu, ps0, 2);
        ps1 += __shfl_xor_sync(0xffffffffu, ps1, 1);
        ps1 += __shfl_xor_sync(0xffffffffu, ps1, 2);
        l0 = l0 * sf0 + ps0;
        l1 = l1 * sf1 + ps1;

        #pragma unroll
        for (int nd = 0; nd < 16; nd++) {
            oacc[nd][0] *= sf0; oacc[nd][1] *= sf0;
            oacc[nd][2] *= sf1; oacc[nd][3] *= sf1;
        }
        __syncwarp();

        // O += P V
        #pragma unroll
        for (int ks = 0; ks < 8; ks++) {
            const float* pa = Ps + (w * 16 + lr) * PTS + (ks << 3) + lc;
            uint32_t af[4] = { __float_as_uint(pa[0]), __float_as_uint(pa[8 * PTS]),
                               __float_as_uint(pa[4]), __float_as_uint(pa[8 * PTS + 4]) };
            #pragma unroll
            for (int nd = 0; nd < 16; nd++) {
                const float* pb = Vs + ((ks << 3) + lc) * VTS + (nd << 3) + lr;
                uint32_t bf[2] = { __float_as_uint(pb[0]), __float_as_uint(pb[4 * VTS]) };
                mma_tf32(oacc[nd], af, bf);
            }
        }
        __syncthreads();
    }

    // epilogue
    float i0 = 1.f / l0, i1 = 1.f / l1;
    float* o0 = g_ao + ((size_t)b * S_ + r0g) * 2048 + h * 128 + 2 * lc;
    float* o1 = g_ao + ((size_t)b * S_ + r1g) * 2048 + h * 128 + 2 * lc;
    #pragma unroll
    for (int nd = 0; nd < 16; nd++) {
        float2 a = { oacc[nd][0] * i0, oacc[nd][1] * i0 };
        float2 c = { oacc[nd][2] * i1, oacc[nd][3] * i1 };
        *(float2*)(o0 + nd * 8) = a;
        *(float2*)(o1 + nd * 8) = c;
    }
}

// ---------------------------------------------------------------------------
extern "C" void kernel_launch(void* const* d_in, const int* in_sizes, int n_in,
                              void* d_out, int out_size)
{
    const float* hs   = (const float*)d_in[0];
    const float* WAq  = (const float*)d_in[1];
    const float* WAk  = (const float*)d_in[2];
    const float* WAv  = (const float*)d_in[3];
    const float* Bq   = (const float*)d_in[4];
    const float* Bk   = (const float*)d_in[5];
    const float* Bv   = (const float*)d_in[6];
    const float* Wo   = (const float*)d_in[7];
    const float* fcos = (const float*)d_in[8];
    const float* fsin = (const float*)d_in[9];
    const int*   widx = (const int*)d_in[11];
    float* out = (float*)d_out;

    float *pA, *pk, *pv, *pao;
    cudaGetSymbolAddress((void**)&pA,  g_A);
    cudaGetSymbolAddress((void**)&pk,  g_k);
    cudaGetSymbolAddress((void**)&pv,  g_v);
    cudaGetSymbolAddress((void**)&pao, g_ao);

    cudaFuncSetAttribute(gemm_tc,
                         cudaFuncAttributeMaxDynamicSharedMemorySize, GT_SMEM);
    cudaFuncSetAttribute(flash_tc,
                         cudaFuncAttributeMaxDynamicSharedMemorySize, FL_SMEM);

    const float inv64 = 1.0f / 64.0f;
    // 1) low-rank projections (alpha folds the /64 scaling)
    gemm_tc<<<dim3(8, 32), 256, GT_SMEM>>>(hs, WAq, pA,        2048, 2048, inv64);
    gemm_tc<<<dim3(4, 32), 256, GT_SMEM>>>(hs, WAk, pA + 1024, 2048, 2048, inv64);
    gemm_tc<<<dim3(4, 32), 256, GT_SMEM>>>(hs, WAv, pA + 1536, 2048, 2048, inv64);

    // 2) zero KV caches, build q/k/v (+RoPE, scatter)
    zero2_kernel<<<(B_*HKV_*S_*D_) / (4 * 256), 256>>>(pk, pv);
    qkv_kernel<<<dim3(NROW, 32), 128>>>(pA, Bq, Bk, Bv, fcos, fsin, widx);

    // 3) causal flash attention (tf32 tensor cores)
    flash_tc<<<dim3(S_ / 64, B_ * H_), 128, FL_SMEM>>>();

    // 4) output projection
    gemm_tc<<<dim3(16, 32), 256, GT_SMEM>>>(pao, Wo, out, 2048, 2048, 1.0f);
}

// round 5
// speedup vs baseline: 2.9289x; 1.1491x over previous
#include <cuda_runtime.h>
#include <cstdint>

// Problem constants
#define B_   2
#define S_   2048
#define H_   16
#define HKV_ 8
#define D_   128
#define NROW (B_*S_)   // 4096

// Scratch (device globals — no allocation allowed)
__device__ __align__(16) float g_A [(size_t)NROW*2048];            // [row][1024 Aq | 512 Ak | 512 Av]
__device__ __align__(16) float g_q [(size_t)B_*H_  *S_*D_];
__device__ __align__(16) float g_k [(size_t)B_*HKV_*S_*D_];
__device__ __align__(16) float g_v [(size_t)B_*HKV_*S_*D_];
__device__ __align__(16) float g_ao[(size_t)NROW*2048];

// ---------------------------------------------------------------------------
__device__ __forceinline__ uint32_t f2tf32(float x) {   // round-to-nearest tf32
    uint32_t r;
    asm("cvt.rna.tf32.f32 %0, %1;" : "=r"(r) : "f"(x));
    return r;
}
__device__ __forceinline__ float tf32r(float x) { return __uint_as_float(f2tf32(x)); }

__device__ __forceinline__ void mma_tf32(float* c, const uint32_t* a, const uint32_t* b) {
    asm volatile(
        "mma.sync.aligned.m16n8k8.row.col.f32.tf32.tf32.f32 "
        "{%0,%1,%2,%3}, {%4,%5,%6,%7}, {%8,%9}, {%0,%1,%2,%3};"
        : "+f"(c[0]), "+f"(c[1]), "+f"(c[2]), "+f"(c[3])
        : "r"(a[0]), "r"(a[1]), "r"(a[2]), "r"(a[3]), "r"(b[0]), "r"(b[1]));
}

// ---------------------------------------------------------------------------
// Shared tf32 GEMM body: C[m][n] = alpha * sum_k A[m][k]*B[n][k], 128x128 tile.
// ---------------------------------------------------------------------------
#define TS 36
#define TILE_WORDS (128*TS)
#define GT_SMEM (2*2*TILE_WORDS*4)

__device__ __forceinline__ void gemm_body(
    float* sm, const float* __restrict__ A, const float* __restrict__ B,
    float* __restrict__ C, int K, int ldc, float alpha)
{
    const int tid = threadIdx.x;
    const int wid = tid >> 5, lane = tid & 31;
    const int wm = wid >> 2, wn = wid & 3;
    const int lr = lane >> 2, lc = lane & 3;

    float acc[4][4][4];
    #pragma unroll
    for (int i = 0; i < 4; i++)
        #pragma unroll
        for (int j = 0; j < 4; j++)
            #pragma unroll
            for (int r = 0; r < 4; r++) acc[i][j][r] = 0.f;

    int ldrow[4], ldc4[4];
    #pragma unroll
    for (int i = 0; i < 4; i++) {
        int idx = tid * 4 + i;
        ldrow[i] = idx >> 3;
        ldc4[i]  = idx & 7;
    }

    const int nch = K >> 5;

    #pragma unroll
    for (int i = 0; i < 4; i++) {
        float4 va = *(const float4*)(A + (size_t)ldrow[i] * K + (ldc4[i] << 2));
        float4 vb = *(const float4*)(B + (size_t)ldrow[i] * K + (ldc4[i] << 2));
        float* pa = sm + ldrow[i] * TS + (ldc4[i] << 2);
        float* pb = sm + TILE_WORDS + ldrow[i] * TS + (ldc4[i] << 2);
        pa[0] = tf32r(va.x); pa[1] = tf32r(va.y); pa[2] = tf32r(va.z); pa[3] = tf32r(va.w);
        pb[0] = tf32r(vb.x); pb[1] = tf32r(vb.y); pb[2] = tf32r(vb.z); pb[3] = tf32r(vb.w);
    }
    __syncthreads();

    for (int c = 0; c < nch; c++) {
        const float* As = sm + (c & 1) * 2 * TILE_WORDS;
        const float* Bs = As + TILE_WORDS;

        float4 na[4], nb[4];
        if (c + 1 < nch) {
            const int k0 = (c + 1) << 5;
            #pragma unroll
            for (int i = 0; i < 4; i++) {
                na[i] = *(const float4*)(A + (size_t)ldrow[i] * K + k0 + (ldc4[i] << 2));
                nb[i] = *(const float4*)(B + (size_t)ldrow[i] * K + k0 + (ldc4[i] << 2));
            }
        }

        #pragma unroll
        for (int ks = 0; ks < 4; ks++) {
            const int kk = ks << 3;
            uint32_t af[4][4], bf[4][2];
            #pragma unroll
            for (int mi = 0; mi < 4; mi++) {
                const float* p = As + (wm * 64 + mi * 16 + lr) * TS + kk + lc;
                af[mi][0] = __float_as_uint(p[0]);
                af[mi][1] = __float_as_uint(p[8 * TS]);
                af[mi][2] = __float_as_uint(p[4]);
                af[mi][3] = __float_as_uint(p[8 * TS + 4]);
            }
            #pragma unroll
            for (int ni = 0; ni < 4; ni++) {
                const float* p = Bs + (wn * 32 + ni * 8 + lr) * TS + kk + lc;
                bf[ni][0] = __float_as_uint(p[0]);
                bf[ni][1] = __float_as_uint(p[4]);
            }
            #pragma unroll
            for (int mi = 0; mi < 4; mi++)
                #pragma unroll
                for (int ni = 0; ni < 4; ni++)
                    mma_tf32(acc[mi][ni], af[mi], bf[ni]);
        }

        if (c + 1 < nch) {
            float* dst = sm + ((c + 1) & 1) * 2 * TILE_WORDS;
            #pragma unroll
            for (int i = 0; i < 4; i++) {
                float* pa = dst + ldrow[i] * TS + (ldc4[i] << 2);
                float* pb = dst + TILE_WORDS + ldrow[i] * TS + (ldc4[i] << 2);
                pa[0] = tf32r(na[i].x); pa[1] = tf32r(na[i].y);
                pa[2] = tf32r(na[i].z); pa[3] = tf32r(na[i].w);
                pb[0] = tf32r(nb[i].x); pb[1] = tf32r(nb[i].y);
                pb[2] = tf32r(nb[i].z); pb[3] = tf32r(nb[i].w);
            }
        }
        __syncthreads();
    }

    #pragma unroll
    for (int mi = 0; mi < 4; mi++) {
        const int row = wm * 64 + mi * 16 + lr;
        #pragma unroll
        for (int ni = 0; ni < 4; ni++) {
            const int col = wn * 32 + ni * 8 + lc * 2;
            float2 v0 = { acc[mi][ni][0] * alpha, acc[mi][ni][1] * alpha };
            float2 v1 = { acc[mi][ni][2] * alpha, acc[mi][ni][3] * alpha };
            *(float2*)(C + (size_t)row * ldc + col)       = v0;
            *(float2*)(C + (size_t)(row + 8) * ldc + col) = v1;
        }
    }
}

// merged 3-way projection: grid (16, 32); x selects Wq/Wk/Wv column block
__global__ void __launch_bounds__(256, 1) proj_tc(
    const float* __restrict__ hs, const float* __restrict__ WAq,
    const float* __restrict__ WAk, const float* __restrict__ WAv,
    float* __restrict__ gA)
{
    extern __shared__ float sm[];
    const int x = blockIdx.x;
    const float* Bsel; int coff;
    if (x < 8)       { Bsel = WAq + (size_t)x * 128 * 2048;        coff = x * 128; }
    else if (x < 12) { Bsel = WAk + (size_t)(x - 8) * 128 * 2048;  coff = 1024 + (x - 8) * 128; }
    else             { Bsel = WAv + (size_t)(x - 12) * 128 * 2048; coff = 1536 + (x - 12) * 128; }
    const size_t m0 = (size_t)blockIdx.y << 7;
    gemm_body(sm, hs + m0 * 2048, Bsel, gA + m0 * 2048 + coff, 2048, 2048, 1.0f / 64.0f);
}

// output projection: grid (16, 32)
__global__ void __launch_bounds__(256, 1) oproj_tc(
    const float* __restrict__ ao, const float* __restrict__ Wo, float* __restrict__ out)
{
    extern __shared__ float sm[];
    const size_t m0 = (size_t)blockIdx.y << 7;
    const size_t n0 = (size_t)blockIdx.x << 7;
    gemm_body(sm, ao + m0 * 2048, Wo + n0 * 2048, out + m0 * 2048 + n0, 2048, 2048, 1.0f);
}

// ---------------------------------------------------------------------------
__global__ void zero2_kernel(float* a, float* b)
{
    size_t i = ((size_t)blockIdx.x * blockDim.x + threadIdx.x) * 4;
    float4 z = {0.f, 0.f, 0.f, 0.f};
    *(float4*)(a + i) = z;
    *(float4*)(b + i) = z;
}

// ---------------------------------------------------------------------------
// q/k/v build on tensor cores + fused RoPE + scatter.
// grid (32, 32): x = 128-row tile, y = head (0..15 q, 16..23 k, 24..31 v).
// CTA: 256 thr, 8 warps, warp tile m16 x n128, K=64.
// ---------------------------------------------------------------------------
#define QK_ATS 68
#define QK_BTS 136
#define QKV_SMEM ((128*QK_ATS + 64*QK_BTS) * 4)   // 69632 B

__global__ void __launch_bounds__(256, 1) qkv_tc(
    const float* __restrict__ gA,
    const float* __restrict__ Bq, const float* __restrict__ Bk, const float* __restrict__ Bv,
    const float* __restrict__ fcos, const float* __restrict__ fsin,
    const int* __restrict__ widx)
{
    extern __shared__ float sm[];
    float* As = sm;                     // [128][68]
    float* Bs = sm + 128 * QK_ATS;      // [64][136]  (k-major rows)

    const int tid = threadIdx.x, w = tid >> 5, lane = tid & 31;
    const int lr = lane >> 2, lc = lane & 3;
    const int m0 = blockIdx.x << 7;
    const int hh = blockIdx.y;

    const float* Bmat; int aoff;
    if (hh < 16)      { Bmat = Bq + (size_t)hh * 64 * 128;        aoff = hh * 64; }
    else if (hh < 24) { Bmat = Bk + (size_t)(hh - 16) * 64 * 128; aoff = 1024 + (hh - 16) * 64; }
    else              { Bmat = Bv + (size_t)(hh - 24) * 64 * 128; aoff = 1536 + (hh - 24) * 64; }

    // stage A (128x64) and B (64x128), tf32-rounded
    #pragma unroll
    for (int i = 0; i < 8; i++) {
        int idx = tid + i * 256;                 // 0..2047
        {   // A: row = idx>>4, col4 = idx&15
            int r = idx >> 4, c4 = idx & 15;
            float4 v = *(const float4*)(gA + (size_t)(m0 + r) * 2048 + aoff + (c4 << 2));
            float* p = As + r * QK_ATS + (c4 << 2);
            p[0] = tf32r(v.x); p[1] = tf32r(v.y); p[2] = tf32r(v.z); p[3] = tf32r(v.w);
        }
        {   // B: row(k) = idx>>5, col4 = idx&31
            int r = idx >> 5, c4 = idx & 31;
            float4 v = *(const float4*)(Bmat + (size_t)r * 128 + (c4 << 2));
            float* p = Bs + r * QK_BTS + (c4 << 2);
            p[0] = tf32r(v.x); p[1] = tf32r(v.y); p[2] = tf32r(v.z); p[3] = tf32r(v.w);
        }
    }
    __syncthreads();

    float acc[16][4];
    #pragma unroll
    for (int i = 0; i < 16; i++)
        #pragma unroll
        for (int j = 0; j < 4; j++) acc[i][j] = 0.f;

    #pragma unroll
    for (int k8 = 0; k8 < 8; k8++) {
        const float* pa = As + (w * 16 + lr) * QK_ATS + (k8 << 3) + lc;
        uint32_t af[4] = { __float_as_uint(pa[0]), __float_as_uint(pa[8 * QK_ATS]),
                           __float_as_uint(pa[4]), __float_as_uint(pa[8 * QK_ATS + 4]) };
        #pragma unroll
        for (int nd = 0; nd < 16; nd++) {
            const float* pb = Bs + ((k8 << 3) + lc) * QK_BTS + (nd << 3) + lr;
            uint32_t bf[2] = { __float_as_uint(pb[0]), __float_as_uint(pb[4 * QK_BTS]) };
            mma_tf32(acc[nd], af, bf);
        }
    }

    // epilogue: RoPE (q,k) + scatter
    const int r0 = m0 + w * 16 + lr, r1 = r0 + 8;
    const int b  = r0 >> 11;
    const int s0 = r0 & 2047, s1 = s0 + 8;

    float *o0, *o1; int pos0, pos1;
    if (hh < 16) {
        pos0 = s0; pos1 = s1;
        o0 = g_q + ((size_t)(b * H_ + hh) * S_ + s0) * D_;
        o1 = g_q + ((size_t)(b * H_ + hh) * S_ + s1) * D_;
    } else if (hh < 24) {
        pos0 = widx[s0]; pos1 = widx[s1];
        o0 = g_k + ((size_t)(b * HKV_ + hh - 16) * S_ + pos0) * D_;
        o1 = g_k + ((size_t)(b * HKV_ + hh - 16) * S_ + pos1) * D_;
    } else {
        pos0 = widx[s0]; pos1 = widx[s1];
        o0 = g_v + ((size_t)(b * HKV_ + hh - 24) * S_ + pos0) * D_;
        o1 = g_v + ((size_t)(b * HKV_ + hh - 24) * S_ + pos1) * D_;
    }

    if (hh < 24) {   // RoPE heads
        #pragma unroll
        for (int nd = 0; nd < 8; nd++) {
            const int d0 = (nd << 3) + 2 * lc;
            float2 c0 = *(const float2*)(fcos + (size_t)pos0 * 64 + d0);
            float2 n0v = *(const float2*)(fsin + (size_t)pos0 * 64 + d0);
            float2 c1 = *(const float2*)(fcos + (size_t)pos1 * 64 + d0);
            float2 n1v = *(const float2*)(fsin + (size_t)pos1 * 64 + d0);
            float x10 = acc[nd][0], x11 = acc[nd][1];
            float x20 = acc[nd + 8][0], x21 = acc[nd + 8][1];
            float2 lo0 = { x10 * c0.x - x20 * n0v.x, x11 * c0.y - x21 * n0v.y };
            float2 hi0 = { x10 * n0v.x + x20 * c0.x, x11 * n0v.y + x21 * c0.y };
            *(float2*)(o0 + d0)      = lo0;
            *(float2*)(o0 + d0 + 64) = hi0;
            float y10 = acc[nd][2], y11 = acc[nd][3];
            float y20 = acc[nd + 8][2], y21 = acc[nd + 8][3];
            float2 lo1 = { y10 * c1.x - y20 * n1v.x, y11 * c1.y - y21 * n1v.y };
            float2 hi1 = { y10 * n1v.x + y20 * c1.x, y11 * n1v.y + y21 * c1.y };
            *(float2*)(o1 + d0)      = lo1;
            *(float2*)(o1 + d0 + 64) = hi1;
        }
    } else {         // V: direct store
        #pragma unroll
        for (int nd = 0; nd < 16; nd++) {
            const int d0 = (nd << 3) + 2 * lc;
            float2 a = { acc[nd][0], acc[nd][1] };
            float2 c = { acc[nd][2], acc[nd][3] };
            *(float2*)(o0 + d0) = a;
            *(float2*)(o1 + d0) = c;
        }
    }
}

// ---------------------------------------------------------------------------
// Flash attention, tf32 mma. 128 q-rows per CTA, 8 warps (m16 each),
// k-tiles of 64. Q frags register-resident (staged via smem overlay).
// ---------------------------------------------------------------------------
#define KTS2 132
#define VTS2 136
#define PTS2 68
#define FL2_SMEM ((64*KTS2 + 64*VTS2 + 128*PTS2) * 4)   // 103424 B

__global__ void __launch_bounds__(256, 1) flash_tc2()
{
    extern __shared__ float sm[];
    float* Ks  = sm;
    float* Vs  = Ks + 64 * KTS2;
    float* Ps  = Vs + 64 * VTS2;
    float* Qst = Vs;            // Q staging overlay (128*KTS2 <= 64*VTS2+128*PTS2)

    const int tid = threadIdx.x, w = tid >> 5, lane = tid & 31;
    const int lr = lane >> 2, lc = lane & 3;
    const int qt = (int)gridDim.x - 1 - (int)blockIdx.x;   // long CTAs first
    const int bh = blockIdx.y;
    const int b = bh >> 4, h = bh & 15, kvh = h >> 1;
    const int qp = qt << 7;

    const float* qbase = g_q + ((size_t)(b * H_ + h) * S_ + qp) * D_;
    const float* kbase = g_k + (size_t)(b * HKV_ + kvh) * S_ * D_;
    const float* vbase = g_v + (size_t)(b * HKV_ + kvh) * S_ * D_;
    const float SC = 0.088388347648318447f;

    // stage Q (scaled + tf32), pull frags
    for (int i = tid; i < 128 * 32; i += 256) {
        int r = i >> 5, c4 = (i & 31) << 2;
        float4 v = *(const float4*)(qbase + (size_t)r * 128 + c4);
        float* p = Qst + r * KTS2 + c4;
        p[0] = tf32r(v.x * SC); p[1] = tf32r(v.y * SC);
        p[2] = tf32r(v.z * SC); p[3] = tf32r(v.w * SC);
    }
    __syncthreads();

    uint32_t qf[16][4];
    #pragma unroll
    for (int k8 = 0; k8 < 16; k8++) {
        const float* p = Qst + (w * 16 + lr) * KTS2 + (k8 << 3) + lc;
        qf[k8][0] = __float_as_uint(p[0]);
        qf[k8][1] = __float_as_uint(p[8 * KTS2]);
        qf[k8][2] = __float_as_uint(p[4]);
        qf[k8][3] = __float_as_uint(p[8 * KTS2 + 4]);
    }
    __syncthreads();

    float oacc[16][4];
    #pragma unroll
    for (int i = 0; i < 16; i++)
        #pragma unroll
        for (int j = 0; j < 4; j++) oacc[i][j] = 0.f;
    float m0 = -1e30f, m1 = -1e30f, l0 = 0.f, l1 = 0.f;
    const int r0g = qp + w * 16 + lr, r1g = r0g + 8;

    const int ktmax = 2 * qt + 1;
    for (int kt = 0; kt <= ktmax; kt++) {
        const float* kp = kbase + (size_t)kt * 64 * 128;
        const float* vp = vbase + (size_t)kt * 64 * 128;
        for (int i = tid; i < 64 * 32; i += 256) {
            int r = i >> 5, c4 = (i & 31) << 2;
            float4 k4 = *(const float4*)(kp + (size_t)r * 128 + c4);
            float4 v4 = *(const float4*)(vp + (size_t)r * 128 + c4);
            float* pk = Ks + r * KTS2 + c4;
            pk[0] = tf32r(k4.x); pk[1] = tf32r(k4.y); pk[2] = tf32r(k4.z); pk[3] = tf32r(k4.w);
            float* pv = Vs + r * VTS2 + c4;
            pv[0] = tf32r(v4.x); pv[1] = tf32r(v4.y); pv[2] = tf32r(v4.z); pv[3] = tf32r(v4.w);
        }
        __syncthreads();

        // S = Q K^T  (warp: 16 rows x 64 cols)
        float sacc[8][4];
        #pragma unroll
        for (int i = 0; i < 8; i++)
            #pragma unroll
            for (int j = 0; j < 4; j++) sacc[i][j] = 0.f;

        #pragma unroll
        for (int k8 = 0; k8 < 16; k8++) {
            #pragma unroll
            for (int nt = 0; nt < 8; nt++) {
                const float* p = Ks + (nt * 8 + lr) * KTS2 + (k8 << 3) + lc;
                uint32_t bf[2] = { __float_as_uint(p[0]), __float_as_uint(p[4]) };
                mma_tf32(sacc[nt], qf[k8], bf);
            }
        }

        if (kt >= 2 * qt) {   // diagonal region: causal mask
            const int cb = kt * 64;
            #pragma unroll
            for (int nt = 0; nt < 8; nt++) {
                int c0 = cb + nt * 8 + 2 * lc;
                if (c0     > r0g) sacc[nt][0] = -1e30f;
                if (c0 + 1 > r0g) sacc[nt][1] = -1e30f;
                if (c0     > r1g) sacc[nt][2] = -1e30f;
                if (c0 + 1 > r1g) sacc[nt][3] = -1e30f;
            }
        }

        // online softmax
        float mi0 = -1e30f, mi1 = -1e30f;
        #pragma unroll
        for (int nt = 0; nt < 8; nt++) {
            mi0 = fmaxf(mi0, fmaxf(sacc[nt][0], sacc[nt][1]));
            mi1 = fmaxf(mi1, fmaxf(sacc[nt][2], sacc[nt][3]));
        }
        mi0 = fmaxf(mi0, __shfl_xor_sync(0xffffffffu, mi0, 1));
        mi0 = fmaxf(mi0, __shfl_xor_sync(0xffffffffu, mi0, 2));
        mi1 = fmaxf(mi1, __shfl_xor_sync(0xffffffffu, mi1, 1));
        mi1 = fmaxf(mi1, __shfl_xor_sync(0xffffffffu, mi1, 2));
        float mn0 = fmaxf(m0, mi0), mn1 = fmaxf(m1, mi1);
        float sf0 = __expf(m0 - mn0), sf1 = __expf(m1 - mn1);
        m0 = mn0; m1 = mn1;

        float ps0 = 0.f, ps1 = 0.f;
        float* pr0 = Ps + (w * 16 + lr) * PTS2 + 2 * lc;
        float* pr1 = pr0 + 8 * PTS2;
        #pragma unroll
        for (int nt = 0; nt < 8; nt++) {
            float p00 = __expf(sacc[nt][0] - m0), p01 = __expf(sacc[nt][1] - m0);
            float p10 = __expf(sacc[nt][2] - m1), p11 = __expf(sacc[nt][3] - m1);
            ps0 += p00 + p01; ps1 += p10 + p11;
            float2 a = { tf32r(p00), tf32r(p01) };
            float2 c = { tf32r(p10), tf32r(p11) };
            *(float2*)(pr0 + nt * 8) = a;
            *(float2*)(pr1 + nt * 8) = c;
        }
        ps0 += __shfl_xor_sync(0xffffffffu, ps0, 1);
        ps0 += __shfl_xor_sync(0xffffffffu, ps0, 2);
        ps1 += __shfl_xor_sync(0xffffffffu, ps1, 1);
        ps1 += __shfl_xor_sync(0xffffffffu, ps1, 2);
        l0 = l0 * sf0 + ps0;
        l1 = l1 * sf1 + ps1;

        #pragma unroll
        for (int nd = 0; nd < 16; nd++) {
            oacc[nd][0] *= sf0; oacc[nd][1] *= sf0;
            oacc[nd][2] *= sf1; oacc[nd][3] *= sf1;
        }
        __syncwarp();

        // O += P V
        #pragma unroll
        for (int ks = 0; ks < 8; ks++) {
            const float* pa = Ps + (w * 16 + lr) * PTS2 + (ks << 3) + lc;
            uint32_t af[4] = { __float_as_uint(pa[0]), __float_as_uint(pa[8 * PTS2]),
                               __float_as_uint(pa[4]), __float_as_uint(pa[8 * PTS2 + 4]) };
            #pragma unroll
            for (int nd = 0; nd < 16; nd++) {
                const float* pb = Vs + ((ks << 3) + lc) * VTS2 + (nd << 3) + lr;
                uint32_t bf[2] = { __float_as_uint(pb[0]), __float_as_uint(pb[4 * VTS2]) };
                mma_tf32(oacc[nd], af, bf);
            }
        }
        __syncthreads();
    }

    // epilogue
    float i0 = 1.f / l0, i1 = 1.f / l1;
    float* o0 = g_ao + ((size_t)b * S_ + r0g) * 2048 + h * 128 + 2 * lc;
    float* o1 = g_ao + ((size_t)b * S_ + r1g) * 2048 + h * 128 + 2 * lc;
    #pragma unroll
    for (int nd = 0; nd < 16; nd++) {
        float2 a = { oacc[nd][0] * i0, oacc[nd][1] * i0 };
        float2 c = { oacc[nd][2] * i1, oacc[nd][3] * i1 };
        *(float2*)(o0 + nd * 8) = a;
        *(float2*)(o1 + nd * 8) = c;
    }
}

// ---------------------------------------------------------------------------
extern "C" void kernel_launch(void* const* d_in, const int* in_sizes, int n_in,
                              void* d_out, int out_size)
{
    const float* hs   = (const float*)d_in[0];
    const float* WAq  = (const float*)d_in[1];
    const float* WAk  = (const float*)d_in[2];
    const float* WAv  = (const float*)d_in[3];
    const float* Bq   = (const float*)d_in[4];
    const float* Bk   = (const float*)d_in[5];
    const float* Bv   = (const float*)d_in[6];
    const float* Wo   = (const float*)d_in[7];
    const float* fcos = (const float*)d_in[8];
    const float* fsin = (const float*)d_in[9];
    const int*   widx = (const int*)d_in[11];
    float* out = (float*)d_out;

    float *pA, *pk, *pv, *pao;
    cudaGetSymbolAddress((void**)&pA,  g_A);
    cudaGetSymbolAddress((void**)&pk,  g_k);
    cudaGetSymbolAddress((void**)&pv,  g_v);
    cudaGetSymbolAddress((void**)&pao, g_ao);

    cudaFuncSetAttribute(proj_tc,  cudaFuncAttributeMaxDynamicSharedMemorySize, GT_SMEM);
    cudaFuncSetAttribute(oproj_tc, cudaFuncAttributeMaxDynamicSharedMemorySize, GT_SMEM);
    cudaFuncSetAttribute(qkv_tc,   cudaFuncAttributeMaxDynamicSharedMemorySize, QKV_SMEM);
    cudaFuncSetAttribute(flash_tc2,cudaFuncAttributeMaxDynamicSharedMemorySize, FL2_SMEM);

    // 0) zero KV caches (scatter semantics)
    zero2_kernel<<<(B_*HKV_*S_*D_) / (4 * 256), 256>>>(pk, pv);

    // 1) low-rank projections (merged, alpha folds the /64)
    proj_tc<<<dim3(16, 32), 256, GT_SMEM>>>(hs, WAq, WAk, WAv, pA);

    // 2) q/k/v build on tensor cores (+RoPE, scatter)
    qkv_tc<<<dim3(32, 32), 256, QKV_SMEM>>>(pA, Bq, Bk, Bv, fcos, fsin, widx);

    // 3) causal flash attention (tf32 tensor cores, 128-row tiles)
    flash_tc2<<<dim3(S_ / 128, B_ * H_), 256, FL2_SMEM>>>();

    // 4) output projection
    oproj_tc<<<dim3(16, 32), 256, GT_SMEM>>>(pao, Wo, out);
}

// round 6
// speedup vs baseline: 2.9290x; 1.0000x over previous
#include <cuda_runtime.h>
#include <cstdint>

// Problem constants
#define B_   2
#define S_   2048
#define H_   16
#define HKV_ 8
#define D_   128
#define NROW (B_*S_)   // 4096

// Scratch (device globals — no allocation allowed)
__device__ __align__(16) float g_A [(size_t)NROW*2048];            // [row][1024 Aq | 512 Ak | 512 Av]
__device__ __align__(16) float g_q [(size_t)B_*H_  *S_*D_];
__device__ __align__(16) float g_k [(size_t)B_*HKV_*S_*D_];
__device__ __align__(16) float g_v [(size_t)B_*HKV_*S_*D_];
__device__ __align__(16) float g_ao[(size_t)NROW*2048];

// ---------------------------------------------------------------------------
__device__ __forceinline__ uint32_t f2tf32(float x) {   // round-to-nearest tf32
    uint32_t r;
    asm("cvt.rna.tf32.f32 %0, %1;" : "=r"(r) : "f"(x));
    return r;
}
__device__ __forceinline__ float tf32r(float x) { return __uint_as_float(f2tf32(x)); }

__device__ __forceinline__ void mma_tf32(float* c, const uint32_t* a, const uint32_t* b) {
    asm volatile(
        "mma.sync.aligned.m16n8k8.row.col.f32.tf32.tf32.f32 "
        "{%0,%1,%2,%3}, {%4,%5,%6,%7}, {%8,%9}, {%0,%1,%2,%3};"
        : "+f"(c[0]), "+f"(c[1]), "+f"(c[2]), "+f"(c[3])
        : "r"(a[0]), "r"(a[1]), "r"(a[2]), "r"(a[3]), "r"(b[0]), "r"(b[1]));
}

// ---------------------------------------------------------------------------
// Shared tf32 GEMM body: C[m][n] = alpha * sum_k A[m][k]*B[n][k], 128x128 tile.
// ---------------------------------------------------------------------------
#define TS 36
#define TILE_WORDS (128*TS)
#define GT_SMEM (2*2*TILE_WORDS*4)

__device__ __forceinline__ void gemm_body(
    float* sm, const float* __restrict__ A, const float* __restrict__ B,
    float* __restrict__ C, int K, int ldc, float alpha)
{
    const int tid = threadIdx.x;
    const int wid = tid >> 5, lane = tid & 31;
    const int wm = wid >> 2, wn = wid & 3;
    const int lr = lane >> 2, lc = lane & 3;

    float acc[4][4][4];
    #pragma unroll
    for (int i = 0; i < 4; i++)
        #pragma unroll
        for (int j = 0; j < 4; j++)
            #pragma unroll
            for (int r = 0; r < 4; r++) acc[i][j][r] = 0.f;

    int ldrow[4], ldc4[4];
    #pragma unroll
    for (int i = 0; i < 4; i++) {
        int idx = tid * 4 + i;
        ldrow[i] = idx >> 3;
        ldc4[i]  = idx & 7;
    }

    const int nch = K >> 5;

    #pragma unroll
    for (int i = 0; i < 4; i++) {
        float4 va = *(const float4*)(A + (size_t)ldrow[i] * K + (ldc4[i] << 2));
        float4 vb = *(const float4*)(B + (size_t)ldrow[i] * K + (ldc4[i] << 2));
        float* pa = sm + ldrow[i] * TS + (ldc4[i] << 2);
        float* pb = sm + TILE_WORDS + ldrow[i] * TS + (ldc4[i] << 2);
        pa[0] = tf32r(va.x); pa[1] = tf32r(va.y); pa[2] = tf32r(va.z); pa[3] = tf32r(va.w);
        pb[0] = tf32r(vb.x); pb[1] = tf32r(vb.y); pb[2] = tf32r(vb.z); pb[3] = tf32r(vb.w);
    }
    __syncthreads();

    for (int c = 0; c < nch; c++) {
        const float* As = sm + (c & 1) * 2 * TILE_WORDS;
        const float* Bs = As + TILE_WORDS;

        float4 na[4], nb[4];
        if (c + 1 < nch) {
            const int k0 = (c + 1) << 5;
            #pragma unroll
            for (int i = 0; i < 4; i++) {
                na[i] = *(const float4*)(A + (size_t)ldrow[i] * K + k0 + (ldc4[i] << 2));
                nb[i] = *(const float4*)(B + (size_t)ldrow[i] * K + k0 + (ldc4[i] << 2));
            }
        }

        #pragma unroll
        for (int ks = 0; ks < 4; ks++) {
            const int kk = ks << 3;
            uint32_t af[4][4], bf[4][2];
            #pragma unroll
            for (int mi = 0; mi < 4; mi++) {
                const float* p = As + (wm * 64 + mi * 16 + lr) * TS + kk + lc;
                af[mi][0] = __float_as_uint(p[0]);
                af[mi][1] = __float_as_uint(p[8 * TS]);
                af[mi][2] = __float_as_uint(p[4]);
                af[mi][3] = __float_as_uint(p[8 * TS + 4]);
            }
            #pragma unroll
            for (int ni = 0; ni < 4; ni++) {
                const float* p = Bs + (wn * 32 + ni * 8 + lr) * TS + kk + lc;
                bf[ni][0] = __float_as_uint(p[0]);
                bf[ni][1] = __float_as_uint(p[4]);
            }
            #pragma unroll
            for (int mi = 0; mi < 4; mi++)
                #pragma unroll
                for (int ni = 0; ni < 4; ni++)
                    mma_tf32(acc[mi][ni], af[mi], bf[ni]);
        }

        if (c + 1 < nch) {
            float* dst = sm + ((c + 1) & 1) * 2 * TILE_WORDS;
            #pragma unroll
            for (int i = 0; i < 4; i++) {
                float* pa = dst + ldrow[i] * TS + (ldc4[i] << 2);
                float* pb = dst + TILE_WORDS + ldrow[i] * TS + (ldc4[i] << 2);
                pa[0] = tf32r(na[i].x); pa[1] = tf32r(na[i].y);
                pa[2] = tf32r(na[i].z); pa[3] = tf32r(na[i].w);
                pb[0] = tf32r(nb[i].x); pb[1] = tf32r(nb[i].y);
                pb[2] = tf32r(nb[i].z); pb[3] = tf32r(nb[i].w);
            }
        }
        __syncthreads();
    }

    #pragma unroll
    for (int mi = 0; mi < 4; mi++) {
        const int row = wm * 64 + mi * 16 + lr;
        #pragma unroll
        for (int ni = 0; ni < 4; ni++) {
            const int col = wn * 32 + ni * 8 + lc * 2;
            float2 v0 = { acc[mi][ni][0] * alpha, acc[mi][ni][1] * alpha };
            float2 v1 = { acc[mi][ni][2] * alpha, acc[mi][ni][3] * alpha };
            *(float2*)(C + (size_t)row * ldc + col)       = v0;
            *(float2*)(C + (size_t)(row + 8) * ldc + col) = v1;
        }
    }
}

// merged 3-way projection: grid (16, 32); x selects Wq/Wk/Wv column block
__global__ void __launch_bounds__(256, 1) proj_tc(
    const float* __restrict__ hs, const float* __restrict__ WAq,
    const float* __restrict__ WAk, const float* __restrict__ WAv,
    float* __restrict__ gA)
{
    extern __shared__ float sm[];
    const int x = blockIdx.x;
    const float* Bsel; int coff;
    if (x < 8)       { Bsel = WAq + (size_t)x * 128 * 2048;        coff = x * 128; }
    else if (x < 12) { Bsel = WAk + (size_t)(x - 8) * 128 * 2048;  coff = 1024 + (x - 8) * 128; }
    else             { Bsel = WAv + (size_t)(x - 12) * 128 * 2048; coff = 1536 + (x - 12) * 128; }
    const size_t m0 = (size_t)blockIdx.y << 7;
    gemm_body(sm, hs + m0 * 2048, Bsel, gA + m0 * 2048 + coff, 2048, 2048, 1.0f / 64.0f);
}

// output projection: grid (16, 32)
__global__ void __launch_bounds__(256, 1) oproj_tc(
    const float* __restrict__ ao, const float* __restrict__ Wo, float* __restrict__ out)
{
    extern __shared__ float sm[];
    const size_t m0 = (size_t)blockIdx.y << 7;
    const size_t n0 = (size_t)blockIdx.x << 7;
    gemm_body(sm, ao + m0 * 2048, Wo + n0 * 2048, out + m0 * 2048 + n0, 2048, 2048, 1.0f);
}

// ---------------------------------------------------------------------------
__global__ void zero2_kernel(float* a, float* b)
{
    size_t i = ((size_t)blockIdx.x * blockDim.x + threadIdx.x) * 4;
    float4 z = {0.f, 0.f, 0.f, 0.f};
    *(float4*)(a + i) = z;
    *(float4*)(b + i) = z;
}

// ---------------------------------------------------------------------------
// q/k/v build on tensor cores + fused RoPE + scatter.
// grid (32, 32): x = 128-row tile, y = head (0..15 q, 16..23 k, 24..31 v).
// CTA: 256 thr, 8 warps, warp tile m16 x n128, K=64.
// ---------------------------------------------------------------------------
#define QK_ATS 68
#define QK_BTS 136
#define QKV_SMEM ((128*QK_ATS + 64*QK_BTS) * 4)   // 69632 B

__global__ void __launch_bounds__(256, 1) qkv_tc(
    const float* __restrict__ gA,
    const float* __restrict__ Bq, const float* __restrict__ Bk, const float* __restrict__ Bv,
    const float* __restrict__ fcos, const float* __restrict__ fsin,
    const int* __restrict__ widx)
{
    extern __shared__ float sm[];
    float* As = sm;                     // [128][68]
    float* Bs = sm + 128 * QK_ATS;      // [64][136]  (k-major rows)

    const int tid = threadIdx.x, w = tid >> 5, lane = tid & 31;
    const int lr = lane >> 2, lc = lane & 3;
    const int m0 = blockIdx.x << 7;
    const int hh = blockIdx.y;

    const float* Bmat; int aoff;
    if (hh < 16)      { Bmat = Bq + (size_t)hh * 64 * 128;        aoff = hh * 64; }
    else if (hh < 24) { Bmat = Bk + (size_t)(hh - 16) * 64 * 128; aoff = 1024 + (hh - 16) * 64; }
    else              { Bmat = Bv + (size_t)(hh - 24) * 64 * 128; aoff = 1536 + (hh - 24) * 64; }

    // stage A (128x64) and B (64x128), tf32-rounded
    #pragma unroll
    for (int i = 0; i < 8; i++) {
        int idx = tid + i * 256;                 // 0..2047
        {   // A: row = idx>>4, col4 = idx&15
            int r = idx >> 4, c4 = idx & 15;
            float4 v = *(const float4*)(gA + (size_t)(m0 + r) * 2048 + aoff + (c4 << 2));
            float* p = As + r * QK_ATS + (c4 << 2);
            p[0] = tf32r(v.x); p[1] = tf32r(v.y); p[2] = tf32r(v.z); p[3] = tf32r(v.w);
        }
        {   // B: row(k) = idx>>5, col4 = idx&31
            int r = idx >> 5, c4 = idx & 31;
            float4 v = *(const float4*)(Bmat + (size_t)r * 128 + (c4 << 2));
            float* p = Bs + r * QK_BTS + (c4 << 2);
            p[0] = tf32r(v.x); p[1] = tf32r(v.y); p[2] = tf32r(v.z); p[3] = tf32r(v.w);
        }
    }
    __syncthreads();

    float acc[16][4];
    #pragma unroll
    for (int i = 0; i < 16; i++)
        #pragma unroll
        for (int j = 0; j < 4; j++) acc[i][j] = 0.f;

    #pragma unroll
    for (int k8 = 0; k8 < 8; k8++) {
        const float* pa = As + (w * 16 + lr) * QK_ATS + (k8 << 3) + lc;
        uint32_t af[4] = { __float_as_uint(pa[0]), __float_as_uint(pa[8 * QK_ATS]),
                           __float_as_uint(pa[4]), __float_as_uint(pa[8 * QK_ATS + 4]) };
        #pragma unroll
        for (int nd = 0; nd < 16; nd++) {
            const float* pb = Bs + ((k8 << 3) + lc) * QK_BTS + (nd << 3) + lr;
            uint32_t bf[2] = { __float_as_uint(pb[0]), __float_as_uint(pb[4 * QK_BTS]) };
            mma_tf32(acc[nd], af, bf);
        }
    }

    // epilogue: RoPE (q,k) + scatter
    const int r0 = m0 + w * 16 + lr, r1 = r0 + 8;
    const int b  = r0 >> 11;
    const int s0 = r0 & 2047, s1 = s0 + 8;

    float *o0, *o1; int pos0, pos1;
    if (hh < 16) {
        pos0 = s0; pos1 = s1;
        o0 = g_q + ((size_t)(b * H_ + hh) * S_ + s0) * D_;
        o1 = g_q + ((size_t)(b * H_ + hh) * S_ + s1) * D_;
    } else if (hh < 24) {
        pos0 = widx[s0]; pos1 = widx[s1];
        o0 = g_k + ((size_t)(b * HKV_ + hh - 16) * S_ + pos0) * D_;
        o1 = g_k + ((size_t)(b * HKV_ + hh - 16) * S_ + pos1) * D_;
    } else {
        pos0 = widx[s0]; pos1 = widx[s1];
        o0 = g_v + ((size_t)(b * HKV_ + hh - 24) * S_ + pos0) * D_;
        o1 = g_v + ((size_t)(b * HKV_ + hh - 24) * S_ + pos1) * D_;
    }

    if (hh < 24) {   // RoPE heads
        #pragma unroll
        for (int nd = 0; nd < 8; nd++) {
            const int d0 = (nd << 3) + 2 * lc;
            float2 c0 = *(const float2*)(fcos + (size_t)pos0 * 64 + d0);
            float2 n0v = *(const float2*)(fsin + (size_t)pos0 * 64 + d0);
            float2 c1 = *(const float2*)(fcos + (size_t)pos1 * 64 + d0);
            float2 n1v = *(const float2*)(fsin + (size_t)pos1 * 64 + d0);
            float x10 = acc[nd][0], x11 = acc[nd][1];
            float x20 = acc[nd + 8][0], x21 = acc[nd + 8][1];
            float2 lo0 = { x10 * c0.x - x20 * n0v.x, x11 * c0.y - x21 * n0v.y };
            float2 hi0 = { x10 * n0v.x + x20 * c0.x, x11 * n0v.y + x21 * c0.y };
            *(float2*)(o0 + d0)      = lo0;
            *(float2*)(o0 + d0 + 64) = hi0;
            float y10 = acc[nd][2], y11 = acc[nd][3];
            float y20 = acc[nd + 8][2], y21 = acc[nd + 8][3];
            float2 lo1 = { y10 * c1.x - y20 * n1v.x, y11 * c1.y - y21 * n1v.y };
            float2 hi1 = { y10 * n1v.x + y20 * c1.x, y11 * n1v.y + y21 * c1.y };
            *(float2*)(o1 + d0)      = lo1;
            *(float2*)(o1 + d0 + 64) = hi1;
        }
    } else {         // V: direct store
        #pragma unroll
        for (int nd = 0; nd < 16; nd++) {
            const int d0 = (nd << 3) + 2 * lc;
            float2 a = { acc[nd][0], acc[nd][1] };
            float2 c = { acc[nd][2], acc[nd][3] };
            *(float2*)(o0 + d0) = a;
            *(float2*)(o1 + d0) = c;
        }
    }
}

// ---------------------------------------------------------------------------
// Flash attention, tf32 mma. 128 q-rows per CTA, 8 warps (m16 each),
// k-tiles of 64. Q frags register-resident (staged via smem overlay).
// ---------------------------------------------------------------------------
#define KTS2 132
#define VTS2 136
#define PTS2 68
#define FL2_SMEM ((64*KTS2 + 64*VTS2 + 128*PTS2) * 4)   // 103424 B

__global__ void __launch_bounds__(256, 1) flash_tc2()
{
    extern __shared__ float sm[];
    float* Ks  = sm;
    float* Vs  = Ks + 64 * KTS2;
    float* Ps  = Vs + 64 * VTS2;
    float* Qst = Vs;            // Q staging overlay (128*KTS2 <= 64*VTS2+128*PTS2)

    const int tid = threadIdx.x, w = tid >> 5, lane = tid & 31;
    const int lr = lane >> 2, lc = lane & 3;
    const int qt = (int)gridDim.x - 1 - (int)blockIdx.x;   // long CTAs first
    const int bh = blockIdx.y;
    const int b = bh >> 4, h = bh & 15, kvh = h >> 1;
    const int qp = qt << 7;

    const float* qbase = g_q + ((size_t)(b * H_ + h) * S_ + qp) * D_;
    const float* kbase = g_k + (size_t)(b * HKV_ + kvh) * S_ * D_;
    const float* vbase = g_v + (size_t)(b * HKV_ + kvh) * S_ * D_;
    const float SC = 0.088388347648318447f;

    // stage Q (scaled + tf32), pull frags
    for (int i = tid; i < 128 * 32; i += 256) {
        int r = i >> 5, c4 = (i & 31) << 2;
        float4 v = *(const float4*)(qbase + (size_t)r * 128 + c4);
        float* p = Qst + r * KTS2 + c4;
        p[0] = tf32r(v.x * SC); p[1] = tf32r(v.y * SC);
        p[2] = tf32r(v.z * SC); p[3] = tf32r(v.w * SC);
    }
    __syncthreads();

    uint32_t qf[16][4];
    #pragma unroll
    for (int k8 = 0; k8 < 16; k8++) {
        const float* p = Qst + (w * 16 + lr) * KTS2 + (k8 << 3) + lc;
        qf[k8][0] = __float_as_uint(p[0]);
        qf[k8][1] = __float_as_uint(p[8 * KTS2]);
        qf[k8][2] = __float_as_uint(p[4]);
        qf[k8][3] = __float_as_uint(p[8 * KTS2 + 4]);
    }
    __syncthreads();

    float oacc[16][4];
    #pragma unroll
    for (int i = 0; i < 16; i++)
        #pragma unroll
        for (int j = 0; j < 4; j++) oacc[i][j] = 0.f;
    float m0 = -1e30f, m1 = -1e30f, l0 = 0.f, l1 = 0.f;
    const int r0g = qp + w * 16 + lr, r1g = r0g + 8;

    const int ktmax = 2 * qt + 1;
    for (int kt = 0; kt <= ktmax; kt++) {
        const float* kp = kbase + (size_t)kt * 64 * 128;
        const float* vp = vbase + (size_t)kt * 64 * 128;
        for (int i = tid; i < 64 * 32; i += 256) {
            int r = i >> 5, c4 = (i & 31) << 2;
            float4 k4 = *(const float4*)(kp + (size_t)r * 128 + c4);
            float4 v4 = *(const float4*)(vp + (size_t)r * 128 + c4);
            float* pk = Ks + r * KTS2 + c4;
            pk[0] = tf32r(k4.x); pk[1] = tf32r(k4.y); pk[2] = tf32r(k4.z); pk[3] = tf32r(k4.w);
            float* pv = Vs + r * VTS2 + c4;
            pv[0] = tf32r(v4.x); pv[1] = tf32r(v4.y); pv[2] = tf32r(v4.z); pv[3] = tf32r(v4.w);
        }
        __syncthreads();

        // S = Q K^T  (warp: 16 rows x 64 cols)
        float sacc[8][4];
        #pragma unroll
        for (int i = 0; i < 8; i++)
            #pragma unroll
            for (int j = 0; j < 4; j++) sacc[i][j] = 0.f;

        #pragma unroll
        for (int k8 = 0; k8 < 16; k8++) {
            #pragma unroll
            for (int nt = 0; nt < 8; nt++) {
                const float* p = Ks + (nt * 8 + lr) * KTS2 + (k8 << 3) + lc;
                uint32_t bf[2] = { __float_as_uint(p[0]), __float_as_uint(p[4]) };
                mma_tf32(sacc[nt], qf[k8], bf);
            }
        }

        if (kt >= 2 * qt) {   // diagonal region: causal mask
            const int cb = kt * 64;
            #pragma unroll
            for (int nt = 0; nt < 8; nt++) {
                int c0 = cb + nt * 8 + 2 * lc;
                if (c0     > r0g) sacc[nt][0] = -1e30f;
                if (c0 + 1 > r0g) sacc[nt][1] = -1e30f;
                if (c0     > r1g) sacc[nt][2] = -1e30f;
                if (c0 + 1 > r1g) sacc[nt][3] = -1e30f;
            }
        }

        // online softmax
        float mi0 = -1e30f, mi1 = -1e30f;
        #pragma unroll
        for (int nt = 0; nt < 8; nt++) {
            mi0 = fmaxf(mi0, fmaxf(sacc[nt][0], sacc[nt][1]));
            mi1 = fmaxf(mi1, fmaxf(sacc[nt][2], sacc[nt][3]));
        }
        mi0 = fmaxf(mi0, __shfl_xor_sync(0xffffffffu, mi0, 1));
        mi0 = fmaxf(mi0, __shfl_xor_sync(0xffffffffu, mi0, 2));
        mi1 = fmaxf(mi1, __shfl_xor_sync(0xffffffffu, mi1, 1));
        mi1 = fmaxf(mi1, __shfl_xor_sync(0xffffffffu, mi1, 2));
        float mn0 = fmaxf(m0, mi0), mn1 = fmaxf(m1, mi1);
        float sf0 = __expf(m0 - mn0), sf1 = __expf(m1 - mn1);
        m0 = mn0; m1 = mn1;

        float ps0 = 0.f, ps1 = 0.f;
        float* pr0 = Ps + (w * 16 + lr) * PTS2 + 2 * lc;
        float* pr1 = pr0 + 8 * PTS2;
        #pragma unroll
        for (int nt = 0; nt < 8; nt++) {
            float p00 = __expf(sacc[nt][0] - m0), p01 = __expf(sacc[nt][1] - m0);
            float p10 = __expf(sacc[nt][2] - m1), p11 = __expf(sacc[nt][3] - m1);
            ps0 += p00 + p01; ps1 += p10 + p11;
            float2 a = { tf32r(p00), tf32r(p01) };
            float2 c = { tf32r(p10), tf32r(p11) };
            *(float2*)(pr0 + nt * 8) = a;
            *(float2*)(pr1 + nt * 8) = c;
        }
        ps0 += __shfl_xor_sync(0xffffffffu, ps0, 1);
        ps0 += __shfl_xor_sync(0xffffffffu, ps0, 2);
        ps1 += __shfl_xor_sync(0xffffffffu, ps1, 1);
        ps1 += __shfl_xor_sync(0xffffffffu, ps1, 2);
        l0 = l0 * sf0 + ps0;
        l1 = l1 * sf1 + ps1;

        #pragma unroll
        for (int nd = 0; nd < 16; nd++) {
            oacc[nd][0] *= sf0; oacc[nd][1] *= sf0;
            oacc[nd][2] *= sf1; oacc[nd][3] *= sf1;
        }
        __syncwarp();

        // O += P V
        #pragma unroll
        for (int ks = 0; ks < 8; ks++) {
            const float* pa = Ps + (w * 16 + lr) * PTS2 + (ks << 3) + lc;
            uint32_t af[4] = { __float_as_uint(pa[0]), __float_as_uint(pa[8 * PTS2]),
                               __float_as_uint(pa[4]), __float_as_uint(pa[8 * PTS2 + 4]) };
            #pragma unroll
            for (int nd = 0; nd < 16; nd++) {
                const float* pb = Vs + ((ks << 3) + lc) * VTS2 + (nd << 3) + lr;
                uint32_t bf[2] = { __float_as_uint(pb[0]), __float_as_uint(pb[4 * VTS2]) };
                mma_tf32(oacc[nd], af, bf);
            }
        }
        __syncthreads();
    }

    // epilogue
    float i0 = 1.f / l0, i1 = 1.f / l1;
    float* o0 = g_ao + ((size_t)b * S_ + r0g) * 2048 + h * 128 + 2 * lc;
    float* o1 = g_ao + ((size_t)b * S_ + r1g) * 2048 + h * 128 + 2 * lc;
    #pragma unroll
    for (int nd = 0; nd < 16; nd++) {
        float2 a = { oacc[nd][0] * i0, oacc[nd][1] * i0 };
        float2 c = { oacc[nd][2] * i1, oacc[nd][3] * i1 };
        *(float2*)(o0 + nd * 8) = a;
        *(float2*)(o1 + nd * 8) = c;
    }
}

// ---------------------------------------------------------------------------
extern "C" void kernel_launch(void* const* d_in, const int* in_sizes, int n_in,
                              void* d_out, int out_size)
{
    const float* hs   = (const float*)d_in[0];
    const float* WAq  = (const float*)d_in[1];
    const float* WAk  = (const float*)d_in[2];
    const float* WAv  = (const float*)d_in[3];
    const float* Bq   = (const float*)d_in[4];
    const float* Bk   = (const float*)d_in[5];
    const float* Bv   = (const float*)d_in[6];
    const float* Wo   = (const float*)d_in[7];
    const float* fcos = (const float*)d_in[8];
    const float* fsin = (const float*)d_in[9];
    const int*   widx = (const int*)d_in[11];
    float* out = (float*)d_out;

    float *pA, *pk, *pv, *pao;
    cudaGetSymbolAddress((void**)&pA,  g_A);
    cudaGetSymbolAddress((void**)&pk,  g_k);
    cudaGetSymbolAddress((void**)&pv,  g_v);
    cudaGetSymbolAddress((void**)&pao, g_ao);

    cudaFuncSetAttribute(proj_tc,  cudaFuncAttributeMaxDynamicSharedMemorySize, GT_SMEM);
    cudaFuncSetAttribute(oproj_tc, cudaFuncAttributeMaxDynamicSharedMemorySize, GT_SMEM);
    cudaFuncSetAttribute(qkv_tc,   cudaFuncAttributeMaxDynamicSharedMemorySize, QKV_SMEM);
    cudaFuncSetAttribute(flash_tc2,cudaFuncAttributeMaxDynamicSharedMemorySize, FL2_SMEM);

    // 0) zero KV caches (scatter semantics)
    zero2_kernel<<<(B_*HKV_*S_*D_) / (4 * 256), 256>>>(pk, pv);

    // 1) low-rank projections (merged, alpha folds the /64)
    proj_tc<<<dim3(16, 32), 256, GT_SMEM>>>(hs, WAq, WAk, WAv, pA);

    // 2) q/k/v build on tensor cores (+RoPE, scatter)
    qkv_tc<<<dim3(32, 32), 256, QKV_SMEM>>>(pA, Bq, Bk, Bv, fcos, fsin, widx);

    // 3) causal flash attention (tf32 tensor cores, 128-row tiles)
    flash_tc2<<<dim3(S_ / 128, B_ * H_), 256, FL2_SMEM>>>();

    // 4) output projection
    oproj_tc<<<dim3(16, 32), 256, GT_SMEM>>>(pao, Wo, out);
}

// round 7
// speedup vs baseline: 4.0249x; 1.3741x over previous
#include <cuda_runtime.h>
#include <cuda_fp16.h>
#include <cstdint>

#define B_   2
#define S_   2048
#define H_   16
#define HKV_ 8
#define D_   128
#define NROW (B_*S_)

// Scratch (device globals)
__device__ __align__(16) __half g_A [(size_t)NROW*2048];
__device__ __align__(16) __half g_q [(size_t)B_*H_  *S_*D_];   // pre-scaled by 1/sqrt(D)
__device__ __align__(16) __half g_k [(size_t)B_*HKV_*S_*D_];
__device__ __align__(16) __half g_v [(size_t)B_*HKV_*S_*D_];
__device__ __align__(16) float  g_ao[(size_t)NROW*2048];

__device__ __forceinline__ uint32_t h2rn(float a, float b) {
    __half2 h = __floats2half2_rn(a, b);
    return *reinterpret_cast<uint32_t*>(&h);
}
__device__ __forceinline__ void mma_f16(float* c, const uint32_t* a, const uint32_t* b) {
    asm volatile(
        "mma.sync.aligned.m16n8k16.row.col.f32.f16.f16.f32 "
        "{%0,%1,%2,%3}, {%4,%5,%6,%7}, {%8,%9}, {%0,%1,%2,%3};"
        : "+f"(c[0]), "+f"(c[1]), "+f"(c[2]), "+f"(c[3])
        : "r"(a[0]), "r"(a[1]), "r"(a[2]), "r"(a[3]), "r"(b[0]), "r"(b[1]));
}

// ---------------------------------------------------------------------------
// fp16 GEMM body: acc += A*B^T; A,B fp32 gmem, staged to fp16 smem.
// 128x128 tile, K-chunks of 32, double buffered, 256 thr.
// ---------------------------------------------------------------------------
#define GTS 40                     // half stride
#define GTILE (128*GTS)
#define GT_SMEM (2*2*GTILE*2)      // 40960 B

__device__ __forceinline__ void gemm_acc_h(
    __half* sm, const float* __restrict__ A, const float* __restrict__ B,
    int K, float acc[4][4][4])
{
    const int tid = threadIdx.x, wid = tid >> 5, lane = tid & 31;
    const int wm = wid >> 2, wn = wid & 3, lr = lane >> 2, lc = lane & 3;

    int ldrow[4], ldc4[4];
    #pragma unroll
    for (int i = 0; i < 4; i++) {
        int idx = tid * 4 + i;
        ldrow[i] = idx >> 3;  ldc4[i] = idx & 7;
    }
    const int nch = K >> 5;

    #pragma unroll
    for (int i = 0; i < 4; i++) {
        float4 va = *(const float4*)(A + (size_t)ldrow[i] * K + (ldc4[i] << 2));
        float4 vb = *(const float4*)(B + (size_t)ldrow[i] * K + (ldc4[i] << 2));
        uint2 pa = { h2rn(va.x, va.y), h2rn(va.z, va.w) };
        uint2 pb = { h2rn(vb.x, vb.y), h2rn(vb.z, vb.w) };
        *(uint2*)(sm + ldrow[i] * GTS + (ldc4[i] << 2)) = pa;
        *(uint2*)(sm + GTILE + ldrow[i] * GTS + (ldc4[i] << 2)) = pb;
    }
    __syncthreads();

    for (int c = 0; c < nch; c++) {
        const __half* As = sm + (c & 1) * 2 * GTILE;
        const __half* Bs = As + GTILE;

        float4 na[4], nb[4];
        if (c + 1 < nch) {
            const int k0 = (c + 1) << 5;
            #pragma unroll
            for (int i = 0; i < 4; i++) {
                na[i] = *(const float4*)(A + (size_t)ldrow[i] * K + k0 + (ldc4[i] << 2));
                nb[i] = *(const float4*)(B + (size_t)ldrow[i] * K + k0 + (ldc4[i] << 2));
            }
        }

        #pragma unroll
        for (int ks = 0; ks < 2; ks++) {
            uint32_t af[4][4], bf[4][2];
            #pragma unroll
            for (int mi = 0; mi < 4; mi++) {
                const __half* p = As + (wm * 64 + mi * 16 + lr) * GTS + ks * 16 + 2 * lc;
                af[mi][0] = *(const uint32_t*)(p);
                af[mi][1] = *(const uint32_t*)(p + 8 * GTS);
                af[mi][2] = *(const uint32_t*)(p + 8);
                af[mi][3] = *(const uint32_t*)(p + 8 * GTS + 8);
            }
            #pragma unroll
            for (int ni = 0; ni < 4; ni++) {
                const __half* p = Bs + (wn * 32 + ni * 8 + lr) * GTS + ks * 16 + 2 * lc;
                bf[ni][0] = *(const uint32_t*)(p);
                bf[ni][1] = *(const uint32_t*)(p + 8);
            }
            #pragma unroll
            for (int mi = 0; mi < 4; mi++)
                #pragma unroll
                for (int ni = 0; ni < 4; ni++)
                    mma_f16(acc[mi][ni], af[mi], bf[ni]);
        }

        if (c + 1 < nch) {
            __half* dst = sm + ((c + 1) & 1) * 2 * GTILE;
            #pragma unroll
            for (int i = 0; i < 4; i++) {
                uint2 pa = { h2rn(na[i].x, na[i].y), h2rn(na[i].z, na[i].w) };
                uint2 pb = { h2rn(nb[i].x, nb[i].y), h2rn(nb[i].z, nb[i].w) };
                *(uint2*)(dst + ldrow[i] * GTS + (ldc4[i] << 2)) = pa;
                *(uint2*)(dst + GTILE + ldrow[i] * GTS + (ldc4[i] << 2)) = pb;
            }
        }
        __syncthreads();
    }
}

// merged 3-way projection -> g_A (fp16, /64 folded)
__global__ void __launch_bounds__(256, 1) proj_h(
    const float* __restrict__ hs, const float* __restrict__ WAq,
    const float* __restrict__ WAk, const float* __restrict__ WAv)
{
    extern __shared__ __half smh[];
    const int x = blockIdx.x;
    const float* Bsel; int coff;
    if (x < 8)       { Bsel = WAq + (size_t)x * 128 * 2048;        coff = x * 128; }
    else if (x < 12) { Bsel = WAk + (size_t)(x - 8) * 128 * 2048;  coff = 1024 + (x - 8) * 128; }
    else             { Bsel = WAv + (size_t)(x - 12) * 128 * 2048; coff = 1536 + (x - 12) * 128; }
    const size_t m0 = (size_t)blockIdx.y << 7;

    float acc[4][4][4];
    #pragma unroll
    for (int i = 0; i < 4; i++)
        #pragma unroll
        for (int j = 0; j < 4; j++)
            #pragma unroll
            for (int r = 0; r < 4; r++) acc[i][j][r] = 0.f;

    gemm_acc_h(smh, hs + m0 * 2048, Bsel, 2048, acc);

    const int tid = threadIdx.x, wid = tid >> 5, lane = tid & 31;
    const int wm = wid >> 2, wn = wid & 3, lr = lane >> 2, lc = lane & 3;
    const float al = 1.0f / 64.0f;
    __half* C = g_A + m0 * 2048 + coff;
    #pragma unroll
    for (int mi = 0; mi < 4; mi++) {
        const int row = wm * 64 + mi * 16 + lr;
        #pragma unroll
        for (int ni = 0; ni < 4; ni++) {
            const int col = wn * 32 + ni * 8 + lc * 2;
            *(uint32_t*)(C + (size_t)row * 2048 + col) = h2rn(acc[mi][ni][0]*al, acc[mi][ni][1]*al);
            *(uint32_t*)(C + (size_t)(row+8) * 2048 + col) = h2rn(acc[mi][ni][2]*al, acc[mi][ni][3]*al);
        }
    }
}

// output projection: g_ao x Wo -> out (fp32)
__global__ void __launch_bounds__(256, 1) oproj_h(
    const float* __restrict__ Wo, float* __restrict__ out)
{
    extern __shared__ __half smh[];
    const size_t m0 = (size_t)blockIdx.y << 7;
    const size_t n0 = (size_t)blockIdx.x << 7;

    float acc[4][4][4];
    #pragma unroll
    for (int i = 0; i < 4; i++)
        #pragma unroll
        for (int j = 0; j < 4; j++)
            #pragma unroll
            for (int r = 0; r < 4; r++) acc[i][j][r] = 0.f;

    gemm_acc_h(smh, g_ao + m0 * 2048, Wo + n0 * 2048, 2048, acc);

    const int tid = threadIdx.x, wid = tid >> 5, lane = tid & 31;
    const int wm = wid >> 2, wn = wid & 3, lr = lane >> 2, lc = lane & 3;
    float* C = out + m0 * 2048 + n0;
    #pragma unroll
    for (int mi = 0; mi < 4; mi++) {
        const int row = wm * 64 + mi * 16 + lr;
        #pragma unroll
        for (int ni = 0; ni < 4; ni++) {
            const int col = wn * 32 + ni * 8 + lc * 2;
            float2 v0 = { acc[mi][ni][0], acc[mi][ni][1] };
            float2 v1 = { acc[mi][ni][2], acc[mi][ni][3] };
            *(float2*)(C + (size_t)row * 2048 + col)     = v0;
            *(float2*)(C + (size_t)(row+8) * 2048 + col) = v1;
        }
    }
}

// ---------------------------------------------------------------------------
// q/k/v build (fp16 mma, K=64) + RoPE + scatter. grid (32, 32).
// A: g_A fp16 [128][64]. B: fp32 [64 r][128 d] packed as r-pairs Bp[r/2][d].
// ---------------------------------------------------------------------------
#define QATS 72
#define BPS  136
#define QKV_SMEM (128*QATS*2 + 32*BPS*4)   // 18432 + 17408 = 35840 B
#define SC_ 0.088388347648318447f

__global__ void __launch_bounds__(256, 1) qkv_h(
    const float* __restrict__ Bq, const float* __restrict__ Bk, const float* __restrict__ Bv,
    const float* __restrict__ fcos, const float* __restrict__ fsin,
    const int* __restrict__ widx)
{
    extern __shared__ __align__(16) char smraw[];
    __half*   As = (__half*)smraw;                     // [128][QATS]
    uint32_t* Bp = (uint32_t*)(smraw + 128*QATS*2);    // [32][BPS] half2 pairs

    const int tid = threadIdx.x, w = tid >> 5, lane = tid & 31;
    const int lr = lane >> 2, lc = lane & 3;
    const int m0 = blockIdx.x << 7;
    const int hh = blockIdx.y;

    const float* Bmat; int aoff;
    if (hh < 16)      { Bmat = Bq + (size_t)hh * 8192;        aoff = hh * 64; }
    else if (hh < 24) { Bmat = Bk + (size_t)(hh - 16) * 8192; aoff = 1024 + (hh - 16) * 64; }
    else              { Bmat = Bv + (size_t)(hh - 24) * 8192; aoff = 1536 + (hh - 24) * 64; }

    // stage A: 128 rows x 64 halves = 1024 uint4 tasks / 4 per thread
    #pragma unroll
    for (int i = 0; i < 4; i++) {
        int idx = tid + (i << 8);
        int r = idx >> 3, g = idx & 7;
        *(uint4*)(As + r * QATS + g * 8) =
            *(const uint4*)(g_A + (size_t)(m0 + r) * 2048 + aoff + g * 8);
    }
    // stage Bp: pack rows (2r2, 2r2+1): 32 x 32 tasks / 4 per thread
    #pragma unroll
    for (int i = 0; i < 4; i++) {
        int idx = tid + (i << 8);
        int r2 = idx >> 5, cg = idx & 31;
        float4 a = *(const float4*)(Bmat + (size_t)(2*r2) * 128 + cg * 4);
        float4 b = *(const float4*)(Bmat + (size_t)(2*r2+1) * 128 + cg * 4);
        uint4 o = { h2rn(a.x,b.x), h2rn(a.y,b.y), h2rn(a.z,b.z), h2rn(a.w,b.w) };
        *(uint4*)(Bp + r2 * BPS + cg * 4) = o;
    }
    __syncthreads();

    float acc[16][4];
    #pragma unroll
    for (int i = 0; i < 16; i++)
        #pragma unroll
        for (int j = 0; j < 4; j++) acc[i][j] = 0.f;

    #pragma unroll
    for (int s = 0; s < 4; s++) {     // K = 64 = 4 x k16
        const __half* pa = As + (w * 16 + lr) * QATS + s * 16 + 2 * lc;
        uint32_t af[4] = { *(const uint32_t*)(pa), *(const uint32_t*)(pa + 8*QATS),
                           *(const uint32_t*)(pa + 8), *(const uint32_t*)(pa + 8*QATS + 8) };
        #pragma unroll
        for (int nd = 0; nd < 16; nd++) {
            const uint32_t* pb = Bp + (s * 8 + lc) * BPS + nd * 8 + lr;
            uint32_t bf[2] = { pb[0], pb[4 * BPS] };
            mma_f16(acc[nd], af, bf);
        }
    }

    const int r0 = m0 + w * 16 + lr, r1 = r0 + 8;
    const int b  = r0 >> 11;
    const int s0 = r0 & 2047, s1 = s0 + 8;

    if (hh < 16) {   // q: scale + RoPE
        #pragma unroll
        for (int i = 0; i < 16; i++)
            #pragma unroll
            for (int j = 0; j < 4; j++) acc[i][j] *= SC_;
        __half* o0 = g_q + ((size_t)(b * H_ + hh) * S_ + s0) * D_;
        __half* o1 = g_q + ((size_t)(b * H_ + hh) * S_ + s1) * D_;
        #pragma unroll
        for (int nd = 0; nd < 8; nd++) {
            const int d0 = (nd << 3) + 2 * lc;
            float2 c0 = *(const float2*)(fcos + (size_t)s0*64 + d0);
            float2 z0 = *(const float2*)(fsin + (size_t)s0*64 + d0);
            float2 c1 = *(const float2*)(fcos + (size_t)s1*64 + d0);
            float2 z1 = *(const float2*)(fsin + (size_t)s1*64 + d0);
            *(uint32_t*)(o0+d0)    = h2rn(acc[nd][0]*c0.x - acc[nd+8][0]*z0.x,
                                          acc[nd][1]*c0.y - acc[nd+8][1]*z0.y);
            *(uint32_t*)(o0+d0+64) = h2rn(acc[nd][0]*z0.x + acc[nd+8][0]*c0.x,
                                          acc[nd][1]*z0.y + acc[nd+8][1]*c0.y);
            *(uint32_t*)(o1+d0)    = h2rn(acc[nd][2]*c1.x - acc[nd+8][2]*z1.x,
                                          acc[nd][3]*c1.y - acc[nd+8][3]*z1.y);
            *(uint32_t*)(o1+d0+64) = h2rn(acc[nd][2]*z1.x + acc[nd+8][2]*c1.x,
                                          acc[nd][3]*z1.y + acc[nd+8][3]*c1.y);
        }
    } else if (hh < 24) {   // k: RoPE + scatter
        int p0 = widx[s0], p1 = widx[s1];
        __half* o0 = g_k + ((size_t)(b * HKV_ + hh-16) * S_ + p0) * D_;
        __half* o1 = g_k + ((size_t)(b * HKV_ + hh-16) * S_ + p1) * D_;
        #pragma unroll
        for (int nd = 0; nd < 8; nd++) {
            const int d0 = (nd << 3) + 2 * lc;
            float2 c0 = *(const float2*)(fcos + (size_t)p0*64 + d0);
            float2 z0 = *(const float2*)(fsin + (size_t)p0*64 + d0);
            float2 c1 = *(const float2*)(fcos + (size_t)p1*64 + d0);
            float2 z1 = *(const float2*)(fsin + (size_t)p1*64 + d0);
            *(uint32_t*)(o0+d0)    = h2rn(acc[nd][0]*c0.x - acc[nd+8][0]*z0.x,
                                          acc[nd][1]*c0.y - acc[nd+8][1]*z0.y);
            *(uint32_t*)(o0+d0+64) = h2rn(acc[nd][0]*z0.x + acc[nd+8][0]*c0.x,
                                          acc[nd][1]*z0.y + acc[nd+8][1]*c0.y);
            *(uint32_t*)(o1+d0)    = h2rn(acc[nd][2]*c1.x - acc[nd+8][2]*z1.x,
                                          acc[nd][3]*c1.y - acc[nd+8][3]*z1.y);
            *(uint32_t*)(o1+d0+64) = h2rn(acc[nd][2]*z1.x + acc[nd+8][2]*c1.x,
                                          acc[nd][3]*z1.y + acc[nd+8][3]*c1.y);
        }
    } else {   // v: direct scatter
        int p0 = widx[s0], p1 = widx[s1];
        __half* o0 = g_v + ((size_t)(b * HKV_ + hh-24) * S_ + p0) * D_;
        __half* o1 = g_v + ((size_t)(b * HKV_ + hh-24) * S_ + p1) * D_;
        #pragma unroll
        for (int nd = 0; nd < 16; nd++) {
            const int d0 = (nd << 3) + 2 * lc;
            *(uint32_t*)(o0 + d0) = h2rn(acc[nd][0], acc[nd][1]);
            *(uint32_t*)(o1 + d0) = h2rn(acc[nd][2], acc[nd][3]);
        }
    }
}

// ---------------------------------------------------------------------------
// Flash attention, fp16 mma. 128 q-rows per CTA, 8 warps, k-tiles of 64.
// Ks: [64][KTS] halves; Vp: [32][VPS] half2 (k,k+1) pairs; P direct from regs.
// ---------------------------------------------------------------------------
#define KTS 136
#define VPS 136
#define FL_SMEM (64*KTS*2 + 32*VPS*4)   // 17408 + 17408 = 34816 B

__global__ void __launch_bounds__(256, 1) flash_h()
{
    extern __shared__ __align__(16) char smraw[];
    __half*   Ks  = (__half*)smraw;
    uint32_t* Vp  = (uint32_t*)(smraw + 64*KTS*2);
    __half*   Qst = (__half*)smraw;     // overlay (128*KTS halves = whole smem)

    const int tid = threadIdx.x, w = tid >> 5, lane = tid & 31;
    const int lr = lane >> 2, lc = lane & 3;
    const int qt = (int)gridDim.x - 1 - (int)blockIdx.x;
    const int bh = blockIdx.y;
    const int b = bh >> 4, h = bh & 15, kvh = h >> 1;
    const int qp = qt << 7;

    const __half* qbase = g_q + ((size_t)(b * H_ + h) * S_ + qp) * D_;
    const __half* kbase = g_k + (size_t)(b * HKV_ + kvh) * S_ * D_;
    const __half* vbase = g_v + (size_t)(b * HKV_ + kvh) * S_ * D_;

    // stage Q (already scaled), pull frags
    #pragma unroll
    for (int i = 0; i < 8; i++) {
        int idx = tid + (i << 8);
        int r = idx >> 4, g = idx & 15;
        *(uint4*)(Qst + r * KTS + g * 8) = *(const uint4*)(qbase + (size_t)r * 128 + g * 8);
    }
    __syncthreads();

    uint32_t qf[8][4];
    #pragma unroll
    for (int k8 = 0; k8 < 8; k8++) {
        const __half* p = Qst + (w * 16 + lr) * KTS + (k8 << 4) + 2 * lc;
        qf[k8][0] = *(const uint32_t*)(p);
        qf[k8][1] = *(const uint32_t*)(p + 8 * KTS);
        qf[k8][2] = *(const uint32_t*)(p + 8);
        qf[k8][3] = *(const uint32_t*)(p + 8 * KTS + 8);
    }
    __syncthreads();

    float oacc[16][4];
    #pragma unroll
    for (int i = 0; i < 16; i++)
        #pragma unroll
        for (int j = 0; j < 4; j++) oacc[i][j] = 0.f;
    float m0 = -1e30f, m1 = -1e30f, l0 = 0.f, l1 = 0.f;
    const int r0g = qp + w * 16 + lr, r1g = r0g + 8;

    const int ktmax = 2 * qt + 1;
    for (int kt = 0; kt <= ktmax; kt++) {
        const __half* kp = kbase + (size_t)kt * 64 * 128;
        const __half* vp = vbase + (size_t)kt * 64 * 128;
        // K: 64 x 128 halves = 1024 uint4 / 4 per thread
        #pragma unroll
        for (int i = 0; i < 4; i++) {
            int idx = tid + (i << 8);
            int r = idx >> 4, g = idx & 15;
            *(uint4*)(Ks + r * KTS + g * 8) = *(const uint4*)(kp + (size_t)r * 128 + g * 8);
        }
        // Vp: pack rows (2r2, 2r2+1): 32 x 32 tasks / 4 per thread
        #pragma unroll
        for (int i = 0; i < 4; i++) {
            int idx = tid + (i << 8);
            int r2 = idx >> 5, cg = idx & 31;
            uint2 a = *(const uint2*)(vp + (size_t)(2*r2) * 128 + cg * 4);
            uint2 c = *(const uint2*)(vp + (size_t)(2*r2+1) * 128 + cg * 4);
            const __half* ah = (const __half*)&a;
            const __half* ch = (const __half*)&c;
            uint4 o;
            __half2 t0 = __halves2half2(ah[0], ch[0]); o.x = *(uint32_t*)&t0;
            __half2 t1 = __halves2half2(ah[1], ch[1]); o.y = *(uint32_t*)&t1;
            __half2 t2 = __halves2half2(ah[2], ch[2]); o.z = *(uint32_t*)&t2;
            __half2 t3 = __halves2half2(ah[3], ch[3]); o.w = *(uint32_t*)&t3;
            *(uint4*)(Vp + r2 * VPS + cg * 4) = o;
        }
        __syncthreads();

        // S = Q K^T
        float sacc[8][4];
        #pragma unroll
        for (int i = 0; i < 8; i++)
            #pragma unroll
            for (int j = 0; j < 4; j++) sacc[i][j] = 0.f;
        #pragma unroll
        for (int k8 = 0; k8 < 8; k8++) {
            #pragma unroll
            for (int nt = 0; nt < 8; nt++) {
                const __half* p = Ks + (nt * 8 + lr) * KTS + (k8 << 4) + 2 * lc;
                uint32_t bf[2] = { *(const uint32_t*)(p), *(const uint32_t*)(p + 8) };
                mma_f16(sacc[nt], qf[k8], bf);
            }
        }

        if (kt >= 2 * qt) {
            const int cb = kt * 64;
            #pragma unroll
            for (int nt = 0; nt < 8; nt++) {
                int c0 = cb + nt * 8 + 2 * lc;
                if (c0     > r0g) sacc[nt][0] = -1e30f;
                if (c0 + 1 > r0g) sacc[nt][1] = -1e30f;
                if (c0     > r1g) sacc[nt][2] = -1e30f;
                if (c0 + 1 > r1g) sacc[nt][3] = -1e30f;
            }
        }

        // online softmax (P stays in sacc registers)
        float mi0 = -1e30f, mi1 = -1e30f;
        #pragma unroll
        for (int nt = 0; nt < 8; nt++) {
            mi0 = fmaxf(mi0, fmaxf(sacc[nt][0], sacc[nt][1]));
            mi1 = fmaxf(mi1, fmaxf(sacc[nt][2], sacc[nt][3]));
        }
        mi0 = fmaxf(mi0, __shfl_xor_sync(0xffffffffu, mi0, 1));
        mi0 = fmaxf(mi0, __shfl_xor_sync(0xffffffffu, mi0, 2));
        mi1 = fmaxf(mi1, __shfl_xor_sync(0xffffffffu, mi1, 1));
        mi1 = fmaxf(mi1, __shfl_xor_sync(0xffffffffu, mi1, 2));
        float mn0 = fmaxf(m0, mi0), mn1 = fmaxf(m1, mi1);
        float sf0 = __expf(m0 - mn0), sf1 = __expf(m1 - mn1);
        m0 = mn0; m1 = mn1;

        float ps0 = 0.f, ps1 = 0.f;
        #pragma unroll
        for (int nt = 0; nt < 8; nt++) {
            sacc[nt][0] = __expf(sacc[nt][0] - m0);
            sacc[nt][1] = __expf(sacc[nt][1] - m0);
            sacc[nt][2] = __expf(sacc[nt][2] - m1);
            sacc[nt][3] = __expf(sacc[nt][3] - m1);
            ps0 += sacc[nt][0] + sacc[nt][1];
            ps1 += sacc[nt][2] + sacc[nt][3];
        }
        ps0 += __shfl_xor_sync(0xffffffffu, ps0, 1);
        ps0 += __shfl_xor_sync(0xffffffffu, ps0, 2);
        ps1 += __shfl_xor_sync(0xffffffffu, ps1, 1);
        ps1 += __shfl_xor_sync(0xffffffffu, ps1, 2);
        l0 = l0 * sf0 + ps0;
        l1 = l1 * sf1 + ps1;

        #pragma unroll
        for (int nd = 0; nd < 16; nd++) {
            oacc[nd][0] *= sf0; oacc[nd][1] *= sf0;
            oacc[nd][2] *= sf1; oacc[nd][3] *= sf1;
        }

        // O += P V  (A-frags packed straight from sacc registers)
        #pragma unroll
        for (int ks = 0; ks < 4; ks++) {
            uint32_t af[4] = { h2rn(sacc[2*ks][0],   sacc[2*ks][1]),
                               h2rn(sacc[2*ks][2],   sacc[2*ks][3]),
                               h2rn(sacc[2*ks+1][0], sacc[2*ks+1][1]),
                               h2rn(sacc[2*ks+1][2], sacc[2*ks+1][3]) };
            #pragma unroll
            for (int nd = 0; nd < 16; nd++) {
                const uint32_t* pb = Vp + (ks * 8 + lc) * VPS + nd * 8 + lr;
                uint32_t bf[2] = { pb[0], pb[4 * VPS] };
                mma_f16(oacc[nd], af, bf);
            }
        }
        __syncthreads();
    }

    float i0 = 1.f / l0, i1 = 1.f / l1;
    float* o0 = g_ao + ((size_t)b * S_ + r0g) * 2048 + h * 128 + 2 * lc;
    float* o1 = g_ao + ((size_t)b * S_ + r1g) * 2048 + h * 128 + 2 * lc;
    #pragma unroll
    for (int nd = 0; nd < 16; nd++) {
        float2 a = { oacc[nd][0] * i0, oacc[nd][1] * i0 };
        float2 c = { oacc[nd][2] * i1, oacc[nd][3] * i1 };
        *(float2*)(o0 + nd * 8) = a;
        *(float2*)(o1 + nd * 8) = c;
    }
}

// ---------------------------------------------------------------------------
extern "C" void kernel_launch(void* const* d_in, const int* in_sizes, int n_in,
                              void* d_out, int out_size)
{
    const float* hs   = (const float*)d_in[0];
    const float* WAq  = (const float*)d_in[1];
    const float* WAk  = (const float*)d_in[2];
    const float* WAv  = (const float*)d_in[3];
    const float* Bq   = (const float*)d_in[4];
    const float* Bk   = (const float*)d_in[5];
    const float* Bv   = (const float*)d_in[6];
    const float* Wo   = (const float*)d_in[7];
    const float* fcos = (const float*)d_in[8];
    const float* fsin = (const float*)d_in[9];
    const int*   widx = (const int*)d_in[11];
    float* out = (float*)d_out;

    cudaFuncSetAttribute(proj_h,  cudaFuncAttributeMaxDynamicSharedMemorySize, GT_SMEM);
    cudaFuncSetAttribute(oproj_h, cudaFuncAttributeMaxDynamicSharedMemorySize, GT_SMEM);
    cudaFuncSetAttribute(qkv_h,   cudaFuncAttributeMaxDynamicSharedMemorySize, QKV_SMEM);
    cudaFuncSetAttribute(flash_h, cudaFuncAttributeMaxDynamicSharedMemorySize, FL_SMEM);

    proj_h <<<dim3(16, 32), 256, GT_SMEM>>>(hs, WAq, WAk, WAv);
    qkv_h  <<<dim3(32, 32), 256, QKV_SMEM>>>(Bq, Bk, Bv, fcos, fsin, widx);
    flash_h<<<dim3(S_ / 128, B_ * H_), 256, FL_SMEM>>>();
    oproj_h<<<dim3(16, 32), 256, GT_SMEM>>>(Wo, out);
}

// round 8
// speedup vs baseline: 6.2408x; 1.5506x over previous
#include <cuda_runtime.h>
#include <cuda_fp16.h>
#include <cstdint>

#define B_   2
#define S_   2048
#define H_   16
#define HKV_ 8
#define D_   128
#define NROW (B_*S_)

// Scratch (device globals)
__device__ __align__(16) __half g_hs16[(size_t)NROW*2048];
__device__ __align__(16) __half g_w16 [(size_t)2048*2048];     // [WAq rows | WAk | WAv]
__device__ __align__(16) __half g_wo16[(size_t)2048*2048];
__device__ __align__(16) __half g_A   [(size_t)NROW*2048];
__device__ __align__(16) __half g_q   [(size_t)B_*H_  *S_*D_]; // pre-scaled by 1/sqrt(D)
__device__ __align__(16) __half g_k   [(size_t)B_*HKV_*S_*D_];
__device__ __align__(16) __half g_v   [(size_t)B_*HKV_*S_*D_];
__device__ __align__(16) __half g_ao16[(size_t)NROW*2048];

__device__ __forceinline__ uint32_t h2rn(float a, float b) {
    __half2 h = __floats2half2_rn(a, b);
    return *reinterpret_cast<uint32_t*>(&h);
}
__device__ __forceinline__ void mma_f16(float* c, const uint32_t* a, const uint32_t* b) {
    asm volatile(
        "mma.sync.aligned.m16n8k16.row.col.f32.f16.f16.f32 "
        "{%0,%1,%2,%3}, {%4,%5,%6,%7}, {%8,%9}, {%0,%1,%2,%3};"
        : "+f"(c[0]), "+f"(c[1]), "+f"(c[2]), "+f"(c[3])
        : "r"(a[0]), "r"(a[1]), "r"(a[2]), "r"(a[3]), "r"(b[0]), "r"(b[1]));
}
__device__ __forceinline__ uint32_t smem_u32(const void* p) {
    uint32_t a;
    asm("{ .reg .u64 t; cvta.to.shared.u64 t, %1; cvt.u32.u64 %0, t; }" : "=r"(a) : "l"(p));
    return a;
}
__device__ __forceinline__ void cp16(uint32_t d, const void* s) {
    asm volatile("cp.async.cg.shared.global [%0], [%1], 16;" :: "r"(d), "l"(s));
}
#define CP_COMMIT() asm volatile("cp.async.commit_group;")

// ---------------------------------------------------------------------------
// fp32 -> fp16 conversion (8 elems/thread)
// ---------------------------------------------------------------------------
__global__ void __launch_bounds__(256) cvt16(const float* __restrict__ s, __half* __restrict__ d)
{
    size_t i = ((size_t)blockIdx.x * 256 + threadIdx.x) * 8;
    float4 a = *(const float4*)(s + i);
    float4 b = *(const float4*)(s + i + 4);
    uint4 o = { h2rn(a.x,a.y), h2rn(a.z,a.w), h2rn(b.x,b.y), h2rn(b.z,b.w) };
    *(uint4*)(d + i) = o;
}

// ---------------------------------------------------------------------------
// Pure-fp16 GEMM body, cp.async 4-stage pipeline. K=2048, chunks of 32.
// A,B fp16 row-major ld=2048. acc += A*B^T over 128x128 tile.
// ---------------------------------------------------------------------------
#define GTS 40
#define GSTG (128*GTS)                 // 5120 halves / matrix / stage
#define NST 4
#define G16_SMEM (NST*2*GSTG*2)        // 81920 B

__device__ __forceinline__ void g16_issue(uint32_t sb, int stg,
    const __half* __restrict__ A, const __half* __restrict__ B, int tid)
{
    uint32_t ab = sb + stg * 2 * GSTG * 2;
    uint32_t bb = ab + GSTG * 2;
    #pragma unroll
    for (int i = 0; i < 2; i++) {
        int t = tid * 2 + i;             // 0..511
        int row = t >> 2, seg = t & 3;
        cp16(ab + row * 80 + seg * 16, A + (size_t)row * 2048 + seg * 8);
        cp16(bb + row * 80 + seg * 16, B + (size_t)row * 2048 + seg * 8);
    }
}

__device__ __forceinline__ void gemm16_acc(
    __half* sm, uint32_t sb, const __half* __restrict__ A,
    const __half* __restrict__ B, float acc[4][4][4])
{
    const int tid = threadIdx.x, wid = tid >> 5, lane = tid & 31;
    const int wm = wid >> 2, wn = wid & 3, lr = lane >> 2, lc = lane & 3;

    #pragma unroll
    for (int s = 0; s < NST - 1; s++) {
        g16_issue(sb, s, A + s * 32, B + s * 32, tid);
        CP_COMMIT();
    }

    for (int c = 0; c < 64; c++) {
        asm volatile("cp.async.wait_group 2;");
        __syncthreads();
        if (c + NST - 1 < 64)
            g16_issue(sb, (c + NST - 1) & 3, A + (c + NST - 1) * 32, B + (c + NST - 1) * 32, tid);
        CP_COMMIT();

        const __half* As = sm + (c & 3) * 2 * GSTG;
        const __half* Bs = As + GSTG;
        #pragma unroll
        for (int ks = 0; ks < 2; ks++) {
            uint32_t af[4][4], bf[4][2];
            #pragma unroll
            for (int mi = 0; mi < 4; mi++) {
                const __half* p = As + (wm * 64 + mi * 16 + lr) * GTS + ks * 16 + 2 * lc;
                af[mi][0] = *(const uint32_t*)(p);
                af[mi][1] = *(const uint32_t*)(p + 8 * GTS);
                af[mi][2] = *(const uint32_t*)(p + 8);
                af[mi][3] = *(const uint32_t*)(p + 8 * GTS + 8);
            }
            #pragma unroll
            for (int ni = 0; ni < 4; ni++) {
                const __half* p = Bs + (wn * 32 + ni * 8 + lr) * GTS + ks * 16 + 2 * lc;
                bf[ni][0] = *(const uint32_t*)(p);
                bf[ni][1] = *(const uint32_t*)(p + 8);
            }
            #pragma unroll
            for (int mi = 0; mi < 4; mi++)
                #pragma unroll
                for (int ni = 0; ni < 4; ni++)
                    mma_f16(acc[mi][ni], af[mi], bf[ni]);
        }
        __syncthreads();
    }
}

// merged 3-way projection -> g_A (fp16, /64 folded)
__global__ void __launch_bounds__(256, 2) proj_h()
{
    extern __shared__ __half smh[];
    const int x = blockIdx.x;
    const size_t m0 = (size_t)blockIdx.y << 7;

    float acc[4][4][4];
    #pragma unroll
    for (int i = 0; i < 4; i++)
        #pragma unroll
        for (int j = 0; j < 4; j++)
            #pragma unroll
            for (int r = 0; r < 4; r++) acc[i][j][r] = 0.f;

    gemm16_acc(smh, smem_u32(smh), g_hs16 + m0 * 2048, g_w16 + (size_t)x * 128 * 2048, acc);

    const int tid = threadIdx.x, wid = tid >> 5, lane = tid & 31;
    const int wm = wid >> 2, wn = wid & 3, lr = lane >> 2, lc = lane & 3;
    const float al = 1.0f / 64.0f;
    __half* C = g_A + m0 * 2048 + x * 128;
    #pragma unroll
    for (int mi = 0; mi < 4; mi++) {
        const int row = wm * 64 + mi * 16 + lr;
        #pragma unroll
        for (int ni = 0; ni < 4; ni++) {
            const int col = wn * 32 + ni * 8 + lc * 2;
            *(uint32_t*)(C + (size_t)row * 2048 + col)     = h2rn(acc[mi][ni][0]*al, acc[mi][ni][1]*al);
            *(uint32_t*)(C + (size_t)(row+8) * 2048 + col) = h2rn(acc[mi][ni][2]*al, acc[mi][ni][3]*al);
        }
    }
}

// output projection: g_ao16 x g_wo16 -> out (fp32)
__global__ void __launch_bounds__(256, 2) oproj_h(float* __restrict__ out)
{
    extern __shared__ __half smh[];
    const size_t m0 = (size_t)blockIdx.y << 7;
    const size_t n0 = (size_t)blockIdx.x << 7;

    float acc[4][4][4];
    #pragma unroll
    for (int i = 0; i < 4; i++)
        #pragma unroll
        for (int j = 0; j < 4; j++)
            #pragma unroll
            for (int r = 0; r < 4; r++) acc[i][j][r] = 0.f;

    gemm16_acc(smh, smem_u32(smh), g_ao16 + m0 * 2048, g_wo16 + n0 * 2048, acc);

    const int tid = threadIdx.x, wid = tid >> 5, lane = tid & 31;
    const int wm = wid >> 2, wn = wid & 3, lr = lane >> 2, lc = lane & 3;
    float* C = out + m0 * 2048 + n0;
    #pragma unroll
    for (int mi = 0; mi < 4; mi++) {
        const int row = wm * 64 + mi * 16 + lr;
        #pragma unroll
        for (int ni = 0; ni < 4; ni++) {
            const int col = wn * 32 + ni * 8 + lc * 2;
            float2 v0 = { acc[mi][ni][0], acc[mi][ni][1] };
            float2 v1 = { acc[mi][ni][2], acc[mi][ni][3] };
            *(float2*)(C + (size_t)row * 2048 + col)     = v0;
            *(float2*)(C + (size_t)(row+8) * 2048 + col) = v1;
        }
    }
}

// ---------------------------------------------------------------------------
// q/k/v build (fp16 mma, K=64) + RoPE + scatter. grid (32, 32).
// ---------------------------------------------------------------------------
#define QATS 72
#define BPS  136
#define QKV_SMEM (128*QATS*2 + 32*BPS*4)
#define SC_ 0.088388347648318447f

__global__ void __launch_bounds__(256, 1) qkv_h(
    const float* __restrict__ Bq, const float* __restrict__ Bk, const float* __restrict__ Bv,
    const float* __restrict__ fcos, const float* __restrict__ fsin,
    const int* __restrict__ widx)
{
    extern __shared__ __align__(16) char smraw[];
    __half*   As = (__half*)smraw;
    uint32_t* Bp = (uint32_t*)(smraw + 128*QATS*2);

    const int tid = threadIdx.x, w = tid >> 5, lane = tid & 31;
    const int lr = lane >> 2, lc = lane & 3;
    const int m0 = blockIdx.x << 7;
    const int hh = blockIdx.y;

    const float* Bmat; int aoff;
    if (hh < 16)      { Bmat = Bq + (size_t)hh * 8192;        aoff = hh * 64; }
    else if (hh < 24) { Bmat = Bk + (size_t)(hh - 16) * 8192; aoff = 1024 + (hh - 16) * 64; }
    else              { Bmat = Bv + (size_t)(hh - 24) * 8192; aoff = 1536 + (hh - 24) * 64; }

    #pragma unroll
    for (int i = 0; i < 4; i++) {
        int idx = tid + (i << 8);
        int r = idx >> 3, g = idx & 7;
        *(uint4*)(As + r * QATS + g * 8) =
            *(const uint4*)(g_A + (size_t)(m0 + r) * 2048 + aoff + g * 8);
    }
    #pragma unroll
    for (int i = 0; i < 4; i++) {
        int idx = tid + (i << 8);
        int r2 = idx >> 5, cg = idx & 31;
        float4 a = *(const float4*)(Bmat + (size_t)(2*r2) * 128 + cg * 4);
        float4 b = *(const float4*)(Bmat + (size_t)(2*r2+1) * 128 + cg * 4);
        uint4 o = { h2rn(a.x,b.x), h2rn(a.y,b.y), h2rn(a.z,b.z), h2rn(a.w,b.w) };
        *(uint4*)(Bp + r2 * BPS + cg * 4) = o;
    }
    __syncthreads();

    float acc[16][4];
    #pragma unroll
    for (int i = 0; i < 16; i++)
        #pragma unroll
        for (int j = 0; j < 4; j++) acc[i][j] = 0.f;

    #pragma unroll
    for (int s = 0; s < 4; s++) {
        const __half* pa = As + (w * 16 + lr) * QATS + s * 16 + 2 * lc;
        uint32_t af[4] = { *(const uint32_t*)(pa), *(const uint32_t*)(pa + 8*QATS),
                           *(const uint32_t*)(pa + 8), *(const uint32_t*)(pa + 8*QATS + 8) };
        #pragma unroll
        for (int nd = 0; nd < 16; nd++) {
            const uint32_t* pb = Bp + (s * 8 + lc) * BPS + nd * 8 + lr;
            uint32_t bf[2] = { pb[0], pb[4 * BPS] };
            mma_f16(acc[nd], af, bf);
        }
    }

    const int r0 = m0 + w * 16 + lr, r1 = r0 + 8;
    const int b  = r0 >> 11;
    const int s0 = r0 & 2047, s1 = s0 + 8;

    if (hh < 16) {
        #pragma unroll
        for (int i = 0; i < 16; i++)
            #pragma unroll
            for (int j = 0; j < 4; j++) acc[i][j] *= SC_;
        __half* o0 = g_q + ((size_t)(b * H_ + hh) * S_ + s0) * D_;
        __half* o1 = g_q + ((size_t)(b * H_ + hh) * S_ + s1) * D_;
        #pragma unroll
        for (int nd = 0; nd < 8; nd++) {
            const int d0 = (nd << 3) + 2 * lc;
            float2 c0 = *(const float2*)(fcos + (size_t)s0*64 + d0);
            float2 z0 = *(const float2*)(fsin + (size_t)s0*64 + d0);
            float2 c1 = *(const float2*)(fcos + (size_t)s1*64 + d0);
            float2 z1 = *(const float2*)(fsin + (size_t)s1*64 + d0);
            *(uint32_t*)(o0+d0)    = h2rn(acc[nd][0]*c0.x - acc[nd+8][0]*z0.x,
                                          acc[nd][1]*c0.y - acc[nd+8][1]*z0.y);
            *(uint32_t*)(o0+d0+64) = h2rn(acc[nd][0]*z0.x + acc[nd+8][0]*c0.x,
                                          acc[nd][1]*z0.y + acc[nd+8][1]*c0.y);
            *(uint32_t*)(o1+d0)    = h2rn(acc[nd][2]*c1.x - acc[nd+8][2]*z1.x,
                                          acc[nd][3]*c1.y - acc[nd+8][3]*z1.y);
            *(uint32_t*)(o1+d0+64) = h2rn(acc[nd][2]*z1.x + acc[nd+8][2]*c1.x,
                                          acc[nd][3]*z1.y + acc[nd+8][3]*c1.y);
        }
    } else if (hh < 24) {
        int p0 = widx[s0], p1 = widx[s1];
        __half* o0 = g_k + ((size_t)(b * HKV_ + hh-16) * S_ + p0) * D_;
        __half* o1 = g_k + ((size_t)(b * HKV_ + hh-16) * S_ + p1) * D_;
        #pragma unroll
        for (int nd = 0; nd < 8; nd++) {
            const int d0 = (nd << 3) + 2 * lc;
            float2 c0 = *(const float2*)(fcos + (size_t)p0*64 + d0);
            float2 z0 = *(const float2*)(fsin + (size_t)p0*64 + d0);
            float2 c1 = *(const float2*)(fcos + (size_t)p1*64 + d0);
            float2 z1 = *(const float2*)(fsin + (size_t)p1*64 + d0);
            *(uint32_t*)(o0+d0)    = h2rn(acc[nd][0]*c0.x - acc[nd+8][0]*z0.x,
                                          acc[nd][1]*c0.y - acc[nd+8][1]*z0.y);
            *(uint32_t*)(o0+d0+64) = h2rn(acc[nd][0]*z0.x + acc[nd+8][0]*c0.x,
                                          acc[nd][1]*z0.y + acc[nd+8][1]*c0.y);
            *(uint32_t*)(o1+d0)    = h2rn(acc[nd][2]*c1.x - acc[nd+8][2]*z1.x,
                                          acc[nd][3]*c1.y - acc[nd+8][3]*z1.y);
            *(uint32_t*)(o1+d0+64) = h2rn(acc[nd][2]*z1.x + acc[nd+8][2]*c1.x,
                                          acc[nd][3]*z1.y + acc[nd+8][3]*c1.y);
        }
    } else {
        int p0 = widx[s0], p1 = widx[s1];
        __half* o0 = g_v + ((size_t)(b * HKV_ + hh-24) * S_ + p0) * D_;
        __half* o1 = g_v + ((size_t)(b * HKV_ + hh-24) * S_ + p1) * D_;
        #pragma unroll
        for (int nd = 0; nd < 16; nd++) {
            const int d0 = (nd << 3) + 2 * lc;
            *(uint32_t*)(o0 + d0) = h2rn(acc[nd][0], acc[nd][1]);
            *(uint32_t*)(o1 + d0) = h2rn(acc[nd][2], acc[nd][3]);
        }
    }
}

// ---------------------------------------------------------------------------
// Flash attention, fp16 mma. 128 q-rows per CTA, 8 warps, k-tiles of 64.
// ---------------------------------------------------------------------------
#define KTS 136
#define VPS 136
#define FL_SMEM (64*KTS*2 + 32*VPS*4)

__global__ void __launch_bounds__(256, 1) flash_h()
{
    extern __shared__ __align__(16) char smraw[];
    __half*   Ks  = (__half*)smraw;
    uint32_t* Vp  = (uint32_t*)(smraw + 64*KTS*2);
    __half*   Qst = (__half*)smraw;

    const int tid = threadIdx.x, w = tid >> 5, lane = tid & 31;
    const int lr = lane >> 2, lc = lane & 3;
    const int qt = (int)gridDim.x - 1 - (int)blockIdx.x;
    const int bh = blockIdx.y;
    const int b = bh >> 4, h = bh & 15, kvh = h >> 1;
    const int qp = qt << 7;

    const __half* qbase = g_q + ((size_t)(b * H_ + h) * S_ + qp) * D_;
    const __half* kbase = g_k + (size_t)(b * HKV_ + kvh) * S_ * D_;
    const __half* vbase = g_v + (size_t)(b * HKV_ + kvh) * S_ * D_;

    #pragma unroll
    for (int i = 0; i < 8; i++) {
        int idx = tid + (i << 8);
        int r = idx >> 4, g = idx & 15;
        *(uint4*)(Qst + r * KTS + g * 8) = *(const uint4*)(qbase + (size_t)r * 128 + g * 8);
    }
    __syncthreads();

    uint32_t qf[8][4];
    #pragma unroll
    for (int k8 = 0; k8 < 8; k8++) {
        const __half* p = Qst + (w * 16 + lr) * KTS + (k8 << 4) + 2 * lc;
        qf[k8][0] = *(const uint32_t*)(p);
        qf[k8][1] = *(const uint32_t*)(p + 8 * KTS);
        qf[k8][2] = *(const uint32_t*)(p + 8);
        qf[k8][3] = *(const uint32_t*)(p + 8 * KTS + 8);
    }
    __syncthreads();

    float oacc[16][4];
    #pragma unroll
    for (int i = 0; i < 16; i++)
        #pragma unroll
        for (int j = 0; j < 4; j++) oacc[i][j] = 0.f;
    float m0 = -1e30f, m1 = -1e30f, l0 = 0.f, l1 = 0.f;
    const int r0g = qp + w * 16 + lr, r1g = r0g + 8;

    const int ktmax = 2 * qt + 1;
    for (int kt = 0; kt <= ktmax; kt++) {
        const __half* kp = kbase + (size_t)kt * 64 * 128;
        const __half* vp = vbase + (size_t)kt * 64 * 128;
        #pragma unroll
        for (int i = 0; i < 4; i++) {
            int idx = tid + (i << 8);
            int r = idx >> 4, g = idx & 15;
            *(uint4*)(Ks + r * KTS + g * 8) = *(const uint4*)(kp + (size_t)r * 128 + g * 8);
        }
        #pragma unroll
        for (int i = 0; i < 4; i++) {
            int idx = tid + (i << 8);
            int r2 = idx >> 5, cg = idx & 31;
            uint2 a = *(const uint2*)(vp + (size_t)(2*r2) * 128 + cg * 4);
            uint2 c = *(const uint2*)(vp + (size_t)(2*r2+1) * 128 + cg * 4);
            const __half* ah = (const __half*)&a;
            const __half* ch = (const __half*)&c;
            uint4 o;
            __half2 t0 = __halves2half2(ah[0], ch[0]); o.x = *(uint32_t*)&t0;
            __half2 t1 = __halves2half2(ah[1], ch[1]); o.y = *(uint32_t*)&t1;
            __half2 t2 = __halves2half2(ah[2], ch[2]); o.z = *(uint32_t*)&t2;
            __half2 t3 = __halves2half2(ah[3], ch[3]); o.w = *(uint32_t*)&t3;
            *(uint4*)(Vp + r2 * VPS + cg * 4) = o;
        }
        __syncthreads();

        float sacc[8][4];
        #pragma unroll
        for (int i = 0; i < 8; i++)
            #pragma unroll
            for (int j = 0; j < 4; j++) sacc[i][j] = 0.f;
        #pragma unroll
        for (int k8 = 0; k8 < 8; k8++) {
            #pragma unroll
            for (int nt = 0; nt < 8; nt++) {
                const __half* p = Ks + (nt * 8 + lr) * KTS + (k8 << 4) + 2 * lc;
                uint32_t bf[2] = { *(const uint32_t*)(p), *(const uint32_t*)(p + 8) };
                mma_f16(sacc[nt], qf[k8], bf);
            }
        }

        if (kt >= 2 * qt) {
            const int cb = kt * 64;
            #pragma unroll
            for (int nt = 0; nt < 8; nt++) {
                int c0 = cb + nt * 8 + 2 * lc;
                if (c0     > r0g) sacc[nt][0] = -1e30f;
                if (c0 + 1 > r0g) sacc[nt][1] = -1e30f;
                if (c0     > r1g) sacc[nt][2] = -1e30f;
                if (c0 + 1 > r1g) sacc[nt][3] = -1e30f;
            }
        }

        float mi0 = -1e30f, mi1 = -1e30f;
        #pragma unroll
        for (int nt = 0; nt < 8; nt++) {
            mi0 = fmaxf(mi0, fmaxf(sacc[nt][0], sacc[nt][1]));
            mi1 = fmaxf(mi1, fmaxf(sacc[nt][2], sacc[nt][3]));
        }
        mi0 = fmaxf(mi0, __shfl_xor_sync(0xffffffffu, mi0, 1));
        mi0 = fmaxf(mi0, __shfl_xor_sync(0xffffffffu, mi0, 2));
        mi1 = fmaxf(mi1, __shfl_xor_sync(0xffffffffu, mi1, 1));
        mi1 = fmaxf(mi1, __shfl_xor_sync(0xffffffffu, mi1, 2));
        float mn0 = fmaxf(m0, mi0), mn1 = fmaxf(m1, mi1);
        float sf0 = __expf(m0 - mn0), sf1 = __expf(m1 - mn1);
        m0 = mn0; m1 = mn1;

        float ps0 = 0.f, ps1 = 0.f;
        #pragma unroll
        for (int nt = 0; nt < 8; nt++) {
            sacc[nt][0] = __expf(sacc[nt][0] - m0);
            sacc[nt][1] = __expf(sacc[nt][1] - m0);
            sacc[nt][2] = __expf(sacc[nt][2] - m1);
            sacc[nt][3] = __expf(sacc[nt][3] - m1);
            ps0 += sacc[nt][0] + sacc[nt][1];
            ps1 += sacc[nt][2] + sacc[nt][3];
        }
        ps0 += __shfl_xor_sync(0xffffffffu, ps0, 1);
        ps0 += __shfl_xor_sync(0xffffffffu, ps0, 2);
        ps1 += __shfl_xor_sync(0xffffffffu, ps1, 1);
        ps1 += __shfl_xor_sync(0xffffffffu, ps1, 2);
        l0 = l0 * sf0 + ps0;
        l1 = l1 * sf1 + ps1;

        #pragma unroll
        for (int nd = 0; nd < 16; nd++) {
            oacc[nd][0] *= sf0; oacc[nd][1] *= sf0;
            oacc[nd][2] *= sf1; oacc[nd][3] *= sf1;
        }

        #pragma unroll
        for (int ks = 0; ks < 4; ks++) {
            uint32_t af[4] = { h2rn(sacc[2*ks][0],   sacc[2*ks][1]),
                               h2rn(sacc[2*ks][2],   sacc[2*ks][3]),
                               h2rn(sacc[2*ks+1][0], sacc[2*ks+1][1]),
                               h2rn(sacc[2*ks+1][2], sacc[2*ks+1][3]) };
            #pragma unroll
            for (int nd = 0; nd < 16; nd++) {
                const uint32_t* pb = Vp + (ks * 8 + lc) * VPS + nd * 8 + lr;
                uint32_t bf[2] = { pb[0], pb[4 * VPS] };
                mma_f16(oacc[nd], af, bf);
            }
        }
        __syncthreads();
    }

    float i0 = 1.f / l0, i1 = 1.f / l1;
    __half* o0 = g_ao16 + ((size_t)b * S_ + r0g) * 2048 + h * 128 + 2 * lc;
    __half* o1 = g_ao16 + ((size_t)b * S_ + r1g) * 2048 + h * 128 + 2 * lc;
    #pragma unroll
    for (int nd = 0; nd < 16; nd++) {
        *(uint32_t*)(o0 + nd * 8) = h2rn(oacc[nd][0] * i0, oacc[nd][1] * i0);
        *(uint32_t*)(o1 + nd * 8) = h2rn(oacc[nd][2] * i1, oacc[nd][3] * i1);
    }
}

// ---------------------------------------------------------------------------
extern "C" void kernel_launch(void* const* d_in, const int* in_sizes, int n_in,
                              void* d_out, int out_size)
{
    const float* hs   = (const float*)d_in[0];
    const float* WAq  = (const float*)d_in[1];
    const float* WAk  = (const float*)d_in[2];
    const float* WAv  = (const float*)d_in[3];
    const float* Bq   = (const float*)d_in[4];
    const float* Bk   = (const float*)d_in[5];
    const float* Bv   = (const float*)d_in[6];
    const float* Wo   = (const float*)d_in[7];
    const float* fcos = (const float*)d_in[8];
    const float* fsin = (const float*)d_in[9];
    const int*   widx = (const int*)d_in[11];
    float* out = (float*)d_out;

    __half *phs, *pw, *pwo;
    cudaGetSymbolAddress((void**)&phs, g_hs16);
    cudaGetSymbolAddress((void**)&pw,  g_w16);
    cudaGetSymbolAddress((void**)&pwo, g_wo16);

    cudaFuncSetAttribute(proj_h,  cudaFuncAttributeMaxDynamicSharedMemorySize, G16_SMEM);
    cudaFuncSetAttribute(oproj_h, cudaFuncAttributeMaxDynamicSharedMemorySize, G16_SMEM);
    cudaFuncSetAttribute(qkv_h,   cudaFuncAttributeMaxDynamicSharedMemorySize, QKV_SMEM);
    cudaFuncSetAttribute(flash_h, cudaFuncAttributeMaxDynamicSharedMemorySize, FL_SMEM);

    // fp32 -> fp16 one-time conversions
    cvt16<<<4096, 256>>>(hs,  phs);
    cvt16<<<1024, 256>>>(WAq, pw);
    cvt16<<< 512, 256>>>(WAk, pw + (size_t)1024*2048);
    cvt16<<< 512, 256>>>(WAv, pw + (size_t)1536*2048);
    cvt16<<<2048, 256>>>(Wo,  pwo);

    proj_h <<<dim3(16, 32), 256, G16_SMEM>>>();
    qkv_h  <<<dim3(32, 32), 256, QKV_SMEM>>>(Bq, Bk, Bv, fcos, fsin, widx);
    flash_h<<<dim3(S_ / 128, B_ * H_), 256, FL_SMEM>>>();
    oproj_h<<<dim3(16, 32), 256, G16_SMEM>>>(out);
}

// round 9
// speedup vs baseline: 6.5108x; 1.0433x over previous
#include <cuda_runtime.h>
#include <cuda_fp16.h>
#include <cstdint>

#define B_   2
#define S_   2048
#define H_   16
#define HKV_ 8
#define D_   128
#define NROW (B_*S_)

// Scratch (device globals)
__device__ __align__(16) __half g_hs16[(size_t)NROW*2048];
__device__ __align__(16) __half g_w16 [(size_t)2048*2048];     // [WAq | WAk | WAv] rows
__device__ __align__(16) __half g_wo16[(size_t)2048*2048];
__device__ __align__(16) __half g_A   [(size_t)NROW*2048];
__device__ __align__(16) __half g_q   [(size_t)B_*H_  *S_*D_]; // pre-scaled by 1/sqrt(D)
__device__ __align__(16) __half g_k   [(size_t)B_*HKV_*S_*D_];
__device__ __align__(16) __half g_v   [(size_t)B_*HKV_*S_*D_]; // PACKED: [(b,kv)][pos/2][2d+(pos&1)]
__device__ __align__(16) __half g_ao16[(size_t)NROW*2048];

__device__ __forceinline__ uint32_t h2rn(float a, float b) {
    __half2 h = __floats2half2_rn(a, b);
    return *reinterpret_cast<uint32_t*>(&h);
}
__device__ __forceinline__ void mma_f16(float* c, const uint32_t* a, const uint32_t* b) {
    asm volatile(
        "mma.sync.aligned.m16n8k16.row.col.f32.f16.f16.f32 "
        "{%0,%1,%2,%3}, {%4,%5,%6,%7}, {%8,%9}, {%0,%1,%2,%3};"
        : "+f"(c[0]), "+f"(c[1]), "+f"(c[2]), "+f"(c[3])
        : "r"(a[0]), "r"(a[1]), "r"(a[2]), "r"(a[3]), "r"(b[0]), "r"(b[1]));
}
__device__ __forceinline__ void ldsm4(uint32_t* r, uint32_t addr) {
    asm volatile("ldmatrix.sync.aligned.m8n8.x4.shared.b16 {%0,%1,%2,%3}, [%4];"
        : "=r"(r[0]), "=r"(r[1]), "=r"(r[2]), "=r"(r[3]) : "r"(addr));
}
__device__ __forceinline__ uint32_t smem_u32(const void* p) {
    uint32_t a;
    asm("{ .reg .u64 t; cvta.to.shared.u64 t, %1; cvt.u32.u64 %0, t; }" : "=r"(a) : "l"(p));
    return a;
}
__device__ __forceinline__ void cp16(uint32_t d, const void* s) {
    asm volatile("cp.async.cg.shared.global [%0], [%1], 16;" :: "r"(d), "l"(s));
}
#define CP_COMMIT() asm volatile("cp.async.commit_group;")

// ---------------------------------------------------------------------------
// fused fp32 -> fp16 conversion of all 5 tensors (8 floats / thread)
// groups: hs 1048576 | WAq 262144 | WAk 131072 | WAv 131072 | Wo 524288
// ---------------------------------------------------------------------------
__global__ void __launch_bounds__(256) cvt_all(
    const float* __restrict__ hs, const float* __restrict__ waq,
    const float* __restrict__ wak, const float* __restrict__ wav,
    const float* __restrict__ wo)
{
    size_t g = (size_t)blockIdx.x * 256 + threadIdx.x;
    const float* s; __half* d;
    if (g < 1048576)      { s = hs;  d = g_hs16; }
    else if (g < 1310720) { g -= 1048576; s = waq; d = g_w16; }
    else if (g < 1441792) { g -= 1310720; s = wak; d = g_w16 + (size_t)1024*2048; }
    else if (g < 1572864) { g -= 1441792; s = wav; d = g_w16 + (size_t)1536*2048; }
    else                  { g -= 1572864; s = wo;  d = g_wo16; }
    size_t i = g * 8;
    float4 a = *(const float4*)(s + i);
    float4 b = *(const float4*)(s + i + 4);
    uint4 o = { h2rn(a.x,a.y), h2rn(a.z,a.w), h2rn(b.x,b.y), h2rn(b.z,b.w) };
    *(uint4*)(d + i) = o;
}

// ---------------------------------------------------------------------------
// Pure-fp16 GEMM body, cp.async 4-stage pipeline + ldmatrix fragments.
// ---------------------------------------------------------------------------
#define GTS 40
#define GSTG (128*GTS)
#define NST 4
#define G16_SMEM (NST*2*GSTG*2)        // 81920 B

__device__ __forceinline__ void g16_issue(uint32_t sb, int stg,
    const __half* __restrict__ A, const __half* __restrict__ B, int tid)
{
    uint32_t ab = sb + stg * 2 * GSTG * 2;
    uint32_t bb = ab + GSTG * 2;
    #pragma unroll
    for (int i = 0; i < 2; i++) {
        int t = tid * 2 + i;
        int row = t >> 2, seg = t & 3;
        cp16(ab + row * 80 + seg * 16, A + (size_t)row * 2048 + seg * 8);
        cp16(bb + row * 80 + seg * 16, B + (size_t)row * 2048 + seg * 8);
    }
}

__device__ __forceinline__ void gemm16_acc(
    uint32_t sb, const __half* __restrict__ A,
    const __half* __restrict__ B, float acc[4][4][4])
{
    const int tid = threadIdx.x, wid = tid >> 5, lane = tid & 31;
    const int wm = wid >> 2, wn = wid & 3;
    const int arow = (lane & 7) + ((lane >> 3) & 1) * 8, acol = (lane >> 4) * 8;
    const int brow = (lane & 7) + (lane >> 4) * 8,       bcol = ((lane >> 3) & 1) * 8;

    #pragma unroll
    for (int s = 0; s < NST - 1; s++) {
        g16_issue(sb, s, A + s * 32, B + s * 32, tid);
        CP_COMMIT();
    }

    for (int c = 0; c < 64; c++) {
        if (c + NST - 1 < 64) {
            asm volatile("cp.async.wait_group 2;");
            __syncthreads();
            g16_issue(sb, (c + NST - 1) & 3, A + (c + NST - 1) * 32, B + (c + NST - 1) * 32, tid);
            CP_COMMIT();
        } else {
            asm volatile("cp.async.wait_group 0;");
            __syncthreads();
        }

        uint32_t ab = sb + (c & 3) * 2 * GSTG * 2;
        uint32_t bb = ab + GSTG * 2;
        #pragma unroll
        for (int ks = 0; ks < 2; ks++) {
            uint32_t af[4][4], b01[4], b23[4];
            #pragma unroll
            for (int mi = 0; mi < 4; mi++)
                ldsm4(af[mi], ab + ((wm*64 + mi*16 + arow) * GTS + ks*16 + acol) * 2);
            ldsm4(b01, bb + ((wn*32 +      brow) * GTS + ks*16 + bcol) * 2);
            ldsm4(b23, bb + ((wn*32 + 16 + brow) * GTS + ks*16 + bcol) * 2);
            uint32_t* bf[4] = { b01, b01 + 2, b23, b23 + 2 };
            #pragma unroll
            for (int mi = 0; mi < 4; mi++)
                #pragma unroll
                for (int ni = 0; ni < 4; ni++)
                    mma_f16(acc[mi][ni], af[mi], bf[ni]);
        }
        __syncthreads();
    }
}

// merged 3-way projection -> g_A (fp16, /64 folded)
__global__ void __launch_bounds__(256, 1) proj_h()
{
    extern __shared__ __half smh[];
    const int x = blockIdx.x;
    const size_t m0 = (size_t)blockIdx.y << 7;

    float acc[4][4][4];
    #pragma unroll
    for (int i = 0; i < 4; i++)
        #pragma unroll
        for (int j = 0; j < 4; j++)
            #pragma unroll
            for (int r = 0; r < 4; r++) acc[i][j][r] = 0.f;

    gemm16_acc(smem_u32(smh), g_hs16 + m0 * 2048, g_w16 + (size_t)x * 128 * 2048, acc);

    const int tid = threadIdx.x, wid = tid >> 5, lane = tid & 31;
    const int wm = wid >> 2, wn = wid & 3, lr = lane >> 2, lc = lane & 3;
    const float al = 1.0f / 64.0f;
    __half* C = g_A + m0 * 2048 + x * 128;
    #pragma unroll
    for (int mi = 0; mi < 4; mi++) {
        const int row = wm * 64 + mi * 16 + lr;
        #pragma unroll
        for (int ni = 0; ni < 4; ni++) {
            const int col = wn * 32 + ni * 8 + lc * 2;
            *(uint32_t*)(C + (size_t)row * 2048 + col)     = h2rn(acc[mi][ni][0]*al, acc[mi][ni][1]*al);
            *(uint32_t*)(C + (size_t)(row+8) * 2048 + col) = h2rn(acc[mi][ni][2]*al, acc[mi][ni][3]*al);
        }
    }
}

// output projection: g_ao16 x g_wo16 -> out (fp32)
__global__ void __launch_bounds__(256, 1) oproj_h(float* __restrict__ out)
{
    extern __shared__ __half smh[];
    const size_t m0 = (size_t)blockIdx.y << 7;
    const size_t n0 = (size_t)blockIdx.x << 7;

    float acc[4][4][4];
    #pragma unroll
    for (int i = 0; i < 4; i++)
        #pragma unroll
        for (int j = 0; j < 4; j++)
            #pragma unroll
            for (int r = 0; r < 4; r++) acc[i][j][r] = 0.f;

    gemm16_acc(smem_u32(smh), g_ao16 + m0 * 2048, g_wo16 + n0 * 2048, acc);

    const int tid = threadIdx.x, wid = tid >> 5, lane = tid & 31;
    const int wm = wid >> 2, wn = wid & 3, lr = lane >> 2, lc = lane & 3;
    float* C = out + m0 * 2048 + n0;
    #pragma unroll
    for (int mi = 0; mi < 4; mi++) {
        const int row = wm * 64 + mi * 16 + lr;
        #pragma unroll
        for (int ni = 0; ni < 4; ni++) {
            const int col = wn * 32 + ni * 8 + lc * 2;
            float2 v0 = { acc[mi][ni][0], acc[mi][ni][1] };
            float2 v1 = { acc[mi][ni][2], acc[mi][ni][3] };
            *(float2*)(C + (size_t)row * 2048 + col)     = v0;
            *(float2*)(C + (size_t)(row+8) * 2048 + col) = v1;
        }
    }
}

// ---------------------------------------------------------------------------
// q/k/v build (fp16 mma, K=64) + RoPE + scatter (V packed pairs). grid (32,32).
// ---------------------------------------------------------------------------
#define QATS 72
#define BPS  136
#define QKV_SMEM (128*QATS*2 + 32*BPS*4)
#define SC_ 0.088388347648318447f

__global__ void __launch_bounds__(256, 1) qkv_h(
    const float* __restrict__ Bq, const float* __restrict__ Bk, const float* __restrict__ Bv,
    const float* __restrict__ fcos, const float* __restrict__ fsin,
    const int* __restrict__ widx)
{
    extern __shared__ __align__(16) char smraw[];
    __half*   As = (__half*)smraw;
    uint32_t* Bp = (uint32_t*)(smraw + 128*QATS*2);

    const int tid = threadIdx.x, w = tid >> 5, lane = tid & 31;
    const int lr = lane >> 2, lc = lane & 3;
    const int m0 = blockIdx.x << 7;
    const int hh = blockIdx.y;

    const float* Bmat; int aoff;
    if (hh < 16)      { Bmat = Bq + (size_t)hh * 8192;        aoff = hh * 64; }
    else if (hh < 24) { Bmat = Bk + (size_t)(hh - 16) * 8192; aoff = 1024 + (hh - 16) * 64; }
    else              { Bmat = Bv + (size_t)(hh - 24) * 8192; aoff = 1536 + (hh - 24) * 64; }

    #pragma unroll
    for (int i = 0; i < 4; i++) {
        int idx = tid + (i << 8);
        int r = idx >> 3, g = idx & 7;
        *(uint4*)(As + r * QATS + g * 8) =
            *(const uint4*)(g_A + (size_t)(m0 + r) * 2048 + aoff + g * 8);
    }
    #pragma unroll
    for (int i = 0; i < 4; i++) {
        int idx = tid + (i << 8);
        int r2 = idx >> 5, cg = idx & 31;
        float4 a = *(const float4*)(Bmat + (size_t)(2*r2) * 128 + cg * 4);
        float4 b = *(const float4*)(Bmat + (size_t)(2*r2+1) * 128 + cg * 4);
        uint4 o = { h2rn(a.x,b.x), h2rn(a.y,b.y), h2rn(a.z,b.z), h2rn(a.w,b.w) };
        *(uint4*)(Bp + r2 * BPS + cg * 4) = o;
    }
    __syncthreads();

    float acc[16][4];
    #pragma unroll
    for (int i = 0; i < 16; i++)
        #pragma unroll
        for (int j = 0; j < 4; j++) acc[i][j] = 0.f;

    #pragma unroll
    for (int s = 0; s < 4; s++) {
        const __half* pa = As + (w * 16 + lr) * QATS + s * 16 + 2 * lc;
        uint32_t af[4] = { *(const uint32_t*)(pa), *(const uint32_t*)(pa + 8*QATS),
                           *(const uint32_t*)(pa + 8), *(const uint32_t*)(pa + 8*QATS + 8) };
        #pragma unroll
        for (int nd = 0; nd < 16; nd++) {
            const uint32_t* pb = Bp + (s * 8 + lc) * BPS + nd * 8 + lr;
            uint32_t bf[2] = { pb[0], pb[4 * BPS] };
            mma_f16(acc[nd], af, bf);
        }
    }

    const int r0 = m0 + w * 16 + lr, r1 = r0 + 8;
    const int b  = r0 >> 11;
    const int s0 = r0 & 2047, s1 = s0 + 8;

    if (hh < 16) {
        #pragma unroll
        for (int i = 0; i < 16; i++)
            #pragma unroll
            for (int j = 0; j < 4; j++) acc[i][j] *= SC_;
        __half* o0 = g_q + ((size_t)(b * H_ + hh) * S_ + s0) * D_;
        __half* o1 = g_q + ((size_t)(b * H_ + hh) * S_ + s1) * D_;
        #pragma unroll
        for (int nd = 0; nd < 8; nd++) {
            const int d0 = (nd << 3) + 2 * lc;
            float2 c0 = *(const float2*)(fcos + (size_t)s0*64 + d0);
            float2 z0 = *(const float2*)(fsin + (size_t)s0*64 + d0);
            float2 c1 = *(const float2*)(fcos + (size_t)s1*64 + d0);
            float2 z1 = *(const float2*)(fsin + (size_t)s1*64 + d0);
            *(uint32_t*)(o0+d0)    = h2rn(acc[nd][0]*c0.x - acc[nd+8][0]*z0.x,
                                          acc[nd][1]*c0.y - acc[nd+8][1]*z0.y);
            *(uint32_t*)(o0+d0+64) = h2rn(acc[nd][0]*z0.x + acc[nd+8][0]*c0.x,
                                          acc[nd][1]*z0.y + acc[nd+8][1]*c0.y);
            *(uint32_t*)(o1+d0)    = h2rn(acc[nd][2]*c1.x - acc[nd+8][2]*z1.x,
                                          acc[nd][3]*c1.y - acc[nd+8][3]*z1.y);
            *(uint32_t*)(o1+d0+64) = h2rn(acc[nd][2]*z1.x + acc[nd+8][2]*c1.x,
                                          acc[nd][3]*z1.y + acc[nd+8][3]*c1.y);
        }
    } else if (hh < 24) {
        int p0 = widx[s0], p1 = widx[s1];
        __half* o0 = g_k + ((size_t)(b * HKV_ + hh-16) * S_ + p0) * D_;
        __half* o1 = g_k + ((size_t)(b * HKV_ + hh-16) * S_ + p1) * D_;
        #pragma unroll
        for (int nd = 0; nd < 8; nd++) {
            const int d0 = (nd << 3) + 2 * lc;
            float2 c0 = *(const float2*)(fcos + (size_t)p0*64 + d0);
            float2 z0 = *(const float2*)(fsin + (size_t)p0*64 + d0);
            float2 c1 = *(const float2*)(fcos + (size_t)p1*64 + d0);
            float2 z1 = *(const float2*)(fsin + (size_t)p1*64 + d0);
            *(uint32_t*)(o0+d0)    = h2rn(acc[nd][0]*c0.x - acc[nd+8][0]*z0.x,
                                          acc[nd][1]*c0.y - acc[nd+8][1]*z0.y);
            *(uint32_t*)(o0+d0+64) = h2rn(acc[nd][0]*z0.x + acc[nd+8][0]*c0.x,
                                          acc[nd][1]*z0.y + acc[nd+8][1]*c0.y);
            *(uint32_t*)(o1+d0)    = h2rn(acc[nd][2]*c1.x - acc[nd+8][2]*z1.x,
                                          acc[nd][3]*c1.y - acc[nd+8][3]*z1.y);
            *(uint32_t*)(o1+d0+64) = h2rn(acc[nd][2]*z1.x + acc[nd+8][2]*c1.x,
                                          acc[nd][3]*z1.y + acc[nd+8][3]*c1.y);
        }
    } else {   // V: packed-pair scatter
        int p0 = widx[s0], p1 = widx[s1];
        __half* vb = g_v + (size_t)(b * HKV_ + hh - 24) * S_ * D_;
        size_t base0 = (size_t)(p0 >> 1) * 256 + (p0 & 1);
        size_t base1 = (size_t)(p1 >> 1) * 256 + (p1 & 1);
        #pragma unroll
        for (int nd = 0; nd < 16; nd++) {
            const int d0 = (nd << 3) + 2 * lc;
            vb[base0 + 2*d0]     = __float2half_rn(acc[nd][0]);
            vb[base0 + 2*d0 + 2] = __float2half_rn(acc[nd][1]);
            vb[base1 + 2*d0]     = __float2half_rn(acc[nd][2]);
            vb[base1 + 2*d0 + 2] = __float2half_rn(acc[nd][3]);
        }
    }
}

// ---------------------------------------------------------------------------
// Flash attention, fp16 mma, cp.async double-buffered K/V, ldmatrix frags.
// 128 q-rows/CTA, 8 warps, k-tiles of 64.
// smem: [K0 17408 | V0 17408 | K1 17408 | V1 17408] = 69632 B; Q overlays K0+V0.
// ---------------------------------------------------------------------------
#define KTS 136           // halves
#define VPS 136           // u32
#define FL_SMEM 69632

__device__ __forceinline__ void fl_issue(uint32_t sb, int buf,
    const __half* __restrict__ kp, const __half* __restrict__ vsrc, int tid)
{
    uint32_t kb = sb + (buf ? 34816u : 0u);
    uint32_t vb = kb + 17408u;
    #pragma unroll
    for (int i = 0; i < 4; i++) {
        int idx = tid + (i << 8);
        int r = idx >> 4, g = idx & 15;
        cp16(kb + (r * KTS + g * 8) * 2, kp + (size_t)r * 128 + g * 8);
    }
    #pragma unroll
    for (int i = 0; i < 4; i++) {
        int idx = tid + (i << 8);
        int r2 = idx >> 5, cg = idx & 31;
        cp16(vb + r2 * (VPS * 4) + cg * 16, vsrc + (size_t)r2 * 256 + cg * 8);
    }
}

__global__ void __launch_bounds__(256, 1) flash_h()
{
    extern __shared__ __align__(16) char smraw[];
    const uint32_t sb = smem_u32(smraw);

    const int tid = threadIdx.x, w = tid >> 5, lane = tid & 31;
    const int lr = lane >> 2, lc = lane & 3;
    const int arow = (lane & 7) + ((lane >> 3) & 1) * 8, acol = (lane >> 4) * 8;
    const int brow = (lane & 7) + (lane >> 4) * 8,       bcol = ((lane >> 3) & 1) * 8;
    const int qt = (int)gridDim.x - 1 - (int)blockIdx.x;
    const int bh = blockIdx.y;
    const int b = bh >> 4, h = bh & 15, kvh = h >> 1;
    const int qp = qt << 7;

    const __half* qbase = g_q + ((size_t)(b * H_ + h) * S_ + qp) * D_;
    const __half* kbase = g_k + (size_t)(b * HKV_ + kvh) * S_ * D_;
    const __half* vbase = g_v + (size_t)(b * HKV_ + kvh) * S_ * D_;   // packed

    // stage Q into overlay, pull frags via ldmatrix
    __half* Qst = (__half*)smraw;
    #pragma unroll
    for (int i = 0; i < 8; i++) {
        int idx = tid + (i << 8);
        int r = idx >> 4, g = idx & 15;
        *(uint4*)(Qst + r * KTS + g * 8) = *(const uint4*)(qbase + (size_t)r * 128 + g * 8);
    }
    __syncthreads();
    uint32_t qf[8][4];
    #pragma unroll
    for (int k8 = 0; k8 < 8; k8++)
        ldsm4(qf[k8], sb + ((w * 16 + arow) * KTS + (k8 << 4) + acol) * 2);
    __syncthreads();

    float oacc[16][4];
    #pragma unroll
    for (int i = 0; i < 16; i++)
        #pragma unroll
        for (int j = 0; j < 4; j++) oacc[i][j] = 0.f;
    float m0 = -1e30f, m1 = -1e30f, l0 = 0.f, l1 = 0.f;
    const int r0g = qp + w * 16 + lr, r1g = r0g + 8;

    const int ktmax = 2 * qt + 1;
    fl_issue(sb, 0, kbase, vbase, tid);
    CP_COMMIT();

    for (int kt = 0; kt <= ktmax; kt++) {
        if (kt < ktmax) {
            fl_issue(sb, (kt + 1) & 1, kbase + (size_t)(kt + 1) * 8192,
                     vbase + (size_t)(kt + 1) * 8192, tid);
            CP_COMMIT();
            asm volatile("cp.async.wait_group 1;");
        } else {
            asm volatile("cp.async.wait_group 0;");
        }
        __syncthreads();

        const uint32_t kb = sb + ((kt & 1) ? 34816u : 0u);
        const uint32_t* Vp = (const uint32_t*)(smraw + ((kt & 1) ? 34816 : 0) + 17408);

        // S = Q K^T via ldmatrix B-frags
        float sacc[8][4];
        #pragma unroll
        for (int i = 0; i < 8; i++)
            #pragma unroll
            for (int j = 0; j < 4; j++) sacc[i][j] = 0.f;
        #pragma unroll
        for (int k8 = 0; k8 < 8; k8++) {
            #pragma unroll
            for (int ntp = 0; ntp < 4; ntp++) {
                uint32_t bq[4];
                ldsm4(bq, kb + ((ntp * 16 + brow) * KTS + (k8 << 4) + bcol) * 2);
                mma_f16(sacc[2*ntp],     qf[k8], bq);
                mma_f16(sacc[2*ntp + 1], qf[k8], bq + 2);
            }
        }

        if (kt >= 2 * qt) {
            const int cb = kt * 64;
            #pragma unroll
            for (int nt = 0; nt < 8; nt++) {
                int c0 = cb + nt * 8 + 2 * lc;
                if (c0     > r0g) sacc[nt][0] = -1e30f;
                if (c0 + 1 > r0g) sacc[nt][1] = -1e30f;
                if (c0     > r1g) sacc[nt][2] = -1e30f;
                if (c0 + 1 > r1g) sacc[nt][3] = -1e30f;
            }
        }

        float mi0 = -1e30f, mi1 = -1e30f;
        #pragma unroll
        for (int nt = 0; nt < 8; nt++) {
            mi0 = fmaxf(mi0, fmaxf(sacc[nt][0], sacc[nt][1]));
            mi1 = fmaxf(mi1, fmaxf(sacc[nt][2], sacc[nt][3]));
        }
        mi0 = fmaxf(mi0, __shfl_xor_sync(0xffffffffu, mi0, 1));
        mi0 = fmaxf(mi0, __shfl_xor_sync(0xffffffffu, mi0, 2));
        mi1 = fmaxf(mi1, __shfl_xor_sync(0xffffffffu, mi1, 1));
        mi1 = fmaxf(mi1, __shfl_xor_sync(0xffffffffu, mi1, 2));
        float mn0 = fmaxf(m0, mi0), mn1 = fmaxf(m1, mi1);
        float sf0 = __expf(m0 - mn0), sf1 = __expf(m1 - mn1);
        m0 = mn0; m1 = mn1;

        float ps0 = 0.f, ps1 = 0.f;
        #pragma unroll
        for (int nt = 0; nt < 8; nt++) {
            sacc[nt][0] = __expf(sacc[nt][0] - m0);
            sacc[nt][1] = __expf(sacc[nt][1] - m0);
            sacc[nt][2] = __expf(sacc[nt][2] - m1);
            sacc[nt][3] = __expf(sacc[nt][3] - m1);
            ps0 += sacc[nt][0] + sacc[nt][1];
            ps1 += sacc[nt][2] + sacc[nt][3];
        }
        ps0 += __shfl_xor_sync(0xffffffffu, ps0, 1);
        ps0 += __shfl_xor_sync(0xffffffffu, ps0, 2);
        ps1 += __shfl_xor_sync(0xffffffffu, ps1, 1);
        ps1 += __shfl_xor_sync(0xffffffffu, ps1, 2);
        l0 = l0 * sf0 + ps0;
        l1 = l1 * sf1 + ps1;

        #pragma unroll
        for (int nd = 0; nd < 16; nd++) {
            oacc[nd][0] *= sf0; oacc[nd][1] *= sf0;
            oacc[nd][2] *= sf1; oacc[nd][3] *= sf1;
        }

        #pragma unroll
        for (int ks = 0; ks < 4; ks++) {
            uint32_t af[4] = { h2rn(sacc[2*ks][0],   sacc[2*ks][1]),
                               h2rn(sacc[2*ks][2],   sacc[2*ks][3]),
                               h2rn(sacc[2*ks+1][0], sacc[2*ks+1][1]),
                               h2rn(sacc[2*ks+1][2], sacc[2*ks+1][3]) };
            #pragma unroll
            for (int nd = 0; nd < 16; nd++) {
                const uint32_t* pb = Vp + (ks * 8 + lc) * VPS + nd * 8 + lr;
                uint32_t bf[2] = { pb[0], pb[4 * VPS] };
                mma_f16(oacc[nd], af, bf);
            }
        }
        __syncthreads();
    }

    float i0 = 1.f / l0, i1 = 1.f / l1;
    __half* o0 = g_ao16 + ((size_t)b * S_ + r0g) * 2048 + h * 128 + 2 * lc;
    __half* o1 = g_ao16 + ((size_t)b * S_ + r1g) * 2048 + h * 128 + 2 * lc;
    #pragma unroll
    for (int nd = 0; nd < 16; nd++) {
        *(uint32_t*)(o0 + nd * 8) = h2rn(oacc[nd][0] * i0, oacc[nd][1] * i0);
        *(uint32_t*)(o1 + nd * 8) = h2rn(oacc[nd][2] * i1, oacc[nd][3] * i1);
    }
}

// ---------------------------------------------------------------------------
extern "C" void kernel_launch(void* const* d_in, const int* in_sizes, int n_in,
                              void* d_out, int out_size)
{
    const float* hs   = (const float*)d_in[0];
    const float* WAq  = (const float*)d_in[1];
    const float* WAk  = (const float*)d_in[2];
    const float* WAv  = (const float*)d_in[3];
    const float* Bq   = (const float*)d_in[4];
    const float* Bk   = (const float*)d_in[5];
    const float* Bv   = (const float*)d_in[6];
    const float* Wo   = (const float*)d_in[7];
    const float* fcos = (const float*)d_in[8];
    const float* fsin = (const float*)d_in[9];
    const int*   widx = (const int*)d_in[11];
    float* out = (float*)d_out;

    cudaFuncSetAttribute(proj_h,  cudaFuncAttributeMaxDynamicSharedMemorySize, G16_SMEM);
    cudaFuncSetAttribute(oproj_h, cudaFuncAttributeMaxDynamicSharedMemorySize, G16_SMEM);
    cudaFuncSetAttribute(qkv_h,   cudaFuncAttributeMaxDynamicSharedMemorySize, QKV_SMEM);
    cudaFuncSetAttribute(flash_h, cudaFuncAttributeMaxDynamicSharedMemorySize, FL_SMEM);

    cvt_all<<<8192, 256>>>(hs, WAq, WAk, WAv, Wo);
    proj_h <<<dim3(16, 32), 256, G16_SMEM>>>();
    qkv_h  <<<dim3(32, 32), 256, QKV_SMEM>>>(Bq, Bk, Bv, fcos, fsin, widx);
    flash_h<<<dim3(S_ / 128, B_ * H_), 256, FL_SMEM>>>();
    oproj_h<<<dim3(16, 32), 256, G16_SMEM>>>(out);
}

// round 10
// speedup vs baseline: 6.8940x; 1.0589x over previous
#include <cuda_runtime.h>
#include <cuda_fp16.h>
#include <cstdint>

#define B_   2
#define S_   2048
#define H_   16
#define HKV_ 8
#define D_   128
#define NROW (B_*S_)

// Scratch (device globals)
__device__ __align__(16) __half g_hs16[(size_t)NROW*2048];
__device__ __align__(16) __half g_w16 [(size_t)2048*2048];     // [WAq | WAk | WAv] rows
__device__ __align__(16) __half g_wo16[(size_t)2048*2048];
__device__ __align__(16) __half g_A   [(size_t)NROW*2048];
__device__ __align__(16) __half g_q   [(size_t)B_*H_  *S_*D_]; // pre-scaled by log2e/sqrt(D)
__device__ __align__(16) __half g_k   [(size_t)B_*HKV_*S_*D_];
__device__ __align__(16) __half g_v   [(size_t)B_*HKV_*S_*D_]; // PACKED: [pos/2][2d+(pos&1)]
__device__ __align__(16) __half g_ao16[(size_t)NROW*2048];

__device__ __forceinline__ uint32_t h2rn(float a, float b) {
    __half2 h = __floats2half2_rn(a, b);
    return *reinterpret_cast<uint32_t*>(&h);
}
__device__ __forceinline__ float ex2(float x) {
    float r; asm("ex2.approx.f32 %0, %1;" : "=f"(r) : "f"(x)); return r;
}
__device__ __forceinline__ void mma_f16(float* c, const uint32_t* a, const uint32_t* b) {
    asm volatile(
        "mma.sync.aligned.m16n8k16.row.col.f32.f16.f16.f32 "
        "{%0,%1,%2,%3}, {%4,%5,%6,%7}, {%8,%9}, {%0,%1,%2,%3};"
        : "+f"(c[0]), "+f"(c[1]), "+f"(c[2]), "+f"(c[3])
        : "r"(a[0]), "r"(a[1]), "r"(a[2]), "r"(a[3]), "r"(b[0]), "r"(b[1]));
}
__device__ __forceinline__ void ldsm4(uint32_t* r, uint32_t addr) {
    asm volatile("ldmatrix.sync.aligned.m8n8.x4.shared.b16 {%0,%1,%2,%3}, [%4];"
        : "=r"(r[0]), "=r"(r[1]), "=r"(r[2]), "=r"(r[3]) : "r"(addr));
}
__device__ __forceinline__ uint32_t smem_u32(const void* p) {
    uint32_t a;
    asm("{ .reg .u64 t; cvta.to.shared.u64 t, %1; cvt.u32.u64 %0, t; }" : "=r"(a) : "l"(p));
    return a;
}
__device__ __forceinline__ void cp16(uint32_t d, const void* s) {
    asm volatile("cp.async.cg.shared.global [%0], [%1], 16;" :: "r"(d), "l"(s));
}
#define CP_COMMIT() asm volatile("cp.async.commit_group;")

// ---------------------------------------------------------------------------
// fused fp32 -> fp16 conversion of all 5 inputs
// ---------------------------------------------------------------------------
__global__ void __launch_bounds__(256) cvt_all(
    const float* __restrict__ hs, const float* __restrict__ waq,
    const float* __restrict__ wak, const float* __restrict__ wav,
    const float* __restrict__ wo)
{
    size_t g = (size_t)blockIdx.x * 256 + threadIdx.x;
    const float* s; __half* d;
    if (g < 1048576)      { s = hs;  d = g_hs16; }
    else if (g < 1310720) { g -= 1048576; s = waq; d = g_w16; }
    else if (g < 1441792) { g -= 1310720; s = wak; d = g_w16 + (size_t)1024*2048; }
    else if (g < 1572864) { g -= 1441792; s = wav; d = g_w16 + (size_t)1536*2048; }
    else                  { g -= 1572864; s = wo;  d = g_wo16; }
    size_t i = g * 8;
    float4 a = *(const float4*)(s + i);
    float4 b = *(const float4*)(s + i + 4);
    uint4 o = { h2rn(a.x,a.y), h2rn(a.z,a.w), h2rn(b.x,b.y), h2rn(b.z,b.w) };
    *(uint4*)(d + i) = o;
}

// ---------------------------------------------------------------------------
// fp16 GEMM body: 512 threads, 16 warps (4x4), warp tile 32x32.
// cp.async 4-stage pipeline, single sync per chunk, ldmatrix frags.
// ---------------------------------------------------------------------------
#define GTS 40
#define GSTG (128*GTS)
#define G16_SMEM (4*2*GSTG*2)        // 81920 B

__device__ __forceinline__ void g16_issue(uint32_t sb, int stg,
    const __half* __restrict__ A, const __half* __restrict__ B, int tid)
{
    uint32_t ab = sb + stg * 2 * GSTG * 2;
    uint32_t bb = ab + GSTG * 2;
    int row = tid >> 2, seg = tid & 3;
    cp16(ab + row * 80 + seg * 16, A + (size_t)row * 2048 + seg * 8);
    cp16(bb + row * 80 + seg * 16, B + (size_t)row * 2048 + seg * 8);
}

__device__ __forceinline__ void gemm16_acc(
    uint32_t sb, const __half* __restrict__ A,
    const __half* __restrict__ B, float acc[2][4][4])
{
    const int tid = threadIdx.x, wid = tid >> 5, lane = tid & 31;
    const int wm = wid >> 2, wn = wid & 3;
    const int arow = (lane & 7) + ((lane >> 3) & 1) * 8, acol = (lane >> 4) * 8;
    const int brow = (lane & 7) + (lane >> 4) * 8,       bcol = ((lane >> 3) & 1) * 8;

    #pragma unroll
    for (int s = 0; s < 3; s++) {
        g16_issue(sb, s, A + s * 32, B + s * 32, tid);
        CP_COMMIT();
    }

    for (int c = 0; c < 64; c++) {
        if (c + 3 < 64) asm volatile("cp.async.wait_group 2;");
        else            asm volatile("cp.async.wait_group 0;");
        __syncthreads();
        if (c + 3 < 64) {
            g16_issue(sb, (c + 3) & 3, A + (c + 3) * 32, B + (c + 3) * 32, tid);
            CP_COMMIT();
        }

        uint32_t ab = sb + (c & 3) * 2 * GSTG * 2;
        uint32_t bb = ab + GSTG * 2;
        #pragma unroll
        for (int ks = 0; ks < 2; ks++) {
            uint32_t af[2][4], bfr[2][4];
            #pragma unroll
            for (int mi = 0; mi < 2; mi++)
                ldsm4(af[mi], ab + ((wm*32 + mi*16 + arow) * GTS + ks*16 + acol) * 2);
            #pragma unroll
            for (int nh = 0; nh < 2; nh++)
                ldsm4(bfr[nh], bb + ((wn*32 + nh*16 + brow) * GTS + ks*16 + bcol) * 2);
            #pragma unroll
            for (int mi = 0; mi < 2; mi++)
                #pragma unroll
                for (int nh = 0; nh < 2; nh++) {
                    mma_f16(acc[mi][nh*2],   af[mi], bfr[nh]);
                    mma_f16(acc[mi][nh*2+1], af[mi], bfr[nh] + 2);
                }
        }
    }
}

// merged 3-way projection -> g_A (fp16, /64 folded)
__global__ void __launch_bounds__(512, 1) proj_h()
{
    extern __shared__ __half smh[];
    const int x = blockIdx.x;
    const size_t m0 = (size_t)blockIdx.y << 7;

    float acc[2][4][4];
    #pragma unroll
    for (int i = 0; i < 2; i++)
        #pragma unroll
        for (int j = 0; j < 4; j++)
            #pragma unroll
            for (int r = 0; r < 4; r++) acc[i][j][r] = 0.f;

    gemm16_acc(smem_u32(smh), g_hs16 + m0 * 2048, g_w16 + (size_t)x * 128 * 2048, acc);

    const int tid = threadIdx.x, wid = tid >> 5, lane = tid & 31;
    const int wm = wid >> 2, wn = wid & 3, lr = lane >> 2, lc = lane & 3;
    const float al = 1.0f / 64.0f;
    __half* C = g_A + m0 * 2048 + x * 128;
    #pragma unroll
    for (int mi = 0; mi < 2; mi++) {
        const int row = wm * 32 + mi * 16 + lr;
        #pragma unroll
        for (int ni = 0; ni < 4; ni++) {
            const int col = wn * 32 + ni * 8 + lc * 2;
            *(uint32_t*)(C + (size_t)row * 2048 + col)     = h2rn(acc[mi][ni][0]*al, acc[mi][ni][1]*al);
            *(uint32_t*)(C + (size_t)(row+8) * 2048 + col) = h2rn(acc[mi][ni][2]*al, acc[mi][ni][3]*al);
        }
    }
}

// output projection: g_ao16 x g_wo16 -> out (fp32)
__global__ void __launch_bounds__(512, 1) oproj_h(float* __restrict__ out)
{
    extern __shared__ __half smh[];
    const size_t m0 = (size_t)blockIdx.y << 7;
    const size_t n0 = (size_t)blockIdx.x << 7;

    float acc[2][4][4];
    #pragma unroll
    for (int i = 0; i < 2; i++)
        #pragma unroll
        for (int j = 0; j < 4; j++)
            #pragma unroll
            for (int r = 0; r < 4; r++) acc[i][j][r] = 0.f;

    gemm16_acc(smem_u32(smh), g_ao16 + m0 * 2048, g_wo16 + n0 * 2048, acc);

    const int tid = threadIdx.x, wid = tid >> 5, lane = tid & 31;
    const int wm = wid >> 2, wn = wid & 3, lr = lane >> 2, lc = lane & 3;
    float* C = out + m0 * 2048 + n0;
    #pragma unroll
    for (int mi = 0; mi < 2; mi++) {
        const int row = wm * 32 + mi * 16 + lr;
        #pragma unroll
        for (int ni = 0; ni < 4; ni++) {
            const int col = wn * 32 + ni * 8 + lc * 2;
            float2 v0 = { acc[mi][ni][0], acc[mi][ni][1] };
            float2 v1 = { acc[mi][ni][2], acc[mi][ni][3] };
            *(float2*)(C + (size_t)row * 2048 + col)     = v0;
            *(float2*)(C + (size_t)(row+8) * 2048 + col) = v1;
        }
    }
}

// ---------------------------------------------------------------------------
// q/k/v build (fp16 mma, K=64) + RoPE + scatter (V packed). grid (32,32).
// q is scaled by log2e/sqrt(D) for exp2-softmax downstream.
// ---------------------------------------------------------------------------
#define QATS 72
#define BPS  136
#define QKV_SMEM (128*QATS*2 + 32*BPS*4)
#define SC2_ 0.12752450221065472f   // (1/sqrt(128)) * log2(e)

__global__ void __launch_bounds__(256, 1) qkv_h(
    const float* __restrict__ Bq, const float* __restrict__ Bk, const float* __restrict__ Bv,
    const float* __restrict__ fcos, const float* __restrict__ fsin,
    const int* __restrict__ widx)
{
    extern __shared__ __align__(16) char smraw[];
    __half*   As = (__half*)smraw;
    uint32_t* Bp = (uint32_t*)(smraw + 128*QATS*2);

    const int tid = threadIdx.x, w = tid >> 5, lane = tid & 31;
    const int lr = lane >> 2, lc = lane & 3;
    const int m0 = blockIdx.x << 7;
    const int hh = blockIdx.y;

    const float* Bmat; int aoff;
    if (hh < 16)      { Bmat = Bq + (size_t)hh * 8192;        aoff = hh * 64; }
    else if (hh < 24) { Bmat = Bk + (size_t)(hh - 16) * 8192; aoff = 1024 + (hh - 16) * 64; }
    else              { Bmat = Bv + (size_t)(hh - 24) * 8192; aoff = 1536 + (hh - 24) * 64; }

    #pragma unroll
    for (int i = 0; i < 4; i++) {
        int idx = tid + (i << 8);
        int r = idx >> 3, g = idx & 7;
        *(uint4*)(As + r * QATS + g * 8) =
            *(const uint4*)(g_A + (size_t)(m0 + r) * 2048 + aoff + g * 8);
    }
    #pragma unroll
    for (int i = 0; i < 4; i++) {
        int idx = tid + (i << 8);
        int r2 = idx >> 5, cg = idx & 31;
        float4 a = *(const float4*)(Bmat + (size_t)(2*r2) * 128 + cg * 4);
        float4 b = *(const float4*)(Bmat + (size_t)(2*r2+1) * 128 + cg * 4);
        uint4 o = { h2rn(a.x,b.x), h2rn(a.y,b.y), h2rn(a.z,b.z), h2rn(a.w,b.w) };
        *(uint4*)(Bp + r2 * BPS + cg * 4) = o;
    }
    __syncthreads();

    float acc[16][4];
    #pragma unroll
    for (int i = 0; i < 16; i++)
        #pragma unroll
        for (int j = 0; j < 4; j++) acc[i][j] = 0.f;

    #pragma unroll
    for (int s = 0; s < 4; s++) {
        const __half* pa = As + (w * 16 + lr) * QATS + s * 16 + 2 * lc;
        uint32_t af[4] = { *(const uint32_t*)(pa), *(const uint32_t*)(pa + 8*QATS),
                           *(const uint32_t*)(pa + 8), *(const uint32_t*)(pa + 8*QATS + 8) };
        #pragma unroll
        for (int nd = 0; nd < 16; nd++) {
            const uint32_t* pb = Bp + (s * 8 + lc) * BPS + nd * 8 + lr;
            uint32_t bf[2] = { pb[0], pb[4 * BPS] };
            mma_f16(acc[nd], af, bf);
        }
    }

    const int r0 = m0 + w * 16 + lr, r1 = r0 + 8;
    const int b  = r0 >> 11;
    const int s0 = r0 & 2047, s1 = s0 + 8;

    if (hh < 16) {
        #pragma unroll
        for (int i = 0; i < 16; i++)
            #pragma unroll
            for (int j = 0; j < 4; j++) acc[i][j] *= SC2_;
        __half* o0 = g_q + ((size_t)(b * H_ + hh) * S_ + s0) * D_;
        __half* o1 = g_q + ((size_t)(b * H_ + hh) * S_ + s1) * D_;
        #pragma unroll
        for (int nd = 0; nd < 8; nd++) {
            const int d0 = (nd << 3) + 2 * lc;
            float2 c0 = *(const float2*)(fcos + (size_t)s0*64 + d0);
            float2 z0 = *(const float2*)(fsin + (size_t)s0*64 + d0);
            float2 c1 = *(const float2*)(fcos + (size_t)s1*64 + d0);
            float2 z1 = *(const float2*)(fsin + (size_t)s1*64 + d0);
            *(uint32_t*)(o0+d0)    = h2rn(acc[nd][0]*c0.x - acc[nd+8][0]*z0.x,
                                          acc[nd][1]*c0.y - acc[nd+8][1]*z0.y);
            *(uint32_t*)(o0+d0+64) = h2rn(acc[nd][0]*z0.x + acc[nd+8][0]*c0.x,
                                          acc[nd][1]*z0.y + acc[nd+8][1]*c0.y);
            *(uint32_t*)(o1+d0)    = h2rn(acc[nd][2]*c1.x - acc[nd+8][2]*z1.x,
                                          acc[nd][3]*c1.y - acc[nd+8][3]*z1.y);
            *(uint32_t*)(o1+d0+64) = h2rn(acc[nd][2]*z1.x + acc[nd+8][2]*c1.x,
                                          acc[nd][3]*z1.y + acc[nd+8][3]*c1.y);
        }
    } else if (hh < 24) {
        int p0 = widx[s0], p1 = widx[s1];
        __half* o0 = g_k + ((size_t)(b * HKV_ + hh-16) * S_ + p0) * D_;
        __half* o1 = g_k + ((size_t)(b * HKV_ + hh-16) * S_ + p1) * D_;
        #pragma unroll
        for (int nd = 0; nd < 8; nd++) {
            const int d0 = (nd << 3) + 2 * lc;
            float2 c0 = *(const float2*)(fcos + (size_t)p0*64 + d0);
            float2 z0 = *(const float2*)(fsin + (size_t)p0*64 + d0);
            float2 c1 = *(const float2*)(fcos + (size_t)p1*64 + d0);
            float2 z1 = *(const float2*)(fsin + (size_t)p1*64 + d0);
            *(uint32_t*)(o0+d0)    = h2rn(acc[nd][0]*c0.x - acc[nd+8][0]*z0.x,
                                          acc[nd][1]*c0.y - acc[nd+8][1]*z0.y);
            *(uint32_t*)(o0+d0+64) = h2rn(acc[nd][0]*z0.x + acc[nd+8][0]*c0.x,
                                          acc[nd][1]*z0.y + acc[nd+8][1]*c0.y);
            *(uint32_t*)(o1+d0)    = h2rn(acc[nd][2]*c1.x - acc[nd+8][2]*z1.x,
                                          acc[nd][3]*c1.y - acc[nd+8][3]*z1.y);
            *(uint32_t*)(o1+d0+64) = h2rn(acc[nd][2]*z1.x + acc[nd+8][2]*c1.x,
                                          acc[nd][3]*z1.y + acc[nd+8][3]*c1.y);
        }
    } else {   // V: packed-pair scatter
        int p0 = widx[s0], p1 = widx[s1];
        __half* vb = g_v + (size_t)(b * HKV_ + hh - 24) * S_ * D_;
        size_t base0 = (size_t)(p0 >> 1) * 256 + (p0 & 1);
        size_t base1 = (size_t)(p1 >> 1) * 256 + (p1 & 1);
        #pragma unroll
        for (int nd = 0; nd < 16; nd++) {
            const int d0 = (nd << 3) + 2 * lc;
            vb[base0 + 2*d0]     = __float2half_rn(acc[nd][0]);
            vb[base0 + 2*d0 + 2] = __float2half_rn(acc[nd][1]);
            vb[base1 + 2*d0]     = __float2half_rn(acc[nd][2]);
            vb[base1 + 2*d0 + 2] = __float2half_rn(acc[nd][3]);
        }
    }
}

// ---------------------------------------------------------------------------
// Flash attention, fp16 mma, cp.async double-buffered K/V, single-sync loop.
// ---------------------------------------------------------------------------
#define KTS 136
#define VPS 136
#define FL_SMEM 69632

__device__ __forceinline__ void fl_issue(uint32_t sb, int buf,
    const __half* __restrict__ kp, const __half* __restrict__ vsrc, int tid)
{
    uint32_t kb = sb + (buf ? 34816u : 0u);
    uint32_t vb = kb + 17408u;
    #pragma unroll
    for (int i = 0; i < 4; i++) {
        int idx = tid + (i << 8);
        int r = idx >> 4, g = idx & 15;
        cp16(kb + (r * KTS + g * 8) * 2, kp + (size_t)r * 128 + g * 8);
    }
    #pragma unroll
    for (int i = 0; i < 4; i++) {
        int idx = tid + (i << 8);
        int r2 = idx >> 5, cg = idx & 31;
        cp16(vb + r2 * (VPS * 4) + cg * 16, vsrc + (size_t)r2 * 256 + cg * 8);
    }
}

__global__ void __launch_bounds__(256, 1) flash_h()
{
    extern __shared__ __align__(16) char smraw[];
    const uint32_t sb = smem_u32(smraw);

    const int tid = threadIdx.x, w = tid >> 5, lane = tid & 31;
    const int lr = lane >> 2, lc = lane & 3;
    const int arow = (lane & 7) + ((lane >> 3) & 1) * 8, acol = (lane >> 4) * 8;
    const int brow = (lane & 7) + (lane >> 4) * 8,       bcol = ((lane >> 3) & 1) * 8;
    const int qt = (int)gridDim.x - 1 - (int)blockIdx.x;
    const int bh = blockIdx.y;
    const int b = bh >> 4, h = bh & 15, kvh = h >> 1;
    const int qp = qt << 7;

    const __half* qbase = g_q + ((size_t)(b * H_ + h) * S_ + qp) * D_;
    const __half* kbase = g_k + (size_t)(b * HKV_ + kvh) * S_ * D_;
    const __half* vbase = g_v + (size_t)(b * HKV_ + kvh) * S_ * D_;

    __half* Qst = (__half*)smraw;
    #pragma unroll
    for (int i = 0; i < 8; i++) {
        int idx = tid + (i << 8);
        int r = idx >> 4, g = idx & 15;
        *(uint4*)(Qst + r * KTS + g * 8) = *(const uint4*)(qbase + (size_t)r * 128 + g * 8);
    }
    __syncthreads();
    uint32_t qf[8][4];
    #pragma unroll
    for (int k8 = 0; k8 < 8; k8++)
        ldsm4(qf[k8], sb + ((w * 16 + arow) * KTS + (k8 << 4) + acol) * 2);
    __syncthreads();

    float oacc[16][4];
    #pragma unroll
    for (int i = 0; i < 16; i++)
        #pragma unroll
        for (int j = 0; j < 4; j++) oacc[i][j] = 0.f;
    float m0 = -1e30f, m1 = -1e30f, l0 = 0.f, l1 = 0.f;
    const int r0g = qp + w * 16 + lr, r1g = r0g + 8;

    const int ktmax = 2 * qt + 1;
    fl_issue(sb, 0, kbase, vbase, tid);
    CP_COMMIT();

    for (int kt = 0; kt <= ktmax; kt++) {
        asm volatile("cp.async.wait_group 0;");
        __syncthreads();
        if (kt < ktmax) {
            fl_issue(sb, (kt + 1) & 1, kbase + (size_t)(kt + 1) * 8192,
                     vbase + (size_t)(kt + 1) * 8192, tid);
            CP_COMMIT();
        }

        const uint32_t kb = sb + ((kt & 1) ? 34816u : 0u);
        const uint32_t* Vp = (const uint32_t*)(smraw + ((kt & 1) ? 34816 : 0) + 17408);

        float sacc[8][4];
        #pragma unroll
        for (int i = 0; i < 8; i++)
            #pragma unroll
            for (int j = 0; j < 4; j++) sacc[i][j] = 0.f;
        #pragma unroll
        for (int k8 = 0; k8 < 8; k8++) {
            #pragma unroll
            for (int ntp = 0; ntp < 4; ntp++) {
                uint32_t bq[4];
                ldsm4(bq, kb + ((ntp * 16 + brow) * KTS + (k8 << 4) + bcol) * 2);
                mma_f16(sacc[2*ntp],     qf[k8], bq);
                mma_f16(sacc[2*ntp + 1], qf[k8], bq + 2);
            }
        }

        if (kt >= 2 * qt) {
            const int cb = kt * 64;
            #pragma unroll
            for (int nt = 0; nt < 8; nt++) {
                int c0 = cb + nt * 8 + 2 * lc;
                if (c0     > r0g) sacc[nt][0] = -1e30f;
                if (c0 + 1 > r0g) sacc[nt][1] = -1e30f;
                if (c0     > r1g) sacc[nt][2] = -1e30f;
                if (c0 + 1 > r1g) sacc[nt][3] = -1e30f;
            }
        }

        float mi0 = -1e30f, mi1 = -1e30f;
        #pragma unroll
        for (int nt = 0; nt < 8; nt++) {
            mi0 = fmaxf(mi0, fmaxf(sacc[nt][0], sacc[nt][1]));
            mi1 = fmaxf(mi1, fmaxf(sacc[nt][2], sacc[nt][3]));
        }
        mi0 = fmaxf(mi0, __shfl_xor_sync(0xffffffffu, mi0, 1));
        mi0 = fmaxf(mi0, __shfl_xor_sync(0xffffffffu, mi0, 2));
        mi1 = fmaxf(mi1, __shfl_xor_sync(0xffffffffu, mi1, 1));
        mi1 = fmaxf(mi1, __shfl_xor_sync(0xffffffffu, mi1, 2));
        float mn0 = fmaxf(m0, mi0), mn1 = fmaxf(m1, mi1);
        float sf0 = ex2(m0 - mn0), sf1 = ex2(m1 - mn1);
        m0 = mn0; m1 = mn1;

        float ps0 = 0.f, ps1 = 0.f;
        #pragma unroll
        for (int nt = 0; nt < 8; nt++) {
            sacc[nt][0] = ex2(sacc[nt][0] - m0);
            sacc[nt][1] = ex2(sacc[nt][1] - m0);
            sacc[nt][2] = ex2(sacc[nt][2] - m1);
            sacc[nt][3] = ex2(sacc[nt][3] - m1);
            ps0 += sacc[nt][0] + sacc[nt][1];
            ps1 += sacc[nt][2] + sacc[nt][3];
        }
        ps0 += __shfl_xor_sync(0xffffffffu, ps0, 1);
        ps0 += __shfl_xor_sync(0xffffffffu, ps0, 2);
        ps1 += __shfl_xor_sync(0xffffffffu, ps1, 1);
        ps1 += __shfl_xor_sync(0xffffffffu, ps1, 2);
        l0 = l0 * sf0 + ps0;
        l1 = l1 * sf1 + ps1;

        #pragma unroll
        for (int nd = 0; nd < 16; nd++) {
            oacc[nd][0] *= sf0; oacc[nd][1] *= sf0;
            oacc[nd][2] *= sf1; oacc[nd][3] *= sf1;
        }

        #pragma unroll
        for (int ks = 0; ks < 4; ks++) {
            uint32_t af[4] = { h2rn(sacc[2*ks][0],   sacc[2*ks][1]),
                               h2rn(sacc[2*ks][2],   sacc[2*ks][3]),
                               h2rn(sacc[2*ks+1][0], sacc[2*ks+1][1]),
                               h2rn(sacc[2*ks+1][2], sacc[2*ks+1][3]) };
            #pragma unroll
            for (int nd = 0; nd < 16; nd++) {
                const uint32_t* pb = Vp + (ks * 8 + lc) * VPS + nd * 8 + lr;
                uint32_t bf[2] = { pb[0], pb[4 * VPS] };
                mma_f16(oacc[nd], af, bf);
            }
        }
        __syncthreads();
    }

    float i0 = 1.f / l0, i1 = 1.f / l1;
    __half* o0 = g_ao16 + ((size_t)b * S_ + r0g) * 2048 + h * 128 + 2 * lc;
    __half* o1 = g_ao16 + ((size_t)b * S_ + r1g) * 2048 + h * 128 + 2 * lc;
    #pragma unroll
    for (int nd = 0; nd < 16; nd++) {
        *(uint32_t*)(o0 + nd * 8) = h2rn(oacc[nd][0] * i0, oacc[nd][1] * i0);
        *(uint32_t*)(o1 + nd * 8) = h2rn(oacc[nd][2] * i1, oacc[nd][3] * i1);
    }
}

// ---------------------------------------------------------------------------
extern "C" void kernel_launch(void* const* d_in, const int* in_sizes, int n_in,
                              void* d_out, int out_size)
{
    const float* hs   = (const float*)d_in[0];
    const float* WAq  = (const float*)d_in[1];
    const float* WAk  = (const float*)d_in[2];
    const float* WAv  = (const float*)d_in[3];
    const float* Bq   = (const float*)d_in[4];
    const float* Bk   = (const float*)d_in[5];
    const float* Bv   = (const float*)d_in[6];
    const float* Wo   = (const float*)d_in[7];
    const float* fcos = (const float*)d_in[8];
    const float* fsin = (const float*)d_in[9];
    const int*   widx = (const int*)d_in[11];
    float* out = (float*)d_out;

    cudaFuncSetAttribute(proj_h,  cudaFuncAttributeMaxDynamicSharedMemorySize, G16_SMEM);
    cudaFuncSetAttribute(oproj_h, cudaFuncAttributeMaxDynamicSharedMemorySize, G16_SMEM);
    cudaFuncSetAttribute(qkv_h,   cudaFuncAttributeMaxDynamicSharedMemorySize, QKV_SMEM);
    cudaFuncSetAttribute(flash_h, cudaFuncAttributeMaxDynamicSharedMemorySize, FL_SMEM);

    cvt_all<<<8192, 256>>>(hs, WAq, WAk, WAv, Wo);
    proj_h <<<dim3(16, 32), 512, G16_SMEM>>>();
    qkv_h  <<<dim3(32, 32), 256, QKV_SMEM>>>(Bq, Bk, Bv, fcos, fsin, widx);
    flash_h<<<dim3(S_ / 128, B_ * H_), 256, FL_SMEM>>>();
    oproj_h<<<dim3(16, 32), 512, G16_SMEM>>>(out);
}

// round 11
// speedup vs baseline: 7.2356x; 1.0495x over previous
#include <cuda_runtime.h>
#include <cuda_fp16.h>
#include <cstdint>

#define B_   2
#define S_   2048
#define H_   16
#define HKV_ 8
#define D_   128
#define NROW (B_*S_)

// Scratch (device globals)
__device__ __align__(16) __half g_hs16[(size_t)NROW*2048];
__device__ __align__(16) __half g_w16 [(size_t)2048*2048];
__device__ __align__(16) __half g_wo16[(size_t)2048*2048];
__device__ __align__(16) __half g_A   [(size_t)NROW*2048];
__device__ __align__(16) __half g_q   [(size_t)B_*H_  *S_*D_]; // scaled by log2e/sqrt(D)
__device__ __align__(16) __half g_k   [(size_t)B_*HKV_*S_*D_];
__device__ __align__(16) __half g_v   [(size_t)B_*HKV_*S_*D_]; // PACKED pairs
__device__ __align__(16) __half g_ao16[(size_t)NROW*2048];

__device__ __forceinline__ uint32_t h2rn(float a, float b) {
    __half2 h = __floats2half2_rn(a, b);
    return *reinterpret_cast<uint32_t*>(&h);
}
__device__ __forceinline__ float ex2(float x) {
    float r; asm("ex2.approx.f32 %0, %1;" : "=f"(r) : "f"(x)); return r;
}
__device__ __forceinline__ uint32_t hex2(float a, float b) {   // 2^a, 2^b packed fp16
    __half2 h = h2exp2(__floats2half2_rn(a, b));
    return *reinterpret_cast<uint32_t*>(&h);
}
__device__ __forceinline__ void mma_f16(float* c, const uint32_t* a, const uint32_t* b) {
    asm volatile(
        "mma.sync.aligned.m16n8k16.row.col.f32.f16.f16.f32 "
        "{%0,%1,%2,%3}, {%4,%5,%6,%7}, {%8,%9}, {%0,%1,%2,%3};"
        : "+f"(c[0]), "+f"(c[1]), "+f"(c[2]), "+f"(c[3])
        : "r"(a[0]), "r"(a[1]), "r"(a[2]), "r"(a[3]), "r"(b[0]), "r"(b[1]));
}
__device__ __forceinline__ void ldsm4(uint32_t* r, uint32_t addr) {
    asm volatile("ldmatrix.sync.aligned.m8n8.x4.shared.b16 {%0,%1,%2,%3}, [%4];"
        : "=r"(r[0]), "=r"(r[1]), "=r"(r[2]), "=r"(r[3]) : "r"(addr));
}
__device__ __forceinline__ uint32_t smem_u32(const void* p) {
    uint32_t a;
    asm("{ .reg .u64 t; cvta.to.shared.u64 t, %1; cvt.u32.u64 %0, t; }" : "=r"(a) : "l"(p));
    return a;
}
__device__ __forceinline__ void cp16(uint32_t d, const void* s) {
    asm volatile("cp.async.cg.shared.global [%0], [%1], 16;" :: "r"(d), "l"(s));
}
#define CP_COMMIT() asm volatile("cp.async.commit_group;")

// ---------------------------------------------------------------------------
// fused fp32 -> fp16 conversion of all 5 inputs
// ---------------------------------------------------------------------------
__global__ void __launch_bounds__(256) cvt_all(
    const float* __restrict__ hs, const float* __restrict__ waq,
    const float* __restrict__ wak, const float* __restrict__ wav,
    const float* __restrict__ wo)
{
    size_t g = (size_t)blockIdx.x * 256 + threadIdx.x;
    const float* s; __half* d;
    if (g < 1048576)      { s = hs;  d = g_hs16; }
    else if (g < 1310720) { g -= 1048576; s = waq; d = g_w16; }
    else if (g < 1441792) { g -= 1310720; s = wak; d = g_w16 + (size_t)1024*2048; }
    else if (g < 1572864) { g -= 1441792; s = wav; d = g_w16 + (size_t)1536*2048; }
    else                  { g -= 1572864; s = wo;  d = g_wo16; }
    size_t i = g * 8;
    float4 a = *(const float4*)(s + i);
    float4 b = *(const float4*)(s + i + 4);
    uint4 o = { h2rn(a.x,a.y), h2rn(a.z,a.w), h2rn(b.x,b.y), h2rn(b.z,b.w) };
    *(uint4*)(d + i) = o;
}

// ---------------------------------------------------------------------------
// fp16 GEMM: 512 thr, 16 warps (4x4), warp tile 32x32, K-chunks of 64,
// 3-stage cp.async pipeline, single sync per chunk.
// ---------------------------------------------------------------------------
#define GTS 72
#define GSTG (128*GTS)                 // halves per matrix per stage
#define G16_SMEM (3*2*GSTG*2)          // 110592 B

__device__ __forceinline__ void g16_issue(uint32_t sb, int stg,
    const __half* __restrict__ A, const __half* __restrict__ B, int tid)
{
    uint32_t ab = sb + stg * 2 * GSTG * 2;
    uint32_t bb = ab + GSTG * 2;
    #pragma unroll
    for (int i = 0; i < 2; i++) {
        int idx = tid + (i << 9);
        int row = idx >> 3, seg = idx & 7;
        cp16(ab + row * 144 + seg * 16, A + (size_t)row * 2048 + seg * 8);
        cp16(bb + row * 144 + seg * 16, B + (size_t)row * 2048 + seg * 8);
    }
}

__device__ __forceinline__ void gemm16_acc(
    uint32_t sb, const __half* __restrict__ A,
    const __half* __restrict__ B, float acc[2][4][4])
{
    const int tid = threadIdx.x, wid = tid >> 5, lane = tid & 31;
    const int wm = wid >> 2, wn = wid & 3;
    const int arow = (lane & 7) + ((lane >> 3) & 1) * 8, acol = (lane >> 4) * 8;
    const int brow = (lane & 7) + (lane >> 4) * 8,       bcol = ((lane >> 3) & 1) * 8;

    #pragma unroll
    for (int s = 0; s < 2; s++) {
        g16_issue(sb, s, A + s * 64, B + s * 64, tid);
        CP_COMMIT();
    }

    for (int c = 0; c < 32; c++) {
        if (c + 2 < 32) asm volatile("cp.async.wait_group 1;");
        else            asm volatile("cp.async.wait_group 0;");
        __syncthreads();
        if (c + 2 < 32) {
            g16_issue(sb, (c + 2) % 3, A + (c + 2) * 64, B + (c + 2) * 64, tid);
            CP_COMMIT();
        }

        uint32_t ab = sb + (c % 3) * 2 * GSTG * 2;
        uint32_t bb = ab + GSTG * 2;
        #pragma unroll
        for (int ks = 0; ks < 4; ks++) {
            uint32_t af[2][4], bfr[2][4];
            #pragma unroll
            for (int mi = 0; mi < 2; mi++)
                ldsm4(af[mi], ab + ((wm*32 + mi*16 + arow) * GTS + ks*16 + acol) * 2);
            #pragma unroll
            for (int nh = 0; nh < 2; nh++)
                ldsm4(bfr[nh], bb + ((wn*32 + nh*16 + brow) * GTS + ks*16 + bcol) * 2);
            #pragma unroll
            for (int mi = 0; mi < 2; mi++)
                #pragma unroll
                for (int nh = 0; nh < 2; nh++) {
                    mma_f16(acc[mi][nh*2],   af[mi], bfr[nh]);
                    mma_f16(acc[mi][nh*2+1], af[mi], bfr[nh] + 2);
                }
        }
    }
}

// merged 3-way projection -> g_A (fp16, /64 folded)
__global__ void __launch_bounds__(512, 1) proj_h()
{
    extern __shared__ __half smh[];
    const int x = blockIdx.x;
    const size_t m0 = (size_t)blockIdx.y << 7;

    float acc[2][4][4];
    #pragma unroll
    for (int i = 0; i < 2; i++)
        #pragma unroll
        for (int j = 0; j < 4; j++)
            #pragma unroll
            for (int r = 0; r < 4; r++) acc[i][j][r] = 0.f;

    gemm16_acc(smem_u32(smh), g_hs16 + m0 * 2048, g_w16 + (size_t)x * 128 * 2048, acc);

    const int tid = threadIdx.x, wid = tid >> 5, lane = tid & 31;
    const int wm = wid >> 2, wn = wid & 3, lr = lane >> 2, lc = lane & 3;
    const float al = 1.0f / 64.0f;
    __half* C = g_A + m0 * 2048 + x * 128;
    #pragma unroll
    for (int mi = 0; mi < 2; mi++) {
        const int row = wm * 32 + mi * 16 + lr;
        #pragma unroll
        for (int ni = 0; ni < 4; ni++) {
            const int col = wn * 32 + ni * 8 + lc * 2;
            *(uint32_t*)(C + (size_t)row * 2048 + col)     = h2rn(acc[mi][ni][0]*al, acc[mi][ni][1]*al);
            *(uint32_t*)(C + (size_t)(row+8) * 2048 + col) = h2rn(acc[mi][ni][2]*al, acc[mi][ni][3]*al);
        }
    }
}

// output projection
__global__ void __launch_bounds__(512, 1) oproj_h(float* __restrict__ out)
{
    extern __shared__ __half smh[];
    const size_t m0 = (size_t)blockIdx.y << 7;
    const size_t n0 = (size_t)blockIdx.x << 7;

    float acc[2][4][4];
    #pragma unroll
    for (int i = 0; i < 2; i++)
        #pragma unroll
        for (int j = 0; j < 4; j++)
            #pragma unroll
            for (int r = 0; r < 4; r++) acc[i][j][r] = 0.f;

    gemm16_acc(smem_u32(smh), g_ao16 + m0 * 2048, g_wo16 + n0 * 2048, acc);

    const int tid = threadIdx.x, wid = tid >> 5, lane = tid & 31;
    const int wm = wid >> 2, wn = wid & 3, lr = lane >> 2, lc = lane & 3;
    float* C = out + m0 * 2048 + n0;
    #pragma unroll
    for (int mi = 0; mi < 2; mi++) {
        const int row = wm * 32 + mi * 16 + lr;
        #pragma unroll
        for (int ni = 0; ni < 4; ni++) {
            const int col = wn * 32 + ni * 8 + lc * 2;
            float2 v0 = { acc[mi][ni][0], acc[mi][ni][1] };
            float2 v1 = { acc[mi][ni][2], acc[mi][ni][3] };
            *(float2*)(C + (size_t)row * 2048 + col)     = v0;
            *(float2*)(C + (size_t)(row+8) * 2048 + col) = v1;
        }
    }
}

// ---------------------------------------------------------------------------
// q/k/v build (fp16 mma, K=64) + RoPE + scatter (V packed). grid (32,32).
// ---------------------------------------------------------------------------
#define QATS 72
#define BPS  136
#define QKV_SMEM (128*QATS*2 + 32*BPS*4)
#define SC2_ 0.12752450221065472f   // (1/sqrt(128)) * log2(e)

__global__ void __launch_bounds__(256, 1) qkv_h(
    const float* __restrict__ Bq, const float* __restrict__ Bk, const float* __restrict__ Bv,
    const float* __restrict__ fcos, const float* __restrict__ fsin,
    const int* __restrict__ widx)
{
    extern __shared__ __align__(16) char smraw[];
    __half*   As = (__half*)smraw;
    uint32_t* Bp = (uint32_t*)(smraw + 128*QATS*2);

    const int tid = threadIdx.x, w = tid >> 5, lane = tid & 31;
    const int lr = lane >> 2, lc = lane & 3;
    const int m0 = blockIdx.x << 7;
    const int hh = blockIdx.y;

    const float* Bmat; int aoff;
    if (hh < 16)      { Bmat = Bq + (size_t)hh * 8192;        aoff = hh * 64; }
    else if (hh < 24) { Bmat = Bk + (size_t)(hh - 16) * 8192; aoff = 1024 + (hh - 16) * 64; }
    else              { Bmat = Bv + (size_t)(hh - 24) * 8192; aoff = 1536 + (hh - 24) * 64; }

    #pragma unroll
    for (int i = 0; i < 4; i++) {
        int idx = tid + (i << 8);
        int r = idx >> 3, g = idx & 7;
        *(uint4*)(As + r * QATS + g * 8) =
            *(const uint4*)(g_A + (size_t)(m0 + r) * 2048 + aoff + g * 8);
    }
    #pragma unroll
    for (int i = 0; i < 4; i++) {
        int idx = tid + (i << 8);
        int r2 = idx >> 5, cg = idx & 31;
        float4 a = *(const float4*)(Bmat + (size_t)(2*r2) * 128 + cg * 4);
        float4 b = *(const float4*)(Bmat + (size_t)(2*r2+1) * 128 + cg * 4);
        uint4 o = { h2rn(a.x,b.x), h2rn(a.y,b.y), h2rn(a.z,b.z), h2rn(a.w,b.w) };
        *(uint4*)(Bp + r2 * BPS + cg * 4) = o;
    }
    __syncthreads();

    float acc[16][4];
    #pragma unroll
    for (int i = 0; i < 16; i++)
        #pragma unroll
        for (int j = 0; j < 4; j++) acc[i][j] = 0.f;

    #pragma unroll
    for (int s = 0; s < 4; s++) {
        const __half* pa = As + (w * 16 + lr) * QATS + s * 16 + 2 * lc;
        uint32_t af[4] = { *(const uint32_t*)(pa), *(const uint32_t*)(pa + 8*QATS),
                           *(const uint32_t*)(pa + 8), *(const uint32_t*)(pa + 8*QATS + 8) };
        #pragma unroll
        for (int nd = 0; nd < 16; nd++) {
            const uint32_t* pb = Bp + (s * 8 + lc) * BPS + nd * 8 + lr;
            uint32_t bf[2] = { pb[0], pb[4 * BPS] };
            mma_f16(acc[nd], af, bf);
        }
    }

    const int r0 = m0 + w * 16 + lr, r1 = r0 + 8;
    const int b  = r0 >> 11;
    const int s0 = r0 & 2047, s1 = s0 + 8;

    if (hh < 16) {
        #pragma unroll
        for (int i = 0; i < 16; i++)
            #pragma unroll
            for (int j = 0; j < 4; j++) acc[i][j] *= SC2_;
        __half* o0 = g_q + ((size_t)(b * H_ + hh) * S_ + s0) * D_;
        __half* o1 = g_q + ((size_t)(b * H_ + hh) * S_ + s1) * D_;
        #pragma unroll
        for (int nd = 0; nd < 8; nd++) {
            const int d0 = (nd << 3) + 2 * lc;
            float2 c0 = *(const float2*)(fcos + (size_t)s0*64 + d0);
            float2 z0 = *(const float2*)(fsin + (size_t)s0*64 + d0);
            float2 c1 = *(const float2*)(fcos + (size_t)s1*64 + d0);
            float2 z1 = *(const float2*)(fsin + (size_t)s1*64 + d0);
            *(uint32_t*)(o0+d0)    = h2rn(acc[nd][0]*c0.x - acc[nd+8][0]*z0.x,
                                          acc[nd][1]*c0.y - acc[nd+8][1]*z0.y);
            *(uint32_t*)(o0+d0+64) = h2rn(acc[nd][0]*z0.x + acc[nd+8][0]*c0.x,
                                          acc[nd][1]*z0.y + acc[nd+8][1]*c0.y);
            *(uint32_t*)(o1+d0)    = h2rn(acc[nd][2]*c1.x - acc[nd+8][2]*z1.x,
                                          acc[nd][3]*c1.y - acc[nd+8][3]*z1.y);
            *(uint32_t*)(o1+d0+64) = h2rn(acc[nd][2]*z1.x + acc[nd+8][2]*c1.x,
                                          acc[nd][3]*z1.y + acc[nd+8][3]*c1.y);
        }
    } else if (hh < 24) {
        int p0 = widx[s0], p1 = widx[s1];
        __half* o0 = g_k + ((size_t)(b * HKV_ + hh-16) * S_ + p0) * D_;
        __half* o1 = g_k + ((size_t)(b * HKV_ + hh-16) * S_ + p1) * D_;
        #pragma unroll
        for (int nd = 0; nd < 8; nd++) {
            const int d0 = (nd << 3) + 2 * lc;
            float2 c0 = *(const float2*)(fcos + (size_t)p0*64 + d0);
            float2 z0 = *(const float2*)(fsin + (size_t)p0*64 + d0);
            float2 c1 = *(const float2*)(fcos + (size_t)p1*64 + d0);
            float2 z1 = *(const float2*)(fsin + (size_t)p1*64 + d0);
            *(uint32_t*)(o0+d0)    = h2rn(acc[nd][0]*c0.x - acc[nd+8][0]*z0.x,
                                          acc[nd][1]*c0.y - acc[nd+8][1]*z0.y);
            *(uint32_t*)(o0+d0+64) = h2rn(acc[nd][0]*z0.x + acc[nd+8][0]*c0.x,
                                          acc[nd][1]*z0.y + acc[nd+8][1]*c0.y);
            *(uint32_t*)(o1+d0)    = h2rn(acc[nd][2]*c1.x - acc[nd+8][2]*z1.x,
                                          acc[nd][3]*c1.y - acc[nd+8][3]*z1.y);
            *(uint32_t*)(o1+d0+64) = h2rn(acc[nd][2]*z1.x + acc[nd+8][2]*c1.x,
                                          acc[nd][3]*z1.y + acc[nd+8][3]*c1.y);
        }
    } else {
        int p0 = widx[s0], p1 = widx[s1];
        __half* vb = g_v + (size_t)(b * HKV_ + hh - 24) * S_ * D_;
        size_t base0 = (size_t)(p0 >> 1) * 256 + (p0 & 1);
        size_t base1 = (size_t)(p1 >> 1) * 256 + (p1 & 1);
        #pragma unroll
        for (int nd = 0; nd < 16; nd++) {
            const int d0 = (nd << 3) + 2 * lc;
            vb[base0 + 2*d0]     = __float2half_rn(acc[nd][0]);
            vb[base0 + 2*d0 + 2] = __float2half_rn(acc[nd][1]);
            vb[base1 + 2*d0]     = __float2half_rn(acc[nd][2]);
            vb[base1 + 2*d0 + 2] = __float2half_rn(acc[nd][3]);
        }
    }
}

// ---------------------------------------------------------------------------
// Flash attention: fp16 mma, cp.async double buffer, tensor-core row sums
// (ones-column), f16x2 exp. 128 q-rows/CTA, 8 warps.
// ---------------------------------------------------------------------------
#define KTS 136
#define VPS 136
#define FL_SMEM 69632

__device__ __forceinline__ void fl_issue(uint32_t sb, int buf,
    const __half* __restrict__ kp, const __half* __restrict__ vsrc, int tid)
{
    uint32_t kb = sb + (buf ? 34816u : 0u);
    uint32_t vb = kb + 17408u;
    #pragma unroll
    for (int i = 0; i < 4; i++) {
        int idx = tid + (i << 8);
        int r = idx >> 4, g = idx & 15;
        cp16(kb + (r * KTS + g * 8) * 2, kp + (size_t)r * 128 + g * 8);
    }
    #pragma unroll
    for (int i = 0; i < 4; i++) {
        int idx = tid + (i << 8);
        int r2 = idx >> 5, cg = idx & 31;
        cp16(vb + r2 * (VPS * 4) + cg * 16, vsrc + (size_t)r2 * 256 + cg * 8);
    }
}

__global__ void __launch_bounds__(256, 1) flash_h()
{
    extern __shared__ __align__(16) char smraw[];
    const uint32_t sb = smem_u32(smraw);

    const int tid = threadIdx.x, w = tid >> 5, lane = tid & 31;
    const int lr = lane >> 2, lc = lane & 3;
    const int arow = (lane & 7) + ((lane >> 3) & 1) * 8, acol = (lane >> 4) * 8;
    const int brow = (lane & 7) + (lane >> 4) * 8,       bcol = ((lane >> 3) & 1) * 8;
    const int qt = (int)gridDim.x - 1 - (int)blockIdx.x;
    const int bh = blockIdx.y;
    const int b = bh >> 4, h = bh & 15, kvh = h >> 1;
    const int qp = qt << 7;

    const __half* qbase = g_q + ((size_t)(b * H_ + h) * S_ + qp) * D_;
    const __half* kbase = g_k + (size_t)(b * HKV_ + kvh) * S_ * D_;
    const __half* vbase = g_v + (size_t)(b * HKV_ + kvh) * S_ * D_;

    // stage Q via smem overlay, pull frags
    __half* Qst = (__half*)smraw;
    #pragma unroll
    for (int i = 0; i < 8; i++) {
        int idx = tid + (i << 8);
        int r = idx >> 4, g = idx & 15;
        *(uint4*)(Qst + r * KTS + g * 8) = *(const uint4*)(qbase + (size_t)r * 128 + g * 8);
    }
    __syncthreads();
    uint32_t qf[8][4];
    #pragma unroll
    for (int k8 = 0; k8 < 8; k8++)
        ldsm4(qf[k8], sb + ((w * 16 + arow) * KTS + (k8 << 4) + acol) * 2);
    __syncthreads();

    // init ones-columns (u32 slots 128..135 of each V row-pair, both buffers)
    {
        uint32_t* v0 = (uint32_t*)(smraw + 17408);
        uint32_t* v1 = (uint32_t*)(smraw + 34816 + 17408);
        for (int i = tid; i < 32 * 8; i += 256) {
            int r2 = i >> 3, j = i & 7;
            v0[r2 * VPS + 128 + j] = 0x3C003C00u;
            v1[r2 * VPS + 128 + j] = 0x3C003C00u;
        }
    }
    __syncthreads();

    float oacc[17][4];
    #pragma unroll
    for (int i = 0; i < 17; i++)
        #pragma unroll
        for (int j = 0; j < 4; j++) oacc[i][j] = 0.f;
    float m0 = -1e30f, m1 = -1e30f;
    const int r0g = qp + w * 16 + lr, r1g = r0g + 8;

    const int ktmax = 2 * qt + 1;
    fl_issue(sb, 0, kbase, vbase, tid);
    CP_COMMIT();

    for (int kt = 0; kt <= ktmax; kt++) {
        asm volatile("cp.async.wait_group 0;");
        __syncthreads();
        if (kt < ktmax) {
            fl_issue(sb, (kt + 1) & 1, kbase + (size_t)(kt + 1) * 8192,
                     vbase + (size_t)(kt + 1) * 8192, tid);
            CP_COMMIT();
        }

        const uint32_t kb = sb + ((kt & 1) ? 34816u : 0u);
        const uint32_t* Vp = (const uint32_t*)(smraw + ((kt & 1) ? 34816 : 0) + 17408);

        float sacc[8][4];
        #pragma unroll
        for (int i = 0; i < 8; i++)
            #pragma unroll
            for (int j = 0; j < 4; j++) sacc[i][j] = 0.f;
        #pragma unroll
        for (int k8 = 0; k8 < 8; k8++) {
            #pragma unroll
            for (int ntp = 0; ntp < 4; ntp++) {
                uint32_t bq[4];
                ldsm4(bq, kb + ((ntp * 16 + brow) * KTS + (k8 << 4) + bcol) * 2);
                mma_f16(sacc[2*ntp],     qf[k8], bq);
                mma_f16(sacc[2*ntp + 1], qf[k8], bq + 2);
            }
        }

        if (kt >= 2 * qt) {
            const int cb = kt * 64;
            #pragma unroll
            for (int nt = 0; nt < 8; nt++) {
                int c0 = cb + nt * 8 + 2 * lc;
                if (c0     > r0g) sacc[nt][0] = -1e30f;
                if (c0 + 1 > r0g) sacc[nt][1] = -1e30f;
                if (c0     > r1g) sacc[nt][2] = -1e30f;
                if (c0 + 1 > r1g) sacc[nt][3] = -1e30f;
            }
        }

        float mi0 = -1e30f, mi1 = -1e30f;
        #pragma unroll
        for (int nt = 0; nt < 8; nt++) {
            mi0 = fmaxf(mi0, fmaxf(sacc[nt][0], sacc[nt][1]));
            mi1 = fmaxf(mi1, fmaxf(sacc[nt][2], sacc[nt][3]));
        }
        mi0 = fmaxf(mi0, __shfl_xor_sync(0xffffffffu, mi0, 1));
        mi0 = fmaxf(mi0, __shfl_xor_sync(0xffffffffu, mi0, 2));
        mi1 = fmaxf(mi1, __shfl_xor_sync(0xffffffffu, mi1, 1));
        mi1 = fmaxf(mi1, __shfl_xor_sync(0xffffffffu, mi1, 2));
        float mn0 = fmaxf(m0, mi0), mn1 = fmaxf(m1, mi1);
        float sf0 = ex2(m0 - mn0), sf1 = ex2(m1 - mn1);
        m0 = mn0; m1 = mn1;

        // P in fp16 A-frag form via f16x2 exp2 (row sums come from the MMA)
        uint32_t pf[8][2];
        #pragma unroll
        for (int nt = 0; nt < 8; nt++) {
            pf[nt][0] = hex2(sacc[nt][0] - m0, sacc[nt][1] - m0);
            pf[nt][1] = hex2(sacc[nt][2] - m1, sacc[nt][3] - m1);
        }

        #pragma unroll
        for (int nd = 0; nd < 17; nd++) {
            oacc[nd][0] *= sf0; oacc[nd][1] *= sf0;
            oacc[nd][2] *= sf1; oacc[nd][3] *= sf1;
        }

        #pragma unroll
        for (int ks = 0; ks < 4; ks++) {
            uint32_t af[4] = { pf[2*ks][0], pf[2*ks][1], pf[2*ks+1][0], pf[2*ks+1][1] };
            #pragma unroll
            for (int nd = 0; nd < 17; nd++) {
                const uint32_t* pb = Vp + (ks * 8 + lc) * VPS + nd * 8 + lr;
                uint32_t bf[2] = { pb[0], pb[4 * VPS] };
                mma_f16(oacc[nd], af, bf);
            }
        }
        __syncthreads();
    }

    float i0 = 1.f / oacc[16][0], i1 = 1.f / oacc[16][2];
    __half* o0 = g_ao16 + ((size_t)b * S_ + r0g) * 2048 + h * 128 + 2 * lc;
    __half* o1 = g_ao16 + ((size_t)b * S_ + r1g) * 2048 + h * 128 + 2 * lc;
    #pragma unroll
    for (int nd = 0; nd < 16; nd++) {
        *(uint32_t*)(o0 + nd * 8) = h2rn(oacc[nd][0] * i0, oacc[nd][1] * i0);
        *(uint32_t*)(o1 + nd * 8) = h2rn(oacc[nd][2] * i1, oacc[nd][3] * i1);
    }
}

// ---------------------------------------------------------------------------
extern "C" void kernel_launch(void* const* d_in, const int* in_sizes, int n_in,
                              void* d_out, int out_size)
{
    const float* hs   = (const float*)d_in[0];
    const float* WAq  = (const float*)d_in[1];
    const float* WAk  = (const float*)d_in[2];
    const float* WAv  = (const float*)d_in[3];
    const float* Bq   = (const float*)d_in[4];
    const float* Bk   = (const float*)d_in[5];
    const float* Bv   = (const float*)d_in[6];
    const float* Wo   = (const float*)d_in[7];
    const float* fcos = (const float*)d_in[8];
    const float* fsin = (const float*)d_in[9];
    const int*   widx = (const int*)d_in[11];
    float* out = (float*)d_out;

    cudaFuncSetAttribute(proj_h,  cudaFuncAttributeMaxDynamicSharedMemorySize, G16_SMEM);
    cudaFuncSetAttribute(oproj_h, cudaFuncAttributeMaxDynamicSharedMemorySize, G16_SMEM);
    cudaFuncSetAttribute(qkv_h,   cudaFuncAttributeMaxDynamicSharedMemorySize, QKV_SMEM);
    cudaFuncSetAttribute(flash_h, cudaFuncAttributeMaxDynamicSharedMemorySize, FL_SMEM);

    cvt_all<<<8192, 256>>>(hs, WAq, WAk, WAv, Wo);
    proj_h <<<dim3(16, 32), 512, G16_SMEM>>>();
    qkv_h  <<<dim3(32, 32), 256, QKV_SMEM>>>(Bq, Bk, Bv, fcos, fsin, widx);
    flash_h<<<dim3(S_ / 128, B_ * H_), 256, FL_SMEM>>>();
    oproj_h<<<dim3(16, 32), 512, G16_SMEM>>>(out);
}

// round 12
// speedup vs baseline: 7.3306x; 1.0131x over previous
#include <cuda_runtime.h>
#include <cuda_fp16.h>
#include <cstdint>

#define B_   2
#define S_   2048
#define H_   16
#define HKV_ 8
#define D_   128
#define NROW (B_*S_)

// Scratch (device globals)
__device__ __align__(16) __half g_hs16[(size_t)NROW*2048];
__device__ __align__(16) __half g_w16 [(size_t)2048*2048];
__device__ __align__(16) __half g_wo16[(size_t)2048*2048];
__device__ __align__(16) __half g_A   [(size_t)NROW*2048];
__device__ __align__(16) __half g_q   [(size_t)B_*H_  *S_*D_]; // scaled by log2e/sqrt(D)
__device__ __align__(16) __half g_k   [(size_t)B_*HKV_*S_*D_];
__device__ __align__(16) __half g_v   [(size_t)B_*HKV_*S_*D_]; // PACKED pairs
__device__ __align__(16) __half g_ao16[(size_t)NROW*2048];

__device__ __forceinline__ uint32_t h2rn(float a, float b) {
    __half2 h = __floats2half2_rn(a, b);
    return *reinterpret_cast<uint32_t*>(&h);
}
__device__ __forceinline__ float ex2(float x) {
    float r; asm("ex2.approx.f32 %0, %1;" : "=f"(r) : "f"(x)); return r;
}
__device__ __forceinline__ uint32_t hex2(float a, float b) {
    __half2 h = h2exp2(__floats2half2_rn(a, b));
    return *reinterpret_cast<uint32_t*>(&h);
}
__device__ __forceinline__ void mma_f16(float* c, const uint32_t* a, const uint32_t* b) {
    asm volatile(
        "mma.sync.aligned.m16n8k16.row.col.f32.f16.f16.f32 "
        "{%0,%1,%2,%3}, {%4,%5,%6,%7}, {%8,%9}, {%0,%1,%2,%3};"
        : "+f"(c[0]), "+f"(c[1]), "+f"(c[2]), "+f"(c[3])
        : "r"(a[0]), "r"(a[1]), "r"(a[2]), "r"(a[3]), "r"(b[0]), "r"(b[1]));
}
__device__ __forceinline__ void ldsm4(uint32_t* r, uint32_t addr) {
    asm volatile("ldmatrix.sync.aligned.m8n8.x4.shared.b16 {%0,%1,%2,%3}, [%4];"
        : "=r"(r[0]), "=r"(r[1]), "=r"(r[2]), "=r"(r[3]) : "r"(addr));
}
__device__ __forceinline__ uint32_t smem_u32(const void* p) {
    uint32_t a;
    asm("{ .reg .u64 t; cvta.to.shared.u64 t, %1; cvt.u32.u64 %0, t; }" : "=r"(a) : "l"(p));
    return a;
}
__device__ __forceinline__ void cp16(uint32_t d, const void* s) {
    asm volatile("cp.async.cg.shared.global [%0], [%1], 16;" :: "r"(d), "l"(s));
}
#define CP_COMMIT() asm volatile("cp.async.commit_group;")

// ---------------------------------------------------------------------------
// fused fp32 -> fp16 conversion of all 5 inputs
// ---------------------------------------------------------------------------
__global__ void __launch_bounds__(256) cvt_all(
    const float* __restrict__ hs, const float* __restrict__ waq,
    const float* __restrict__ wak, const float* __restrict__ wav,
    const float* __restrict__ wo)
{
    size_t g = (size_t)blockIdx.x * 256 + threadIdx.x;
    const float* s; __half* d;
    if (g < 1048576)      { s = hs;  d = g_hs16; }
    else if (g < 1310720) { g -= 1048576; s = waq; d = g_w16; }
    else if (g < 1441792) { g -= 1310720; s = wak; d = g_w16 + (size_t)1024*2048; }
    else if (g < 1572864) { g -= 1441792; s = wav; d = g_w16 + (size_t)1536*2048; }
    else                  { g -= 1572864; s = wo;  d = g_wo16; }
    size_t i = g * 8;
    float4 a = *(const float4*)(s + i);
    float4 b = *(const float4*)(s + i + 4);
    uint4 o = { h2rn(a.x,a.y), h2rn(a.z,a.w), h2rn(b.x,b.y), h2rn(b.z,b.w) };
    *(uint4*)(d + i) = o;
}

// ---------------------------------------------------------------------------
// fp16 GEMM: 512 thr, 16 warps (4x4), warp tile 32x32, K-chunks of 64,
// 3-stage cp.async pipeline, single sync per chunk.  (at mma.sync ceiling)
// ---------------------------------------------------------------------------
#define GTS 72
#define GSTG (128*GTS)
#define G16_SMEM (3*2*GSTG*2)

__device__ __forceinline__ void g16_issue(uint32_t sb, int stg,
    const __half* __restrict__ A, const __half* __restrict__ B, int tid)
{
    uint32_t ab = sb + stg * 2 * GSTG * 2;
    uint32_t bb = ab + GSTG * 2;
    #pragma unroll
    for (int i = 0; i < 2; i++) {
        int idx = tid + (i << 9);
        int row = idx >> 3, seg = idx & 7;
        cp16(ab + row * 144 + seg * 16, A + (size_t)row * 2048 + seg * 8);
        cp16(bb + row * 144 + seg * 16, B + (size_t)row * 2048 + seg * 8);
    }
}

__device__ __forceinline__ void gemm16_acc(
    uint32_t sb, const __half* __restrict__ A,
    const __half* __restrict__ B, float acc[2][4][4])
{
    const int tid = threadIdx.x, wid = tid >> 5, lane = tid & 31;
    const int wm = wid >> 2, wn = wid & 3;
    const int arow = (lane & 7) + ((lane >> 3) & 1) * 8, acol = (lane >> 4) * 8;
    const int brow = (lane & 7) + (lane >> 4) * 8,       bcol = ((lane >> 3) & 1) * 8;

    #pragma unroll
    for (int s = 0; s < 2; s++) {
        g16_issue(sb, s, A + s * 64, B + s * 64, tid);
        CP_COMMIT();
    }

    for (int c = 0; c < 32; c++) {
        if (c + 2 < 32) asm volatile("cp.async.wait_group 1;");
        else            asm volatile("cp.async.wait_group 0;");
        __syncthreads();
        if (c + 2 < 32) {
            g16_issue(sb, (c + 2) % 3, A + (c + 2) * 64, B + (c + 2) * 64, tid);
            CP_COMMIT();
        }

        uint32_t ab = sb + (c % 3) * 2 * GSTG * 2;
        uint32_t bb = ab + GSTG * 2;
        #pragma unroll
        for (int ks = 0; ks < 4; ks++) {
            uint32_t af[2][4], bfr[2][4];
            #pragma unroll
            for (int mi = 0; mi < 2; mi++)
                ldsm4(af[mi], ab + ((wm*32 + mi*16 + arow) * GTS + ks*16 + acol) * 2);
            #pragma unroll
            for (int nh = 0; nh < 2; nh++)
                ldsm4(bfr[nh], bb + ((wn*32 + nh*16 + brow) * GTS + ks*16 + bcol) * 2);
            #pragma unroll
            for (int mi = 0; mi < 2; mi++)
                #pragma unroll
                for (int nh = 0; nh < 2; nh++) {
                    mma_f16(acc[mi][nh*2],   af[mi], bfr[nh]);
                    mma_f16(acc[mi][nh*2+1], af[mi], bfr[nh] + 2);
                }
        }
    }
}

// merged 3-way projection -> g_A (fp16, /64 folded)
__global__ void __launch_bounds__(512, 1) proj_h()
{
    extern __shared__ __half smh[];
    const int x = blockIdx.x;
    const size_t m0 = (size_t)blockIdx.y << 7;

    float acc[2][4][4];
    #pragma unroll
    for (int i = 0; i < 2; i++)
        #pragma unroll
        for (int j = 0; j < 4; j++)
            #pragma unroll
            for (int r = 0; r < 4; r++) acc[i][j][r] = 0.f;

    gemm16_acc(smem_u32(smh), g_hs16 + m0 * 2048, g_w16 + (size_t)x * 128 * 2048, acc);

    const int tid = threadIdx.x, wid = tid >> 5, lane = tid & 31;
    const int wm = wid >> 2, wn = wid & 3, lr = lane >> 2, lc = lane & 3;
    const float al = 1.0f / 64.0f;
    __half* C = g_A + m0 * 2048 + x * 128;
    #pragma unroll
    for (int mi = 0; mi < 2; mi++) {
        const int row = wm * 32 + mi * 16 + lr;
        #pragma unroll
        for (int ni = 0; ni < 4; ni++) {
            const int col = wn * 32 + ni * 8 + lc * 2;
            *(uint32_t*)(C + (size_t)row * 2048 + col)     = h2rn(acc[mi][ni][0]*al, acc[mi][ni][1]*al);
            *(uint32_t*)(C + (size_t)(row+8) * 2048 + col) = h2rn(acc[mi][ni][2]*al, acc[mi][ni][3]*al);
        }
    }
}

// output projection
__global__ void __launch_bounds__(512, 1) oproj_h(float* __restrict__ out)
{
    extern __shared__ __half smh[];
    const size_t m0 = (size_t)blockIdx.y << 7;
    const size_t n0 = (size_t)blockIdx.x << 7;

    float acc[2][4][4];
    #pragma unroll
    for (int i = 0; i < 2; i++)
        #pragma unroll
        for (int j = 0; j < 4; j++)
            #pragma unroll
            for (int r = 0; r < 4; r++) acc[i][j][r] = 0.f;

    gemm16_acc(smem_u32(smh), g_ao16 + m0 * 2048, g_wo16 + n0 * 2048, acc);

    const int tid = threadIdx.x, wid = tid >> 5, lane = tid & 31;
    const int wm = wid >> 2, wn = wid & 3, lr = lane >> 2, lc = lane & 3;
    float* C = out + m0 * 2048 + n0;
    #pragma unroll
    for (int mi = 0; mi < 2; mi++) {
        const int row = wm * 32 + mi * 16 + lr;
        #pragma unroll
        for (int ni = 0; ni < 4; ni++) {
            const int col = wn * 32 + ni * 8 + lc * 2;
            float2 v0 = { acc[mi][ni][0], acc[mi][ni][1] };
            float2 v1 = { acc[mi][ni][2], acc[mi][ni][3] };
            *(float2*)(C + (size_t)row * 2048 + col)     = v0;
            *(float2*)(C + (size_t)(row+8) * 2048 + col) = v1;
        }
    }
}

// ---------------------------------------------------------------------------
// q/k/v build (fp16 mma, K=64) + RoPE + scatter (V packed). grid (32,32).
// ---------------------------------------------------------------------------
#define QATS 72
#define BPS  136
#define QKV_SMEM (128*QATS*2 + 32*BPS*4)
#define SC2_ 0.12752450221065472f   // (1/sqrt(128)) * log2(e)

__global__ void __launch_bounds__(256, 1) qkv_h(
    const float* __restrict__ Bq, const float* __restrict__ Bk, const float* __restrict__ Bv,
    const float* __restrict__ fcos, const float* __restrict__ fsin,
    const int* __restrict__ widx)
{
    extern __shared__ __align__(16) char smraw[];
    __half*   As = (__half*)smraw;
    uint32_t* Bp = (uint32_t*)(smraw + 128*QATS*2);

    const int tid = threadIdx.x, w = tid >> 5, lane = tid & 31;
    const int lr = lane >> 2, lc = lane & 3;
    const int m0 = blockIdx.x << 7;
    const int hh = blockIdx.y;

    const float* Bmat; int aoff;
    if (hh < 16)      { Bmat = Bq + (size_t)hh * 8192;        aoff = hh * 64; }
    else if (hh < 24) { Bmat = Bk + (size_t)(hh - 16) * 8192; aoff = 1024 + (hh - 16) * 64; }
    else              { Bmat = Bv + (size_t)(hh - 24) * 8192; aoff = 1536 + (hh - 24) * 64; }

    #pragma unroll
    for (int i = 0; i < 4; i++) {
        int idx = tid + (i << 8);
        int r = idx >> 3, g = idx & 7;
        *(uint4*)(As + r * QATS + g * 8) =
            *(const uint4*)(g_A + (size_t)(m0 + r) * 2048 + aoff + g * 8);
    }
    #pragma unroll
    for (int i = 0; i < 4; i++) {
        int idx = tid + (i << 8);
        int r2 = idx >> 5, cg = idx & 31;
        float4 a = *(const float4*)(Bmat + (size_t)(2*r2) * 128 + cg * 4);
        float4 b = *(const float4*)(Bmat + (size_t)(2*r2+1) * 128 + cg * 4);
        uint4 o = { h2rn(a.x,b.x), h2rn(a.y,b.y), h2rn(a.z,b.z), h2rn(a.w,b.w) };
        *(uint4*)(Bp + r2 * BPS + cg * 4) = o;
    }
    __syncthreads();

    float acc[16][4];
    #pragma unroll
    for (int i = 0; i < 16; i++)
        #pragma unroll
        for (int j = 0; j < 4; j++) acc[i][j] = 0.f;

    #pragma unroll
    for (int s = 0; s < 4; s++) {
        const __half* pa = As + (w * 16 + lr) * QATS + s * 16 + 2 * lc;
        uint32_t af[4] = { *(const uint32_t*)(pa), *(const uint32_t*)(pa + 8*QATS),
                           *(const uint32_t*)(pa + 8), *(const uint32_t*)(pa + 8*QATS + 8) };
        #pragma unroll
        for (int nd = 0; nd < 16; nd++) {
            const uint32_t* pb = Bp + (s * 8 + lc) * BPS + nd * 8 + lr;
            uint32_t bf[2] = { pb[0], pb[4 * BPS] };
            mma_f16(acc[nd], af, bf);
        }
    }

    const int r0 = m0 + w * 16 + lr, r1 = r0 + 8;
    const int b  = r0 >> 11;
    const int s0 = r0 & 2047, s1 = s0 + 8;

    if (hh < 16) {
        #pragma unroll
        for (int i = 0; i < 16; i++)
            #pragma unroll
            for (int j = 0; j < 4; j++) acc[i][j] *= SC2_;
        __half* o0 = g_q + ((size_t)(b * H_ + hh) * S_ + s0) * D_;
        __half* o1 = g_q + ((size_t)(b * H_ + hh) * S_ + s1) * D_;
        #pragma unroll
        for (int nd = 0; nd < 8; nd++) {
            const int d0 = (nd << 3) + 2 * lc;
            float2 c0 = *(const float2*)(fcos + (size_t)s0*64 + d0);
            float2 z0 = *(const float2*)(fsin + (size_t)s0*64 + d0);
            float2 c1 = *(const float2*)(fcos + (size_t)s1*64 + d0);
            float2 z1 = *(const float2*)(fsin + (size_t)s1*64 + d0);
            *(uint32_t*)(o0+d0)    = h2rn(acc[nd][0]*c0.x - acc[nd+8][0]*z0.x,
                                          acc[nd][1]*c0.y - acc[nd+8][1]*z0.y);
            *(uint32_t*)(o0+d0+64) = h2rn(acc[nd][0]*z0.x + acc[nd+8][0]*c0.x,
                                          acc[nd][1]*z0.y + acc[nd+8][1]*c0.y);
            *(uint32_t*)(o1+d0)    = h2rn(acc[nd][2]*c1.x - acc[nd+8][2]*z1.x,
                                          acc[nd][3]*c1.y - acc[nd+8][3]*z1.y);
            *(uint32_t*)(o1+d0+64) = h2rn(acc[nd][2]*z1.x + acc[nd+8][2]*c1.x,
                                          acc[nd][3]*z1.y + acc[nd+8][3]*c1.y);
        }
    } else if (hh < 24) {
        int p0 = widx[s0], p1 = widx[s1];
        __half* o0 = g_k + ((size_t)(b * HKV_ + hh-16) * S_ + p0) * D_;
        __half* o1 = g_k + ((size_t)(b * HKV_ + hh-16) * S_ + p1) * D_;
        #pragma unroll
        for (int nd = 0; nd < 8; nd++) {
            const int d0 = (nd << 3) + 2 * lc;
            float2 c0 = *(const float2*)(fcos + (size_t)p0*64 + d0);
            float2 z0 = *(const float2*)(fsin + (size_t)p0*64 + d0);
            float2 c1 = *(const float2*)(fcos + (size_t)p1*64 + d0);
            float2 z1 = *(const float2*)(fsin + (size_t)p1*64 + d0);
            *(uint32_t*)(o0+d0)    = h2rn(acc[nd][0]*c0.x - acc[nd+8][0]*z0.x,
                                          acc[nd][1]*c0.y - acc[nd+8][1]*z0.y);
            *(uint32_t*)(o0+d0+64) = h2rn(acc[nd][0]*z0.x + acc[nd+8][0]*c0.x,
                                          acc[nd][1]*z0.y + acc[nd+8][1]*c0.y);
            *(uint32_t*)(o1+d0)    = h2rn(acc[nd][2]*c1.x - acc[nd+8][2]*z1.x,
                                          acc[nd][3]*c1.y - acc[nd+8][3]*z1.y);
            *(uint32_t*)(o1+d0+64) = h2rn(acc[nd][2]*z1.x + acc[nd+8][2]*c1.x,
                                          acc[nd][3]*z1.y + acc[nd+8][3]*c1.y);
        }
    } else {
        int p0 = widx[s0], p1 = widx[s1];
        __half* vb = g_v + (size_t)(b * HKV_ + hh - 24) * S_ * D_;
        size_t base0 = (size_t)(p0 >> 1) * 256 + (p0 & 1);
        size_t base1 = (size_t)(p1 >> 1) * 256 + (p1 & 1);
        #pragma unroll
        for (int nd = 0; nd < 16; nd++) {
            const int d0 = (nd << 3) + 2 * lc;
            vb[base0 + 2*d0]     = __float2half_rn(acc[nd][0]);
            vb[base0 + 2*d0 + 2] = __float2half_rn(acc[nd][1]);
            vb[base1 + 2*d0]     = __float2half_rn(acc[nd][2]);
            vb[base1 + 2*d0 + 2] = __float2half_rn(acc[nd][3]);
        }
    }
}

// ---------------------------------------------------------------------------
// Flash attention: 128x128 tiles (q x k), fp16 mma, cp.async double buffer,
// tensor-core row sums, f16x2 exp. 8 warps.
// smem per buffer: K 128x136h (34816 B) + V 64x136u32 (34816 B); x2 = 139264 B.
// ---------------------------------------------------------------------------
#define KTS 136
#define VPS 136
#define FL_BUF 69632
#define FL_SMEM (2*FL_BUF)

__device__ __forceinline__ void fl_issue(uint32_t sb, int buf,
    const __half* __restrict__ kp, const __half* __restrict__ vsrc, int tid)
{
    uint32_t kb = sb + buf * FL_BUF;
    uint32_t vb = kb + 34816u;
    #pragma unroll
    for (int i = 0; i < 8; i++) {
        int idx = tid + (i << 8);
        int r = idx >> 4, g = idx & 15;
        cp16(kb + (r * KTS + g * 8) * 2, kp + (size_t)r * 128 + g * 8);
    }
    #pragma unroll
    for (int i = 0; i < 8; i++) {
        int idx = tid + (i << 8);
        int r2 = idx >> 5, cg = idx & 31;
        cp16(vb + r2 * (VPS * 4) + cg * 16, vsrc + (size_t)r2 * 256 + cg * 8);
    }
}

__global__ void __launch_bounds__(256, 1) flash_h()
{
    extern __shared__ __align__(16) char smraw[];
    const uint32_t sb = smem_u32(smraw);

    const int tid = threadIdx.x, w = tid >> 5, lane = tid & 31;
    const int lr = lane >> 2, lc = lane & 3;
    const int arow = (lane & 7) + ((lane >> 3) & 1) * 8, acol = (lane >> 4) * 8;
    const int brow = (lane & 7) + (lane >> 4) * 8,       bcol = ((lane >> 3) & 1) * 8;
    const int qt = (int)gridDim.x - 1 - (int)blockIdx.x;   // long CTAs first
    const int bh = blockIdx.y;
    const int b = bh >> 4, h = bh & 15, kvh = h >> 1;
    const int qp = qt << 7;

    const __half* qbase = g_q + ((size_t)(b * H_ + h) * S_ + qp) * D_;
    const __half* kbase = g_k + (size_t)(b * HKV_ + kvh) * S_ * D_;
    const __half* vbase = g_v + (size_t)(b * HKV_ + kvh) * S_ * D_;

    // stage Q into buf0-K overlay, pull frags
    __half* Qst = (__half*)smraw;
    #pragma unroll
    for (int i = 0; i < 8; i++) {
        int idx = tid + (i << 8);
        int r = idx >> 4, g = idx & 15;
        *(uint4*)(Qst + r * KTS + g * 8) = *(const uint4*)(qbase + (size_t)r * 128 + g * 8);
    }
    __syncthreads();
    uint32_t qf[8][4];
    #pragma unroll
    for (int k8 = 0; k8 < 8; k8++)
        ldsm4(qf[k8], sb + ((w * 16 + arow) * KTS + (k8 << 4) + acol) * 2);

    // ones-columns in both V buffers (u32 slots 128..135; cp.async never touches them)
    {
        uint32_t* v0 = (uint32_t*)(smraw + 34816);
        uint32_t* v1 = (uint32_t*)(smraw + FL_BUF + 34816);
        for (int i = tid; i < 64 * 8; i += 256) {
            int r2 = i >> 3, j = i & 7;
            v0[r2 * VPS + 128 + j] = 0x3C003C00u;
            v1[r2 * VPS + 128 + j] = 0x3C003C00u;
        }
    }
    __syncthreads();   // Q reads + ones done before cp.async overwrites buf0

    float oacc[17][4];
    #pragma unroll
    for (int i = 0; i < 17; i++)
        #pragma unroll
        for (int j = 0; j < 4; j++) oacc[i][j] = 0.f;
    float m0 = -1e30f, m1 = -1e30f;
    const int r0g = qp + w * 16 + lr, r1g = r0g + 8;

    fl_issue(sb, 0, kbase, vbase, tid);
    CP_COMMIT();

    for (int kt = 0; kt <= qt; kt++) {
        asm volatile("cp.async.wait_group 0;");
        __syncthreads();
        if (kt < qt) {
            fl_issue(sb, (kt + 1) & 1, kbase + (size_t)(kt + 1) * 16384,
                     vbase + (size_t)(kt + 1) * 16384, tid);
            CP_COMMIT();
        }

        const uint32_t kb = sb + (kt & 1) * FL_BUF;
        const uint32_t* Vp = (const uint32_t*)(smraw + (kt & 1) * FL_BUF + 34816);

        // S = Q K^T  (16 x 128 per warp)
        float sacc[16][4];
        #pragma unroll
        for (int i = 0; i < 16; i++)
            #pragma unroll
            for (int j = 0; j < 4; j++) sacc[i][j] = 0.f;
        #pragma unroll
        for (int k8 = 0; k8 < 8; k8++) {
            #pragma unroll
            for (int ntp = 0; ntp < 8; ntp++) {
                uint32_t bq[4];
                ldsm4(bq, kb + ((ntp * 16 + brow) * KTS + (k8 << 4) + bcol) * 2);
                mma_f16(sacc[2*ntp],     qf[k8], bq);
                mma_f16(sacc[2*ntp + 1], qf[k8], bq + 2);
            }
        }

        if (kt == qt) {   // square diagonal tile
            const int cb = kt << 7;
            #pragma unroll
            for (int nt = 0; nt < 16; nt++) {
                int c0 = cb + nt * 8 + 2 * lc;
                if (c0     > r0g) sacc[nt][0] = -1e30f;
                if (c0 + 1 > r0g) sacc[nt][1] = -1e30f;
                if (c0     > r1g) sacc[nt][2] = -1e30f;
                if (c0 + 1 > r1g) sacc[nt][3] = -1e30f;
            }
        }

        float mi0 = -1e30f, mi1 = -1e30f;
        #pragma unroll
        for (int nt = 0; nt < 16; nt++) {
            mi0 = fmaxf(mi0, fmaxf(sacc[nt][0], sacc[nt][1]));
            mi1 = fmaxf(mi1, fmaxf(sacc[nt][2], sacc[nt][3]));
        }
        mi0 = fmaxf(mi0, __shfl_xor_sync(0xffffffffu, mi0, 1));
        mi0 = fmaxf(mi0, __shfl_xor_sync(0xffffffffu, mi0, 2));
        mi1 = fmaxf(mi1, __shfl_xor_sync(0xffffffffu, mi1, 1));
        mi1 = fmaxf(mi1, __shfl_xor_sync(0xffffffffu, mi1, 2));
        float mn0 = fmaxf(m0, mi0), mn1 = fmaxf(m1, mi1);
        float sf0 = ex2(m0 - mn0), sf1 = ex2(m1 - mn1);
        m0 = mn0; m1 = mn1;

        uint32_t pf[16][2];
        #pragma unroll
        for (int nt = 0; nt < 16; nt++) {
            pf[nt][0] = hex2(sacc[nt][0] - m0, sacc[nt][1] - m0);
            pf[nt][1] = hex2(sacc[nt][2] - m1, sacc[nt][3] - m1);
        }

        #pragma unroll
        for (int nd = 0; nd < 17; nd++) {
            oacc[nd][0] *= sf0; oacc[nd][1] *= sf0;
            oacc[nd][2] *= sf1; oacc[nd][3] *= sf1;
        }

        #pragma unroll
        for (int ks = 0; ks < 8; ks++) {
            uint32_t af[4] = { pf[2*ks][0], pf[2*ks][1], pf[2*ks+1][0], pf[2*ks+1][1] };
            #pragma unroll
            for (int nd = 0; nd < 17; nd++) {
                const uint32_t* pb = Vp + (ks * 8 + lc) * VPS + nd * 8 + lr;
                uint32_t bf[2] = { pb[0], pb[4 * VPS] };
                mma_f16(oacc[nd], af, bf);
            }
        }
        __syncthreads();
    }

    float i0 = 1.f / oacc[16][0], i1 = 1.f / oacc[16][2];
    __half* o0 = g_ao16 + ((size_t)b * S_ + r0g) * 2048 + h * 128 + 2 * lc;
    __half* o1 = g_ao16 + ((size_t)b * S_ + r1g) * 2048 + h * 128 + 2 * lc;
    #pragma unroll
    for (int nd = 0; nd < 16; nd++) {
        *(uint32_t*)(o0 + nd * 8) = h2rn(oacc[nd][0] * i0, oacc[nd][1] * i0);
        *(uint32_t*)(o1 + nd * 8) = h2rn(oacc[nd][2] * i1, oacc[nd][3] * i1);
    }
}

// ---------------------------------------------------------------------------
extern "C" void kernel_launch(void* const* d_in, const int* in_sizes, int n_in,
                              void* d_out, int out_size)
{
    const float* hs   = (const float*)d_in[0];
    const float* WAq  = (const float*)d_in[1];
    const float* WAk  = (const float*)d_in[2];
    const float* WAv  = (const float*)d_in[3];
    const float* Bq   = (const float*)d_in[4];
    const float* Bk   = (const float*)d_in[5];
    const float* Bv   = (const float*)d_in[6];
    const float* Wo   = (const float*)d_in[7];
    const float* fcos = (const float*)d_in[8];
    const float* fsin = (const float*)d_in[9];
    const int*   widx = (const int*)d_in[11];
    float* out = (float*)d_out;

    cudaFuncSetAttribute(proj_h,  cudaFuncAttributeMaxDynamicSharedMemorySize, G16_SMEM);
    cudaFuncSetAttribute(oproj_h, cudaFuncAttributeMaxDynamicSharedMemorySize, G16_SMEM);
    cudaFuncSetAttribute(qkv_h,   cudaFuncAttributeMaxDynamicSharedMemorySize, QKV_SMEM);
    cudaFuncSetAttribute(flash_h, cudaFuncAttributeMaxDynamicSharedMemorySize, FL_SMEM);

    cvt_all<<<8192, 256>>>(hs, WAq, WAk, WAv, Wo);
    proj_h <<<dim3(16, 32), 512, G16_SMEM>>>();
    qkv_h  <<<dim3(32, 32), 256, QKV_SMEM>>>(Bq, Bk, Bv, fcos, fsin, widx);
    flash_h<<<dim3(S_ / 128, B_ * H_), 256, FL_SMEM>>>();
    oproj_h<<<dim3(16, 32), 512, G16_SMEM>>>(out);
}

// round 13
// speedup vs baseline: 7.3906x; 1.0082x over previous
#include <cuda_runtime.h>
#include <cuda_fp16.h>
#include <cstdint>

#define B_   2
#define S_   2048
#define H_   16
#define HKV_ 8
#define D_   128
#define NROW (B_*S_)

// Scratch (device globals)
__device__ __align__(16) __half g_hs16[(size_t)NROW*2048];
__device__ __align__(16) __half g_w16 [(size_t)2048*2048];
__device__ __align__(16) __half g_wo16[(size_t)2048*2048];
__device__ __align__(16) __half g_A   [(size_t)NROW*2048];
__device__ __align__(16) __half g_q   [(size_t)B_*H_  *S_*D_]; // scaled by log2e/sqrt(D)
__device__ __align__(16) __half g_k   [(size_t)B_*HKV_*S_*D_];
__device__ __align__(16) __half g_v   [(size_t)B_*HKV_*S_*D_]; // d-MAJOR: [(b,kv)][d][s/2] u32 k-pairs
__device__ __align__(16) __half g_ao16[(size_t)NROW*2048];

__device__ __forceinline__ uint32_t h2rn(float a, float b) {
    __half2 h = __floats2half2_rn(a, b);
    return *reinterpret_cast<uint32_t*>(&h);
}
__device__ __forceinline__ float ex2(float x) {
    float r; asm("ex2.approx.f32 %0, %1;" : "=f"(r) : "f"(x)); return r;
}
__device__ __forceinline__ uint32_t hex2(float a, float b) {
    __half2 h = h2exp2(__floats2half2_rn(a, b));
    return *reinterpret_cast<uint32_t*>(&h);
}
__device__ __forceinline__ void mma_f16(float* c, const uint32_t* a, const uint32_t* b) {
    asm volatile(
        "mma.sync.aligned.m16n8k16.row.col.f32.f16.f16.f32 "
        "{%0,%1,%2,%3}, {%4,%5,%6,%7}, {%8,%9}, {%0,%1,%2,%3};"
        : "+f"(c[0]), "+f"(c[1]), "+f"(c[2]), "+f"(c[3])
        : "r"(a[0]), "r"(a[1]), "r"(a[2]), "r"(a[3]), "r"(b[0]), "r"(b[1]));
}
__device__ __forceinline__ void ldsm4(uint32_t* r, uint32_t addr) {
    asm volatile("ldmatrix.sync.aligned.m8n8.x4.shared.b16 {%0,%1,%2,%3}, [%4];"
        : "=r"(r[0]), "=r"(r[1]), "=r"(r[2]), "=r"(r[3]) : "r"(addr));
}
__device__ __forceinline__ uint32_t smem_u32(const void* p) {
    uint32_t a;
    asm("{ .reg .u64 t; cvta.to.shared.u64 t, %1; cvt.u32.u64 %0, t; }" : "=r"(a) : "l"(p));
    return a;
}
__device__ __forceinline__ void cp16(uint32_t d, const void* s) {
    asm volatile("cp.async.cg.shared.global [%0], [%1], 16;" :: "r"(d), "l"(s));
}
#define CP_COMMIT() asm volatile("cp.async.commit_group;")

// ---------------------------------------------------------------------------
// fused fp32 -> fp16 conversion of all 5 inputs
// ---------------------------------------------------------------------------
__global__ void __launch_bounds__(256) cvt_all(
    const float* __restrict__ hs, const float* __restrict__ waq,
    const float* __restrict__ wak, const float* __restrict__ wav,
    const float* __restrict__ wo)
{
    size_t g = (size_t)blockIdx.x * 256 + threadIdx.x;
    const float* s; __half* d;
    if (g < 1048576)      { s = hs;  d = g_hs16; }
    else if (g < 1310720) { g -= 1048576; s = waq; d = g_w16; }
    else if (g < 1441792) { g -= 1310720; s = wak; d = g_w16 + (size_t)1024*2048; }
    else if (g < 1572864) { g -= 1441792; s = wav; d = g_w16 + (size_t)1536*2048; }
    else                  { g -= 1572864; s = wo;  d = g_wo16; }
    size_t i = g * 8;
    float4 a = *(const float4*)(s + i);
    float4 b = *(const float4*)(s + i + 4);
    uint4 o = { h2rn(a.x,a.y), h2rn(a.z,a.w), h2rn(b.x,b.y), h2rn(b.z,b.w) };
    *(uint4*)(d + i) = o;
}

// ---------------------------------------------------------------------------
// fp16 GEMM: 512 thr, 16 warps (4x4), warp tile 32x32, K-chunks of 64,
// 3-stage cp.async pipeline, single sync per chunk.
// ---------------------------------------------------------------------------
#define GTS 72
#define GSTG (128*GTS)
#define G16_SMEM (3*2*GSTG*2)

__device__ __forceinline__ void g16_issue(uint32_t sb, int stg,
    const __half* __restrict__ A, const __half* __restrict__ B, int tid)
{
    uint32_t ab = sb + stg * 2 * GSTG * 2;
    uint32_t bb = ab + GSTG * 2;
    #pragma unroll
    for (int i = 0; i < 2; i++) {
        int idx = tid + (i << 9);
        int row = idx >> 3, seg = idx & 7;
        cp16(ab + row * 144 + seg * 16, A + (size_t)row * 2048 + seg * 8);
        cp16(bb + row * 144 + seg * 16, B + (size_t)row * 2048 + seg * 8);
    }
}

__device__ __forceinline__ void gemm16_acc(
    uint32_t sb, const __half* __restrict__ A,
    const __half* __restrict__ B, float acc[2][4][4])
{
    const int tid = threadIdx.x, wid = tid >> 5, lane = tid & 31;
    const int wm = wid >> 2, wn = wid & 3;
    const int arow = (lane & 7) + ((lane >> 3) & 1) * 8, acol = (lane >> 4) * 8;
    const int brow = (lane & 7) + (lane >> 4) * 8,       bcol = ((lane >> 3) & 1) * 8;

    #pragma unroll
    for (int s = 0; s < 2; s++) {
        g16_issue(sb, s, A + s * 64, B + s * 64, tid);
        CP_COMMIT();
    }

    for (int c = 0; c < 32; c++) {
        if (c + 2 < 32) asm volatile("cp.async.wait_group 1;");
        else            asm volatile("cp.async.wait_group 0;");
        __syncthreads();
        if (c + 2 < 32) {
            g16_issue(sb, (c + 2) % 3, A + (c + 2) * 64, B + (c + 2) * 64, tid);
            CP_COMMIT();
        }

        uint32_t ab = sb + (c % 3) * 2 * GSTG * 2;
        uint32_t bb = ab + GSTG * 2;
        #pragma unroll
        for (int ks = 0; ks < 4; ks++) {
            uint32_t af[2][4], bfr[2][4];
            #pragma unroll
            for (int mi = 0; mi < 2; mi++)
                ldsm4(af[mi], ab + ((wm*32 + mi*16 + arow) * GTS + ks*16 + acol) * 2);
            #pragma unroll
            for (int nh = 0; nh < 2; nh++)
                ldsm4(bfr[nh], bb + ((wn*32 + nh*16 + brow) * GTS + ks*16 + bcol) * 2);
            #pragma unroll
            for (int mi = 0; mi < 2; mi++)
                #pragma unroll
                for (int nh = 0; nh < 2; nh++) {
                    mma_f16(acc[mi][nh*2],   af[mi], bfr[nh]);
                    mma_f16(acc[mi][nh*2+1], af[mi], bfr[nh] + 2);
                }
        }
    }
}

// merged 3-way projection -> g_A (fp16, /64 folded)
__global__ void __launch_bounds__(512, 1) proj_h()
{
    extern __shared__ __half smh[];
    const int x = blockIdx.x;
    const size_t m0 = (size_t)blockIdx.y << 7;

    float acc[2][4][4];
    #pragma unroll
    for (int i = 0; i < 2; i++)
        #pragma unroll
        for (int j = 0; j < 4; j++)
            #pragma unroll
            for (int r = 0; r < 4; r++) acc[i][j][r] = 0.f;

    gemm16_acc(smem_u32(smh), g_hs16 + m0 * 2048, g_w16 + (size_t)x * 128 * 2048, acc);

    const int tid = threadIdx.x, wid = tid >> 5, lane = tid & 31;
    const int wm = wid >> 2, wn = wid & 3, lr = lane >> 2, lc = lane & 3;
    const float al = 1.0f / 64.0f;
    __half* C = g_A + m0 * 2048 + x * 128;
    #pragma unroll
    for (int mi = 0; mi < 2; mi++) {
        const int row = wm * 32 + mi * 16 + lr;
        #pragma unroll
        for (int ni = 0; ni < 4; ni++) {
            const int col = wn * 32 + ni * 8 + lc * 2;
            *(uint32_t*)(C + (size_t)row * 2048 + col)     = h2rn(acc[mi][ni][0]*al, acc[mi][ni][1]*al);
            *(uint32_t*)(C + (size_t)(row+8) * 2048 + col) = h2rn(acc[mi][ni][2]*al, acc[mi][ni][3]*al);
        }
    }
}

// output projection
__global__ void __launch_bounds__(512, 1) oproj_h(float* __restrict__ out)
{
    extern __shared__ __half smh[];
    const size_t m0 = (size_t)blockIdx.y << 7;
    const size_t n0 = (size_t)blockIdx.x << 7;

    float acc[2][4][4];
    #pragma unroll
    for (int i = 0; i < 2; i++)
        #pragma unroll
        for (int j = 0; j < 4; j++)
            #pragma unroll
            for (int r = 0; r < 4; r++) acc[i][j][r] = 0.f;

    gemm16_acc(smem_u32(smh), g_ao16 + m0 * 2048, g_wo16 + n0 * 2048, acc);

    const int tid = threadIdx.x, wid = tid >> 5, lane = tid & 31;
    const int wm = wid >> 2, wn = wid & 3, lr = lane >> 2, lc = lane & 3;
    float* C = out + m0 * 2048 + n0;
    #pragma unroll
    for (int mi = 0; mi < 2; mi++) {
        const int row = wm * 32 + mi * 16 + lr;
        #pragma unroll
        for (int ni = 0; ni < 4; ni++) {
            const int col = wn * 32 + ni * 8 + lc * 2;
            float2 v0 = { acc[mi][ni][0], acc[mi][ni][1] };
            float2 v1 = { acc[mi][ni][2], acc[mi][ni][3] };
            *(float2*)(C + (size_t)row * 2048 + col)     = v0;
            *(float2*)(C + (size_t)(row+8) * 2048 + col) = v1;
        }
    }
}

// ---------------------------------------------------------------------------
// q/k/v build (fp16 mma, K=64) + RoPE + scatter. grid (32,32).
// V written d-major packed via register transpose (shfl + byte_perm).
// ---------------------------------------------------------------------------
#define QATS 72
#define BPS  136
#define QKV_SMEM (128*QATS*2 + 32*BPS*4)
#define SC2_ 0.12752450221065472f   // (1/sqrt(128)) * log2(e)

__global__ void __launch_bounds__(256, 1) qkv_h(
    const float* __restrict__ Bq, const float* __restrict__ Bk, const float* __restrict__ Bv,
    const float* __restrict__ fcos, const float* __restrict__ fsin,
    const int* __restrict__ widx)
{
    extern __shared__ __align__(16) char smraw[];
    __half*   As = (__half*)smraw;
    uint32_t* Bp = (uint32_t*)(smraw + 128*QATS*2);

    const int tid = threadIdx.x, w = tid >> 5, lane = tid & 31;
    const int lr = lane >> 2, lc = lane & 3;
    const int m0 = blockIdx.x << 7;
    const int hh = blockIdx.y;

    const float* Bmat; int aoff;
    if (hh < 16)      { Bmat = Bq + (size_t)hh * 8192;        aoff = hh * 64; }
    else if (hh < 24) { Bmat = Bk + (size_t)(hh - 16) * 8192; aoff = 1024 + (hh - 16) * 64; }
    else              { Bmat = Bv + (size_t)(hh - 24) * 8192; aoff = 1536 + (hh - 24) * 64; }

    #pragma unroll
    for (int i = 0; i < 4; i++) {
        int idx = tid + (i << 8);
        int r = idx >> 3, g = idx & 7;
        *(uint4*)(As + r * QATS + g * 8) =
            *(const uint4*)(g_A + (size_t)(m0 + r) * 2048 + aoff + g * 8);
    }
    #pragma unroll
    for (int i = 0; i < 4; i++) {
        int idx = tid + (i << 8);
        int r2 = idx >> 5, cg = idx & 31;
        float4 a = *(const float4*)(Bmat + (size_t)(2*r2) * 128 + cg * 4);
        float4 b = *(const float4*)(Bmat + (size_t)(2*r2+1) * 128 + cg * 4);
        uint4 o = { h2rn(a.x,b.x), h2rn(a.y,b.y), h2rn(a.z,b.z), h2rn(a.w,b.w) };
        *(uint4*)(Bp + r2 * BPS + cg * 4) = o;
    }
    __syncthreads();

    float acc[16][4];
    #pragma unroll
    for (int i = 0; i < 16; i++)
        #pragma unroll
        for (int j = 0; j < 4; j++) acc[i][j] = 0.f;

    #pragma unroll
    for (int s = 0; s < 4; s++) {
        const __half* pa = As + (w * 16 + lr) * QATS + s * 16 + 2 * lc;
        uint32_t af[4] = { *(const uint32_t*)(pa), *(const uint32_t*)(pa + 8*QATS),
                           *(const uint32_t*)(pa + 8), *(const uint32_t*)(pa + 8*QATS + 8) };
        #pragma unroll
        for (int nd = 0; nd < 16; nd++) {
            const uint32_t* pb = Bp + (s * 8 + lc) * BPS + nd * 8 + lr;
            uint32_t bf[2] = { pb[0], pb[4 * BPS] };
            mma_f16(acc[nd], af, bf);
        }
    }

    const int r0 = m0 + w * 16 + lr, r1 = r0 + 8;
    const int b  = r0 >> 11;
    const int s0 = r0 & 2047, s1 = s0 + 8;

    if (hh < 16) {
        #pragma unroll
        for (int i = 0; i < 16; i++)
            #pragma unroll
            for (int j = 0; j < 4; j++) acc[i][j] *= SC2_;
        __half* o0 = g_q + ((size_t)(b * H_ + hh) * S_ + s0) * D_;
        __half* o1 = g_q + ((size_t)(b * H_ + hh) * S_ + s1) * D_;
        #pragma unroll
        for (int nd = 0; nd < 8; nd++) {
            const int d0 = (nd << 3) + 2 * lc;
            float2 c0 = *(const float2*)(fcos + (size_t)s0*64 + d0);
            float2 z0 = *(const float2*)(fsin + (size_t)s0*64 + d0);
            float2 c1 = *(const float2*)(fcos + (size_t)s1*64 + d0);
            float2 z1 = *(const float2*)(fsin + (size_t)s1*64 + d0);
            *(uint32_t*)(o0+d0)    = h2rn(acc[nd][0]*c0.x - acc[nd+8][0]*z0.x,
                                          acc[nd][1]*c0.y - acc[nd+8][1]*z0.y);
            *(uint32_t*)(o0+d0+64) = h2rn(acc[nd][0]*z0.x + acc[nd+8][0]*c0.x,
                                          acc[nd][1]*z0.y + acc[nd+8][1]*c0.y);
            *(uint32_t*)(o1+d0)    = h2rn(acc[nd][2]*c1.x - acc[nd+8][2]*z1.x,
                                          acc[nd][3]*c1.y - acc[nd+8][3]*z1.y);
            *(uint32_t*)(o1+d0+64) = h2rn(acc[nd][2]*z1.x + acc[nd+8][2]*c1.x,
                                          acc[nd][3]*z1.y + acc[nd+8][3]*c1.y);
        }
    } else if (hh < 24) {
        int p0 = widx[s0], p1 = widx[s1];
        __half* o0 = g_k + ((size_t)(b * HKV_ + hh-16) * S_ + p0) * D_;
        __half* o1 = g_k + ((size_t)(b * HKV_ + hh-16) * S_ + p1) * D_;
        #pragma unroll
        for (int nd = 0; nd < 8; nd++) {
            const int d0 = (nd << 3) + 2 * lc;
            float2 c0 = *(const float2*)(fcos + (size_t)p0*64 + d0);
            float2 z0 = *(const float2*)(fsin + (size_t)p0*64 + d0);
            float2 c1 = *(const float2*)(fcos + (size_t)p1*64 + d0);
            float2 z1 = *(const float2*)(fsin + (size_t)p1*64 + d0);
            *(uint32_t*)(o0+d0)    = h2rn(acc[nd][0]*c0.x - acc[nd+8][0]*z0.x,
                                          acc[nd][1]*c0.y - acc[nd+8][1]*z0.y);
            *(uint32_t*)(o0+d0+64) = h2rn(acc[nd][0]*z0.x + acc[nd+8][0]*c0.x,
                                          acc[nd][1]*z0.y + acc[nd+8][1]*c0.y);
            *(uint32_t*)(o1+d0)    = h2rn(acc[nd][2]*c1.x - acc[nd+8][2]*z1.x,
                                          acc[nd][3]*c1.y - acc[nd+8][3]*z1.y);
            *(uint32_t*)(o1+d0+64) = h2rn(acc[nd][2]*z1.x + acc[nd+8][2]*c1.x,
                                          acc[nd][3]*z1.y + acc[nd+8][3]*c1.y);
        }
    } else {   // V: register transpose -> d-major packed g_v
        const int par = lr & 1;
        int pe0 = widx[s0 - par] >> 1;        // pos-pair index, rows (r0pair)
        int pe1 = widx[s0 - par + 8] >> 1;    // rows (r1pair)
        uint32_t* gvt = (uint32_t*)g_v + (size_t)(b * HKV_ + hh - 24) * (D_ * (S_/2));
        #pragma unroll
        for (int nd = 0; nd < 16; nd++) {
            uint32_t v0 = h2rn(acc[nd][0], acc[nd][1]);
            uint32_t v1 = h2rn(acc[nd][2], acc[nd][3]);
            uint32_t q0 = __shfl_xor_sync(0xffffffffu, v0, 4);
            uint32_t q1 = __shfl_xor_sync(0xffffffffu, v1, 4);
            uint32_t o0 = par ? __byte_perm(v0, q0, 0x3276) : __byte_perm(v0, q0, 0x5410);
            uint32_t o1 = par ? __byte_perm(v1, q1, 0x3276) : __byte_perm(v1, q1, 0x5410);
            const int d = (nd << 3) + 2 * lc + par;
            gvt[(size_t)d * (S_/2) + pe0] = o0;
            gvt[(size_t)d * (S_/2) + pe1] = o1;
        }
    }
}

// ---------------------------------------------------------------------------
// Flash attention: 128x128 tiles, fp16 mma, cp.async double buffer,
// d-major V (ldsm4 PV frags), tensor-core row sums (ones d-rows), f16x2 exp.
// buffer: K 128x136h (34816 B) + Vt 136x68u32 (36992 B) = 71808 B; x2.
// ---------------------------------------------------------------------------
#define KTS 136
#define VTS 68
#define FL_BUF 71808
#define FL_SMEM (2*FL_BUF)

__device__ __forceinline__ void fl_issue(uint32_t sb, int buf,
    const __half* __restrict__ kp, const uint32_t* __restrict__ vt, int kt, int tid)
{
    uint32_t kb = sb + buf * FL_BUF;
    uint32_t vb = kb + 34816u;
    #pragma unroll
    for (int i = 0; i < 8; i++) {
        int idx = tid + (i << 8);
        int r = idx >> 4, g = idx & 15;
        cp16(kb + (r * KTS + g * 8) * 2, kp + (size_t)r * 128 + g * 8);
    }
    #pragma unroll
    for (int i = 0; i < 8; i++) {
        int idx = tid + (i << 8);
        int d = idx >> 4, g = idx & 15;
        cp16(vb + (d * VTS + g * 4) * 4, vt + (size_t)d * (S_/2) + kt * 64 + g * 4);
    }
}

__global__ void __launch_bounds__(256, 1) flash_h()
{
    extern __shared__ __align__(16) char smraw[];
    const uint32_t sb = smem_u32(smraw);

    const int tid = threadIdx.x, w = tid >> 5, lane = tid & 31;
    const int lr = lane >> 2, lc = lane & 3;
    const int arow = (lane & 7) + ((lane >> 3) & 1) * 8, acol = (lane >> 4) * 8;
    const int brow = (lane & 7) + (lane >> 4) * 8,       bcol = ((lane >> 3) & 1) * 8;
    const int vrow = ((lane >> 4) << 3) + (lane & 7),    vc4  = ((lane >> 3) & 1) * 4;
    const int qt = (int)gridDim.x - 1 - (int)blockIdx.x;
    const int bh = blockIdx.y;
    const int b = bh >> 4, h = bh & 15, kvh = h >> 1;
    const int qp = qt << 7;

    const __half*   qbase = g_q + ((size_t)(b * H_ + h) * S_ + qp) * D_;
    const __half*   kbase = g_k + (size_t)(b * HKV_ + kvh) * S_ * D_;
    const uint32_t* vtb_g = (const uint32_t*)g_v + (size_t)(b * HKV_ + kvh) * (D_ * (S_/2));

    // stage Q into buf0-K overlay, pull frags
    __half* Qst = (__half*)smraw;
    #pragma unroll
    for (int i = 0; i < 8; i++) {
        int idx = tid + (i << 8);
        int r = idx >> 4, g = idx & 15;
        *(uint4*)(Qst + r * KTS + g * 8) = *(const uint4*)(qbase + (size_t)r * 128 + g * 8);
    }
    __syncthreads();
    uint32_t qf[8][4];
    #pragma unroll
    for (int k8 = 0; k8 < 8; k8++)
        ldsm4(qf[k8], sb + ((w * 16 + arow) * KTS + (k8 << 4) + acol) * 2);

    // ones d-rows (128..135) in both Vt buffers (cp.async never writes them)
    {
        uint32_t* v0 = (uint32_t*)(smraw + 34816);
        uint32_t* v1 = (uint32_t*)(smraw + FL_BUF + 34816);
        for (int i = tid; i < 512; i += 256) {
            int r = i >> 6, c = i & 63;
            v0[(128 + r) * VTS + c] = 0x3C003C00u;
            v1[(128 + r) * VTS + c] = 0x3C003C00u;
        }
    }
    __syncthreads();

    float oacc[17][4];
    #pragma unroll
    for (int i = 0; i < 17; i++)
        #pragma unroll
        for (int j = 0; j < 4; j++) oacc[i][j] = 0.f;
    float m0 = -1e30f, m1 = -1e30f;
    const int r0g = qp + w * 16 + lr, r1g = r0g + 8;

    fl_issue(sb, 0, kbase, vtb_g, 0, tid);
    CP_COMMIT();

    for (int kt = 0; kt <= qt; kt++) {
        asm volatile("cp.async.wait_group 0;");
        __syncthreads();
        if (kt < qt) {
            fl_issue(sb, (kt + 1) & 1, kbase + (size_t)(kt + 1) * 16384,
                     vtb_g, kt + 1, tid);
            CP_COMMIT();
        }

        const uint32_t kb  = sb + (kt & 1) * FL_BUF;
        const uint32_t vtb = kb + 34816u;
        const uint32_t* Vt = (const uint32_t*)(smraw + (kt & 1) * FL_BUF + 34816);

        // S = Q K^T  (16 x 128 per warp)
        float sacc[16][4];
        #pragma unroll
        for (int i = 0; i < 16; i++)
            #pragma unroll
            for (int j = 0; j < 4; j++) sacc[i][j] = 0.f;
        #pragma unroll
        for (int k8 = 0; k8 < 8; k8++) {
            #pragma unroll
            for (int ntp = 0; ntp < 8; ntp++) {
                uint32_t bq[4];
                ldsm4(bq, kb + ((ntp * 16 + brow) * KTS + (k8 << 4) + bcol) * 2);
                mma_f16(sacc[2*ntp],     qf[k8], bq);
                mma_f16(sacc[2*ntp + 1], qf[k8], bq + 2);
            }
        }

        if (kt == qt) {
            const int cb = kt << 7;
            #pragma unroll
            for (int nt = 0; nt < 16; nt++) {
                int c0 = cb + nt * 8 + 2 * lc;
                if (c0     > r0g) sacc[nt][0] = -1e30f;
                if (c0 + 1 > r0g) sacc[nt][1] = -1e30f;
                if (c0     > r1g) sacc[nt][2] = -1e30f;
                if (c0 + 1 > r1g) sacc[nt][3] = -1e30f;
            }
        }

        float mi0 = -1e30f, mi1 = -1e30f;
        #pragma unroll
        for (int nt = 0; nt < 16; nt++) {
            mi0 = fmaxf(mi0, fmaxf(sacc[nt][0], sacc[nt][1]));
            mi1 = fmaxf(mi1, fmaxf(sacc[nt][2], sacc[nt][3]));
        }
        mi0 = fmaxf(mi0, __shfl_xor_sync(0xffffffffu, mi0, 1));
        mi0 = fmaxf(mi0, __shfl_xor_sync(0xffffffffu, mi0, 2));
        mi1 = fmaxf(mi1, __shfl_xor_sync(0xffffffffu, mi1, 1));
        mi1 = fmaxf(mi1, __shfl_xor_sync(0xffffffffu, mi1, 2));
        float mn0 = fmaxf(m0, mi0), mn1 = fmaxf(m1, mi1);
        float sf0 = ex2(m0 - mn0), sf1 = ex2(m1 - mn1);
        m0 = mn0; m1 = mn1;

        uint32_t pf[16][2];
        #pragma unroll
        for (int nt = 0; nt < 16; nt++) {
            pf[nt][0] = hex2(sacc[nt][0] - m0, sacc[nt][1] - m0);
            pf[nt][1] = hex2(sacc[nt][2] - m1, sacc[nt][3] - m1);
        }

        #pragma unroll
        for (int nd = 0; nd < 17; nd++) {
            oacc[nd][0] *= sf0; oacc[nd][1] *= sf0;
            oacc[nd][2] *= sf1; oacc[nd][3] *= sf1;
        }

        // O += P V  (ldsm4 B-frags from d-major Vt; ones row via LDS32)
        #pragma unroll
        for (int ks = 0; ks < 8; ks++) {
            uint32_t af[4] = { pf[2*ks][0], pf[2*ks][1], pf[2*ks+1][0], pf[2*ks+1][1] };
            #pragma unroll
            for (int ndp = 0; ndp < 8; ndp++) {
                uint32_t bv[4];
                ldsm4(bv, vtb + ((ndp * 16 + vrow) * VTS + ks * 8 + vc4) * 4);
                mma_f16(oacc[2*ndp],     af, bv);
                mma_f16(oacc[2*ndp + 1], af, bv + 2);
            }
            const uint32_t* po = Vt + (128 + lr) * VTS + ks * 8 + lc;
            uint32_t bo[2] = { po[0], po[4] };
            mma_f16(oacc[16], af, bo);
        }
        __syncthreads();
    }

    float i0 = 1.f / oacc[16][0], i1 = 1.f / oacc[16][2];
    __half* o0 = g_ao16 + ((size_t)b * S_ + r0g) * 2048 + h * 128 + 2 * lc;
    __half* o1 = g_ao16 + ((size_t)b * S_ + r1g) * 2048 + h * 128 + 2 * lc;
    #pragma unroll
    for (int nd = 0; nd < 16; nd++) {
        *(uint32_t*)(o0 + nd * 8) = h2rn(oacc[nd][0] * i0, oacc[nd][1] * i0);
        *(uint32_t*)(o1 + nd * 8) = h2rn(oacc[nd][2] * i1, oacc[nd][3] * i1);
    }
}

// ---------------------------------------------------------------------------
extern "C" void kernel_launch(void* const* d_in, const int* in_sizes, int n_in,
                              void* d_out, int out_size)
{
    const float* hs   = (const float*)d_in[0];
    const float* WAq  = (const float*)d_in[1];
    const float* WAk  = (const float*)d_in[2];
    const float* WAv  = (const float*)d_in[3];
    const float* Bq   = (const float*)d_in[4];
    const float* Bk   = (const float*)d_in[5];
    const float* Bv   = (const float*)d_in[6];
    const float* Wo   = (const float*)d_in[7];
    const float* fcos = (const float*)d_in[8];
    const float* fsin = (const float*)d_in[9];
    const int*   widx = (const int*)d_in[11];
    float* out = (float*)d_out;

    cudaFuncSetAttribute(proj_h,  cudaFuncAttributeMaxDynamicSharedMemorySize, G16_SMEM);
    cudaFuncSetAttribute(oproj_h, cudaFuncAttributeMaxDynamicSharedMemorySize, G16_SMEM);
    cudaFuncSetAttribute(qkv_h,   cudaFuncAttributeMaxDynamicSharedMemorySize, QKV_SMEM);
    cudaFuncSetAttribute(flash_h, cudaFuncAttributeMaxDynamicSharedMemorySize, FL_SMEM);

    cvt_all<<<8192, 256>>>(hs, WAq, WAk, WAv, Wo);
    proj_h <<<dim3(16, 32), 512, G16_SMEM>>>();
    qkv_h  <<<dim3(32, 32), 256, QKV_SMEM>>>(Bq, Bk, Bv, fcos, fsin, widx);
    flash_h<<<dim3(S_ / 128, B_ * H_), 256, FL_SMEM>>>();
    oproj_h<<<dim3(16, 32), 512, G16_SMEM>>>(out);
}

// round 14
// speedup vs baseline: 8.2801x; 1.1204x over previous
#include <cuda_runtime.h>
#include <cuda_fp16.h>
#include <cstdint>

#define B_   2
#define S_   2048
#define H_   16
#define HKV_ 8
#define D_   128
#define NROW (B_*S_)

// Scratch (device globals)
__device__ __align__(16) __half g_hs16[(size_t)NROW*2048];
__device__ __align__(16) __half g_w16 [(size_t)2048*2048];
__device__ __align__(16) __half g_wo16[(size_t)2048*2048];
__device__ __align__(16) __half g_A   [(size_t)NROW*2048];
__device__ __align__(16) __half g_q   [(size_t)B_*H_  *S_*D_]; // scaled by log2e/sqrt(D)
__device__ __align__(16) __half g_k   [(size_t)B_*HKV_*S_*D_];
__device__ __align__(16) __half g_v   [(size_t)B_*HKV_*S_*D_]; // d-MAJOR: [(b,kv)][d][s/2] u32 k-pairs
__device__ __align__(16) __half g_ao16[(size_t)NROW*2048];

__device__ __forceinline__ uint32_t h2rn(float a, float b) {
    __half2 h = __floats2half2_rn(a, b);
    return *reinterpret_cast<uint32_t*>(&h);
}
__device__ __forceinline__ float ex2(float x) {
    float r; asm("ex2.approx.f32 %0, %1;" : "=f"(r) : "f"(x)); return r;
}
__device__ __forceinline__ uint32_t hex2(float a, float b) {
    __half2 h = h2exp2(__floats2half2_rn(a, b));
    return *reinterpret_cast<uint32_t*>(&h);
}
__device__ __forceinline__ void mma_f16(float* c, const uint32_t* a, const uint32_t* b) {
    asm volatile(
        "mma.sync.aligned.m16n8k16.row.col.f32.f16.f16.f32 "
        "{%0,%1,%2,%3}, {%4,%5,%6,%7}, {%8,%9}, {%0,%1,%2,%3};"
        : "+f"(c[0]), "+f"(c[1]), "+f"(c[2]), "+f"(c[3])
        : "r"(a[0]), "r"(a[1]), "r"(a[2]), "r"(a[3]), "r"(b[0]), "r"(b[1]));
}
__device__ __forceinline__ void ldsm4(uint32_t* r, uint32_t addr) {
    asm volatile("ldmatrix.sync.aligned.m8n8.x4.shared.b16 {%0,%1,%2,%3}, [%4];"
        : "=r"(r[0]), "=r"(r[1]), "=r"(r[2]), "=r"(r[3]) : "r"(addr));
}
__device__ __forceinline__ uint32_t smem_u32(const void* p) {
    uint32_t a;
    asm("{ .reg .u64 t; cvta.to.shared.u64 t, %1; cvt.u32.u64 %0, t; }" : "=r"(a) : "l"(p));
    return a;
}
__device__ __forceinline__ void cp16(uint32_t d, const void* s) {
    asm volatile("cp.async.cg.shared.global [%0], [%1], 16;" :: "r"(d), "l"(s));
}
#define CP_COMMIT() asm volatile("cp.async.commit_group;")

// ---------------------------------------------------------------------------
// fused fp32 -> fp16 conversion of all 5 inputs
// ---------------------------------------------------------------------------
__global__ void __launch_bounds__(256) cvt_all(
    const float* __restrict__ hs, const float* __restrict__ waq,
    const float* __restrict__ wak, const float* __restrict__ wav,
    const float* __restrict__ wo)
{
    size_t g = (size_t)blockIdx.x * 256 + threadIdx.x;
    const float* s; __half* d;
    if (g < 1048576)      { s = hs;  d = g_hs16; }
    else if (g < 1310720) { g -= 1048576; s = waq; d = g_w16; }
    else if (g < 1441792) { g -= 1310720; s = wak; d = g_w16 + (size_t)1024*2048; }
    else if (g < 1572864) { g -= 1441792; s = wav; d = g_w16 + (size_t)1536*2048; }
    else                  { g -= 1572864; s = wo;  d = g_wo16; }
    size_t i = g * 8;
    float4 a = *(const float4*)(s + i);
    float4 b = *(const float4*)(s + i + 4);
    uint4 o = { h2rn(a.x,a.y), h2rn(a.z,a.w), h2rn(b.x,b.y), h2rn(b.z,b.w) };
    *(uint4*)(d + i) = o;
}

// ---------------------------------------------------------------------------
// fp16 GEMM: 128 thr, 4 warps (2x2), warp tile 64x64 (max fragment reuse),
// K-chunks of 64, 3-stage cp.async pipeline, single sync per chunk.
// ---------------------------------------------------------------------------
#define GTS 72
#define GSTG (128*GTS)
#define G16_SMEM (3*2*GSTG*2)   // 110592 B

__device__ __forceinline__ void g16_issue(uint32_t sb, int stg,
    const __half* __restrict__ A, const __half* __restrict__ B, int tid)
{
    uint32_t ab = sb + stg * 2 * GSTG * 2;
    uint32_t bb = ab + GSTG * 2;
    #pragma unroll
    for (int i = 0; i < 8; i++) {
        int idx = tid + (i << 7);
        int row = idx >> 3, seg = idx & 7;
        cp16(ab + row * 144 + seg * 16, A + (size_t)row * 2048 + seg * 8);
        cp16(bb + row * 144 + seg * 16, B + (size_t)row * 2048 + seg * 8);
    }
}

__device__ __forceinline__ void gemm16_acc(
    uint32_t sb, const __half* __restrict__ A,
    const __half* __restrict__ B, float acc[4][8][4])
{
    const int tid = threadIdx.x, wid = tid >> 5, lane = tid & 31;
    const int wm = wid >> 1, wn = wid & 1;
    const int arow = (lane & 7) + ((lane >> 3) & 1) * 8, acol = (lane >> 4) * 8;
    const int brow = (lane & 7) + (lane >> 4) * 8,       bcol = ((lane >> 3) & 1) * 8;

    #pragma unroll
    for (int s = 0; s < 2; s++) {
        g16_issue(sb, s, A + s * 64, B + s * 64, tid);
        CP_COMMIT();
    }

    for (int c = 0; c < 32; c++) {
        if (c + 2 < 32) asm volatile("cp.async.wait_group 1;");
        else            asm volatile("cp.async.wait_group 0;");
        __syncthreads();
        if (c + 2 < 32) {
            g16_issue(sb, (c + 2) % 3, A + (c + 2) * 64, B + (c + 2) * 64, tid);
            CP_COMMIT();
        }

        uint32_t ab = sb + (c % 3) * 2 * GSTG * 2;
        uint32_t bb = ab + GSTG * 2;
        #pragma unroll
        for (int ks = 0; ks < 4; ks++) {
            uint32_t af[4][4], bfr[4][4];
            #pragma unroll
            for (int mi = 0; mi < 4; mi++)
                ldsm4(af[mi], ab + ((wm*64 + mi*16 + arow) * GTS + ks*16 + acol) * 2);
            #pragma unroll
            for (int ni = 0; ni < 4; ni++)
                ldsm4(bfr[ni], bb + ((wn*64 + ni*16 + brow) * GTS + ks*16 + bcol) * 2);
            #pragma unroll
            for (int mi = 0; mi < 4; mi++)
                #pragma unroll
                for (int ni = 0; ni < 4; ni++) {
                    mma_f16(acc[mi][ni*2],   af[mi], bfr[ni]);
                    mma_f16(acc[mi][ni*2+1], af[mi], bfr[ni] + 2);
                }
        }
    }
}

// merged 3-way projection -> g_A (fp16, /64 folded)
__global__ void __launch_bounds__(128, 1) proj_h()
{
    extern __shared__ __half smh[];
    const int x = blockIdx.x;
    const size_t m0 = (size_t)blockIdx.y << 7;

    float acc[4][8][4];
    #pragma unroll
    for (int i = 0; i < 4; i++)
        #pragma unroll
        for (int j = 0; j < 8; j++)
            #pragma unroll
            for (int r = 0; r < 4; r++) acc[i][j][r] = 0.f;

    gemm16_acc(smem_u32(smh), g_hs16 + m0 * 2048, g_w16 + (size_t)x * 128 * 2048, acc);

    const int tid = threadIdx.x, wid = tid >> 5, lane = tid & 31;
    const int wm = wid >> 1, wn = wid & 1, lr = lane >> 2, lc = lane & 3;
    const float al = 1.0f / 64.0f;
    __half* C = g_A + m0 * 2048 + x * 128;
    #pragma unroll
    for (int mi = 0; mi < 4; mi++) {
        const int row = wm * 64 + mi * 16 + lr;
        #pragma unroll
        for (int nj = 0; nj < 8; nj++) {
            const int col = wn * 64 + nj * 8 + lc * 2;
            *(uint32_t*)(C + (size_t)row * 2048 + col)     = h2rn(acc[mi][nj][0]*al, acc[mi][nj][1]*al);
            *(uint32_t*)(C + (size_t)(row+8) * 2048 + col) = h2rn(acc[mi][nj][2]*al, acc[mi][nj][3]*al);
        }
    }
}

// output projection
__global__ void __launch_bounds__(128, 1) oproj_h(float* __restrict__ out)
{
    extern __shared__ __half smh[];
    const size_t m0 = (size_t)blockIdx.y << 7;
    const size_t n0 = (size_t)blockIdx.x << 7;

    float acc[4][8][4];
    #pragma unroll
    for (int i = 0; i < 4; i++)
        #pragma unroll
        for (int j = 0; j < 8; j++)
            #pragma unroll
            for (int r = 0; r < 4; r++) acc[i][j][r] = 0.f;

    gemm16_acc(smem_u32(smh), g_ao16 + m0 * 2048, g_wo16 + n0 * 2048, acc);

    const int tid = threadIdx.x, wid = tid >> 5, lane = tid & 31;
    const int wm = wid >> 1, wn = wid & 1, lr = lane >> 2, lc = lane & 3;
    float* C = out + m0 * 2048 + n0;
    #pragma unroll
    for (int mi = 0; mi < 4; mi++) {
        const int row = wm * 64 + mi * 16 + lr;
        #pragma unroll
        for (int nj = 0; nj < 8; nj++) {
            const int col = wn * 64 + nj * 8 + lc * 2;
            float2 v0 = { acc[mi][nj][0], acc[mi][nj][1] };
            float2 v1 = { acc[mi][nj][2], acc[mi][nj][3] };
            *(float2*)(C + (size_t)row * 2048 + col)     = v0;
            *(float2*)(C + (size_t)(row+8) * 2048 + col) = v1;
        }
    }
}

// ---------------------------------------------------------------------------
// q/k/v build (fp16 mma, K=64) + RoPE + scatter. grid (32,32).
// V written d-major packed via register transpose (shfl + byte_perm).
// ---------------------------------------------------------------------------
#define QATS 72
#define BPS  136
#define QKV_SMEM (128*QATS*2 + 32*BPS*4)
#define SC2_ 0.12752450221065472f   // (1/sqrt(128)) * log2(e)

__global__ void __launch_bounds__(256, 1) qkv_h(
    const float* __restrict__ Bq, const float* __restrict__ Bk, const float* __restrict__ Bv,
    const float* __restrict__ fcos, const float* __restrict__ fsin,
    const int* __restrict__ widx)
{
    extern __shared__ __align__(16) char smraw[];
    __half*   As = (__half*)smraw;
    uint32_t* Bp = (uint32_t*)(smraw + 128*QATS*2);

    const int tid = threadIdx.x, w = tid >> 5, lane = tid & 31;
    const int lr = lane >> 2, lc = lane & 3;
    const int m0 = blockIdx.x << 7;
    const int hh = blockIdx.y;

    const float* Bmat; int aoff;
    if (hh < 16)      { Bmat = Bq + (size_t)hh * 8192;        aoff = hh * 64; }
    else if (hh < 24) { Bmat = Bk + (size_t)(hh - 16) * 8192; aoff = 1024 + (hh - 16) * 64; }
    else              { Bmat = Bv + (size_t)(hh - 24) * 8192; aoff = 1536 + (hh - 24) * 64; }

    #pragma unroll
    for (int i = 0; i < 4; i++) {
        int idx = tid + (i << 8);
        int r = idx >> 3, g = idx & 7;
        *(uint4*)(As + r * QATS + g * 8) =
            *(const uint4*)(g_A + (size_t)(m0 + r) * 2048 + aoff + g * 8);
    }
    #pragma unroll
    for (int i = 0; i < 4; i++) {
        int idx = tid + (i << 8);
        int r2 = idx >> 5, cg = idx & 31;
        float4 a = *(const float4*)(Bmat + (size_t)(2*r2) * 128 + cg * 4);
        float4 b = *(const float4*)(Bmat + (size_t)(2*r2+1) * 128 + cg * 4);
        uint4 o = { h2rn(a.x,b.x), h2rn(a.y,b.y), h2rn(a.z,b.z), h2rn(a.w,b.w) };
        *(uint4*)(Bp + r2 * BPS + cg * 4) = o;
    }
    __syncthreads();

    float acc[16][4];
    #pragma unroll
    for (int i = 0; i < 16; i++)
        #pragma unroll
        for (int j = 0; j < 4; j++) acc[i][j] = 0.f;

    #pragma unroll
    for (int s = 0; s < 4; s++) {
        const __half* pa = As + (w * 16 + lr) * QATS + s * 16 + 2 * lc;
        uint32_t af[4] = { *(const uint32_t*)(pa), *(const uint32_t*)(pa + 8*QATS),
                           *(const uint32_t*)(pa + 8), *(const uint32_t*)(pa + 8*QATS + 8) };
        #pragma unroll
        for (int nd = 0; nd < 16; nd++) {
            const uint32_t* pb = Bp + (s * 8 + lc) * BPS + nd * 8 + lr;
            uint32_t bf[2] = { pb[0], pb[4 * BPS] };
            mma_f16(acc[nd], af, bf);
        }
    }

    const int r0 = m0 + w * 16 + lr, r1 = r0 + 8;
    const int b  = r0 >> 11;
    const int s0 = r0 & 2047, s1 = s0 + 8;

    if (hh < 16) {
        #pragma unroll
        for (int i = 0; i < 16; i++)
            #pragma unroll
            for (int j = 0; j < 4; j++) acc[i][j] *= SC2_;
        __half* o0 = g_q + ((size_t)(b * H_ + hh) * S_ + s0) * D_;
        __half* o1 = g_q + ((size_t)(b * H_ + hh) * S_ + s1) * D_;
        #pragma unroll
        for (int nd = 0; nd < 8; nd++) {
            const int d0 = (nd << 3) + 2 * lc;
            float2 c0 = *(const float2*)(fcos + (size_t)s0*64 + d0);
            float2 z0 = *(const float2*)(fsin + (size_t)s0*64 + d0);
            float2 c1 = *(const float2*)(fcos + (size_t)s1*64 + d0);
            float2 z1 = *(const float2*)(fsin + (size_t)s1*64 + d0);
            *(uint32_t*)(o0+d0)    = h2rn(acc[nd][0]*c0.x - acc[nd+8][0]*z0.x,
                                          acc[nd][1]*c0.y - acc[nd+8][1]*z0.y);
            *(uint32_t*)(o0+d0+64) = h2rn(acc[nd][0]*z0.x + acc[nd+8][0]*c0.x,
                                          acc[nd][1]*z0.y + acc[nd+8][1]*c0.y);
            *(uint32_t*)(o1+d0)    = h2rn(acc[nd][2]*c1.x - acc[nd+8][2]*z1.x,
                                          acc[nd][3]*c1.y - acc[nd+8][3]*z1.y);
            *(uint32_t*)(o1+d0+64) = h2rn(acc[nd][2]*z1.x + acc[nd+8][2]*c1.x,
                                          acc[nd][3]*z1.y + acc[nd+8][3]*c1.y);
        }
    } else if (hh < 24) {
        int p0 = widx[s0], p1 = widx[s1];
        __half* o0 = g_k + ((size_t)(b * HKV_ + hh-16) * S_ + p0) * D_;
        __half* o1 = g_k + ((size_t)(b * HKV_ + hh-16) * S_ + p1) * D_;
        #pragma unroll
        for (int nd = 0; nd < 8; nd++) {
            const int d0 = (nd << 3) + 2 * lc;
            float2 c0 = *(const float2*)(fcos + (size_t)p0*64 + d0);
            float2 z0 = *(const float2*)(fsin + (size_t)p0*64 + d0);
            float2 c1 = *(const float2*)(fcos + (size_t)p1*64 + d0);
            float2 z1 = *(const float2*)(fsin + (size_t)p1*64 + d0);
            *(uint32_t*)(o0+d0)    = h2rn(acc[nd][0]*c0.x - acc[nd+8][0]*z0.x,
                                          acc[nd][1]*c0.y - acc[nd+8][1]*z0.y);
            *(uint32_t*)(o0+d0+64) = h2rn(acc[nd][0]*z0.x + acc[nd+8][0]*c0.x,
                                          acc[nd][1]*z0.y + acc[nd+8][1]*c0.y);
            *(uint32_t*)(o1+d0)    = h2rn(acc[nd][2]*c1.x - acc[nd+8][2]*z1.x,
                                          acc[nd][3]*c1.y - acc[nd+8][3]*z1.y);
            *(uint32_t*)(o1+d0+64) = h2rn(acc[nd][2]*z1.x + acc[nd+8][2]*c1.x,
                                          acc[nd][3]*z1.y + acc[nd+8][3]*c1.y);
        }
    } else {   // V: register transpose -> d-major packed g_v
        const int par = lr & 1;
        int pe0 = widx[s0 - par] >> 1;
        int pe1 = widx[s0 - par + 8] >> 1;
        uint32_t* gvt = (uint32_t*)g_v + (size_t)(b * HKV_ + hh - 24) * (D_ * (S_/2));
        #pragma unroll
        for (int nd = 0; nd < 16; nd++) {
            uint32_t v0 = h2rn(acc[nd][0], acc[nd][1]);
            uint32_t v1 = h2rn(acc[nd][2], acc[nd][3]);
            uint32_t q0 = __shfl_xor_sync(0xffffffffu, v0, 4);
            uint32_t q1 = __shfl_xor_sync(0xffffffffu, v1, 4);
            uint32_t o0 = par ? __byte_perm(v0, q0, 0x3276) : __byte_perm(v0, q0, 0x5410);
            uint32_t o1 = par ? __byte_perm(v1, q1, 0x3276) : __byte_perm(v1, q1, 0x5410);
            const int d = (nd << 3) + 2 * lc + par;
            gvt[(size_t)d * (S_/2) + pe0] = o0;
            gvt[(size_t)d * (S_/2) + pe1] = o1;
        }
    }
}

// ---------------------------------------------------------------------------
// Flash attention: 128x128 tiles, fp16 mma, cp.async double buffer,
// d-major V (ldsm4 PV frags), tensor-core row sums, f16x2 exp.
// ---------------------------------------------------------------------------
#define KTS 136
#define VTS 68
#define FL_BUF 71808
#define FL_SMEM (2*FL_BUF)

__device__ __forceinline__ void fl_issue(uint32_t sb, int buf,
    const __half* __restrict__ kp, const uint32_t* __restrict__ vt, int kt, int tid)
{
    uint32_t kb = sb + buf * FL_BUF;
    uint32_t vb = kb + 34816u;
    #pragma unroll
    for (int i = 0; i < 8; i++) {
        int idx = tid + (i << 8);
        int r = idx >> 4, g = idx & 15;
        cp16(kb + (r * KTS + g * 8) * 2, kp + (size_t)r * 128 + g * 8);
    }
    #pragma unroll
    for (int i = 0; i < 8; i++) {
        int idx = tid + (i << 8);
        int d = idx >> 4, g = idx & 15;
        cp16(vb + (d * VTS + g * 4) * 4, vt + (size_t)d * (S_/2) + kt * 64 + g * 4);
    }
}

__global__ void __launch_bounds__(256, 1) flash_h()
{
    extern __shared__ __align__(16) char smraw[];
    const uint32_t sb = smem_u32(smraw);

    const int tid = threadIdx.x, w = tid >> 5, lane = tid & 31;
    const int lr = lane >> 2, lc = lane & 3;
    const int arow = (lane & 7) + ((lane >> 3) & 1) * 8, acol = (lane >> 4) * 8;
    const int brow = (lane & 7) + (lane >> 4) * 8,       bcol = ((lane >> 3) & 1) * 8;
    const int vrow = ((lane >> 4) << 3) + (lane & 7),    vc4  = ((lane >> 3) & 1) * 4;
    const int qt = (int)gridDim.x - 1 - (int)blockIdx.x;
    const int bh = blockIdx.y;
    const int b = bh >> 4, h = bh & 15, kvh = h >> 1;
    const int qp = qt << 7;

    const __half*   qbase = g_q + ((size_t)(b * H_ + h) * S_ + qp) * D_;
    const __half*   kbase = g_k + (size_t)(b * HKV_ + kvh) * S_ * D_;
    const uint32_t* vtb_g = (const uint32_t*)g_v + (size_t)(b * HKV_ + kvh) * (D_ * (S_/2));

    __half* Qst = (__half*)smraw;
    #pragma unroll
    for (int i = 0; i < 8; i++) {
        int idx = tid + (i << 8);
        int r = idx >> 4, g = idx & 15;
        *(uint4*)(Qst + r * KTS + g * 8) = *(const uint4*)(qbase + (size_t)r * 128 + g * 8);
    }
    __syncthreads();
    uint32_t qf[8][4];
    #pragma unroll
    for (int k8 = 0; k8 < 8; k8++)
        ldsm4(qf[k8], sb + ((w * 16 + arow) * KTS + (k8 << 4) + acol) * 2);

    {
        uint32_t* v0 = (uint32_t*)(smraw + 34816);
        uint32_t* v1 = (uint32_t*)(smraw + FL_BUF + 34816);
        for (int i = tid; i < 512; i += 256) {
            int r = i >> 6, c = i & 63;
            v0[(128 + r) * VTS + c] = 0x3C003C00u;
            v1[(128 + r) * VTS + c] = 0x3C003C00u;
        }
    }
    __syncthreads();

    float oacc[17][4];
    #pragma unroll
    for (int i = 0; i < 17; i++)
        #pragma unroll
        for (int j = 0; j < 4; j++) oacc[i][j] = 0.f;
    float m0 = -1e30f, m1 = -1e30f;
    const int r0g = qp + w * 16 + lr, r1g = r0g + 8;

    fl_issue(sb, 0, kbase, vtb_g, 0, tid);
    CP_COMMIT();

    for (int kt = 0; kt <= qt; kt++) {
        asm volatile("cp.async.wait_group 0;");
        __syncthreads();
        if (kt < qt) {
            fl_issue(sb, (kt + 1) & 1, kbase + (size_t)(kt + 1) * 16384,
                     vtb_g, kt + 1, tid);
            CP_COMMIT();
        }

        const uint32_t kb  = sb + (kt & 1) * FL_BUF;
        const uint32_t vtb = kb + 34816u;
        const uint32_t* Vt = (const uint32_t*)(smraw + (kt & 1) * FL_BUF + 34816);

        float sacc[16][4];
        #pragma unroll
        for (int i = 0; i < 16; i++)
            #pragma unroll
            for (int j = 0; j < 4; j++) sacc[i][j] = 0.f;
        #pragma unroll
        for (int k8 = 0; k8 < 8; k8++) {
            #pragma unroll
            for (int ntp = 0; ntp < 8; ntp++) {
                uint32_t bq[4];
                ldsm4(bq, kb + ((ntp * 16 + brow) * KTS + (k8 << 4) + bcol) * 2);
                mma_f16(sacc[2*ntp],     qf[k8], bq);
                mma_f16(sacc[2*ntp + 1], qf[k8], bq + 2);
            }
        }

        if (kt == qt) {
            const int cb = kt << 7;
            #pragma unroll
            for (int nt = 0; nt < 16; nt++) {
                int c0 = cb + nt * 8 + 2 * lc;
                if (c0     > r0g) sacc[nt][0] = -1e30f;
                if (c0 + 1 > r0g) sacc[nt][1] = -1e30f;
                if (c0     > r1g) sacc[nt][2] = -1e30f;
                if (c0 + 1 > r1g) sacc[nt][3] = -1e30f;
            }
        }

        float mi0 = -1e30f, mi1 = -1e30f;
        #pragma unroll
        for (int nt = 0; nt < 16; nt++) {
            mi0 = fmaxf(mi0, fmaxf(sacc[nt][0], sacc[nt][1]));
            mi1 = fmaxf(mi1, fmaxf(sacc[nt][2], sacc[nt][3]));
        }
        mi0 = fmaxf(mi0, __shfl_xor_sync(0xffffffffu, mi0, 1));
        mi0 = fmaxf(mi0, __shfl_xor_sync(0xffffffffu, mi0, 2));
        mi1 = fmaxf(mi1, __shfl_xor_sync(0xffffffffu, mi1, 1));
        mi1 = fmaxf(mi1, __shfl_xor_sync(0xffffffffu, mi1, 2));
        float mn0 = fmaxf(m0, mi0), mn1 = fmaxf(m1, mi1);
        float sf0 = ex2(m0 - mn0), sf1 = ex2(m1 - mn1);
        m0 = mn0; m1 = mn1;

        uint32_t pf[16][2];
        #pragma unroll
        for (int nt = 0; nt < 16; nt++) {
            pf[nt][0] = hex2(sacc[nt][0] - m0, sacc[nt][1] - m0);
            pf[nt][1] = hex2(sacc[nt][2] - m1, sacc[nt][3] - m1);
        }

        #pragma unroll
        for (int nd = 0; nd < 17; nd++) {
            oacc[nd][0] *= sf0; oacc[nd][1] *= sf0;
            oacc[nd][2] *= sf1; oacc[nd][3] *= sf1;
        }

        #pragma unroll
        for (int ks = 0; ks < 8; ks++) {
            uint32_t af[4] = { pf[2*ks][0], pf[2*ks][1], pf[2*ks+1][0], pf[2*ks+1][1] };
            #pragma unroll
            for (int ndp = 0; ndp < 8; ndp++) {
                uint32_t bv[4];
                ldsm4(bv, vtb + ((ndp * 16 + vrow) * VTS + ks * 8 + vc4) * 4);
                mma_f16(oacc[2*ndp],     af, bv);
                mma_f16(oacc[2*ndp + 1], af, bv + 2);
            }
            const uint32_t* po = Vt + (128 + lr) * VTS + ks * 8 + lc;
            uint32_t bo[2] = { po[0], po[4] };
            mma_f16(oacc[16], af, bo);
        }
        __syncthreads();
    }

    float i0 = 1.f / oacc[16][0], i1 = 1.f / oacc[16][2];
    __half* o0 = g_ao16 + ((size_t)b * S_ + r0g) * 2048 + h * 128 + 2 * lc;
    __half* o1 = g_ao16 + ((size_t)b * S_ + r1g) * 2048 + h * 128 + 2 * lc;
    #pragma unroll
    for (int nd = 0; nd < 16; nd++) {
        *(uint32_t*)(o0 + nd * 8) = h2rn(oacc[nd][0] * i0, oacc[nd][1] * i0);
        *(uint32_t*)(o1 + nd * 8) = h2rn(oacc[nd][2] * i1, oacc[nd][3] * i1);
    }
}

// ---------------------------------------------------------------------------
extern "C" void kernel_launch(void* const* d_in, const int* in_sizes, int n_in,
                              void* d_out, int out_size)
{
    const float* hs   = (const float*)d_in[0];
    const float* WAq  = (const float*)d_in[1];
    const float* WAk  = (const float*)d_in[2];
    const float* WAv  = (const float*)d_in[3];
    const float* Bq   = (const float*)d_in[4];
    const float* Bk   = (const float*)d_in[5];
    const float* Bv   = (const float*)d_in[6];
    const float* Wo   = (const float*)d_in[7];
    const float* fcos = (const float*)d_in[8];
    const float* fsin = (const float*)d_in[9];
    const int*   widx = (const int*)d_in[11];
    float* out = (float*)d_out;

    cudaFuncSetAttribute(proj_h,  cudaFuncAttributeMaxDynamicSharedMemorySize, G16_SMEM);
    cudaFuncSetAttribute(oproj_h, cudaFuncAttributeMaxDynamicSharedMemorySize, G16_SMEM);
    cudaFuncSetAttribute(qkv_h,   cudaFuncAttributeMaxDynamicSharedMemorySize, QKV_SMEM);
    cudaFuncSetAttribute(flash_h, cudaFuncAttributeMaxDynamicSharedMemorySize, FL_SMEM);

    cvt_all<<<8192, 256>>>(hs, WAq, WAk, WAv, Wo);
    proj_h <<<dim3(16, 32), 128, G16_SMEM>>>();
    qkv_h  <<<dim3(32, 32), 256, QKV_SMEM>>>(Bq, Bk, Bv, fcos, fsin, widx);
    flash_h<<<dim3(S_ / 128, B_ * H_), 256, FL_SMEM>>>();
    oproj_h<<<dim3(16, 32), 128, G16_SMEM>>>(out);
}